// round 1
// baseline (speedup 1.0000x reference)
#include <cuda_runtime.h>
#include <math.h>

// Problem constants
#define BATCH 32
#define LQ    576
#define LV    3024
#define CDIM  384
#define NHEAD 6
#define DHEAD 64
#define NLVL  3
#define NPTS  4

// Scratch (device globals; no dynamic allocation allowed)
__device__ float g_val [BATCH * LV * CDIM];        // value projection  (B, Lv, NH, d)
__device__ float g_off [BATCH * LQ * (NHEAD*NLVL*NPTS*2)]; // sampling offsets
__device__ float g_attn[BATCH * LQ * (NHEAD*NLVL*NPTS)];   // attn logits
__device__ float g_ref [BATCH * LQ * 2];                   // processed reference points
__device__ float g_mid [BATCH * LQ * CDIM];                // sampled output pre out-proj

// ---------------------------------------------------------------------------
// Generic SGEMM: C[M,N] = A[M,K] @ B[K,N] + bias[N]
// A,B,C row-major. M % 64 == 0, K % 16 == 0, N % 4 == 0 (N arbitrary otherwise).
// 64x64 block tile, 256 threads, 4x4 micro-tile, KT=16.
// ---------------------------------------------------------------------------
#define KT 16
__global__ void sgemm64(const float* __restrict__ A, const float* __restrict__ Bm,
                        const float* __restrict__ bias, float* __restrict__ Cm,
                        int M, int N, int K)
{
    __shared__ float As[KT][68];   // transposed tile: As[k][m], padded
    __shared__ float Bs[KT][64];

    const int m0 = blockIdx.y * 64;
    const int n0 = blockIdx.x * 64;
    const int tid = threadIdx.x;
    const int tx = tid & 15;       // 0..15 (N micro)
    const int ty = tid >> 4;       // 0..15 (M micro)

    const int arow = tid >> 2;            // 0..63
    const int ak4  = (tid & 3) * 4;       // 0,4,8,12
    const int bkr  = tid >> 4;            // 0..15
    const int bn4  = (tid & 15) * 4;      // 0..60

    float acc[4][4];
#pragma unroll
    for (int i = 0; i < 4; i++)
#pragma unroll
        for (int j = 0; j < 4; j++) acc[i][j] = 0.f;

    for (int kt = 0; kt < K; kt += KT) {
        float4 av = *(const float4*)&A[(size_t)(m0 + arow) * K + kt + ak4];
        As[ak4 + 0][arow] = av.x;
        As[ak4 + 1][arow] = av.y;
        As[ak4 + 2][arow] = av.z;
        As[ak4 + 3][arow] = av.w;

        float4 bv = make_float4(0.f, 0.f, 0.f, 0.f);
        if (n0 + bn4 < N)
            bv = *(const float4*)&Bm[(size_t)(kt + bkr) * N + n0 + bn4];
        *(float4*)&Bs[bkr][bn4] = bv;

        __syncthreads();

#pragma unroll
        for (int kk = 0; kk < KT; kk++) {
            float4 a = *(const float4*)&As[kk][ty * 4];
            float4 b = *(const float4*)&Bs[kk][tx * 4];
            acc[0][0] += a.x * b.x; acc[0][1] += a.x * b.y; acc[0][2] += a.x * b.z; acc[0][3] += a.x * b.w;
            acc[1][0] += a.y * b.x; acc[1][1] += a.y * b.y; acc[1][2] += a.y * b.z; acc[1][3] += a.y * b.w;
            acc[2][0] += a.z * b.x; acc[2][1] += a.z * b.y; acc[2][2] += a.z * b.z; acc[2][3] += a.z * b.w;
            acc[3][0] += a.w * b.x; acc[3][1] += a.w * b.y; acc[3][2] += a.w * b.z; acc[3][3] += a.w * b.w;
        }
        __syncthreads();
    }

#pragma unroll
    for (int i = 0; i < 4; i++) {
        int row = m0 + ty * 4 + i;
#pragma unroll
        for (int j = 0; j < 4; j++) {
            int col = n0 + tx * 4 + j;
            if (col < N)
                Cm[(size_t)row * N + col] = acc[i][j] + bias[col];
        }
    }
}

// ---------------------------------------------------------------------------
// Reference-point processing: (B, 3024, 2) -> (B, 576, 2)
// p1 = mean of first 2304; p2 = middle 576; p3 = 12x12 bilinear-upsampled to 24x24
// (half-pixel centers, clamp-to-edge == jax.image.resize bilinear for 2x upsample)
// ---------------------------------------------------------------------------
__global__ void ref_kernel(const float* __restrict__ rp, float* __restrict__ ref)
{
    const int b = blockIdx.x;
    const float* r = rp + (size_t)b * LV * 2;

    __shared__ float redx[256], redy[256];
    float ax = 0.f, ay = 0.f;
    for (int i = threadIdx.x; i < 2304; i += 256) {
        ax += r[2 * i];
        ay += r[2 * i + 1];
    }
    redx[threadIdx.x] = ax; redy[threadIdx.x] = ay;
    __syncthreads();
    for (int s = 128; s > 0; s >>= 1) {
        if (threadIdx.x < s) {
            redx[threadIdx.x] += redx[threadIdx.x + s];
            redy[threadIdx.x] += redy[threadIdx.x + s];
        }
        __syncthreads();
    }
    const float p1x = redx[0] * (1.f / 2304.f);
    const float p1y = redy[0] * (1.f / 2304.f);

    for (int q = threadIdx.x; q < LQ; q += 256) {
        float p2x = r[2 * (2304 + q)];
        float p2y = r[2 * (2304 + q) + 1];

        int rr = q / 24, cc = q % 24;
        float yy = 0.5f * rr - 0.25f;
        float xx = 0.5f * cc - 0.25f;
        int y0 = (int)floorf(yy), x0 = (int)floorf(xx);
        float wy = yy - (float)y0, wx = xx - (float)x0;
        int y0c = max(y0, 0), y1c = min(y0 + 1, 11);
        int x0c = max(x0, 0), x1c = min(x0 + 1, 11);

        const float* p3 = r + 2 * 2880;
        float v00x = p3[2 * (y0c * 12 + x0c)],     v00y = p3[2 * (y0c * 12 + x0c) + 1];
        float v01x = p3[2 * (y0c * 12 + x1c)],     v01y = p3[2 * (y0c * 12 + x1c) + 1];
        float v10x = p3[2 * (y1c * 12 + x0c)],     v10y = p3[2 * (y1c * 12 + x0c) + 1];
        float v11x = p3[2 * (y1c * 12 + x1c)],     v11y = p3[2 * (y1c * 12 + x1c) + 1];
        float p3x = (1.f - wy) * ((1.f - wx) * v00x + wx * v01x) + wy * ((1.f - wx) * v10x + wx * v11x);
        float p3y = (1.f - wy) * ((1.f - wx) * v00y + wx * v01y) + wy * ((1.f - wx) * v10y + wx * v11y);

        ref[((size_t)b * LQ + q) * 2 + 0] = (p1x + p2x + p3x) * (1.f / 3.f);
        ref[((size_t)b * LQ + q) * 2 + 1] = (p1y + p2y + p3y) * (1.f / 3.f);
    }
}

// ---------------------------------------------------------------------------
// Deformable sampling + softmax + attention-weighted accumulation
// One 64-thread block per (b, q, h); thread = d channel.
// ---------------------------------------------------------------------------
__global__ void sample_kernel(const float* __restrict__ off,
                              const float* __restrict__ logits,
                              const float* __restrict__ refp,
                              const float* __restrict__ val,
                              float* __restrict__ mid)
{
    const int bid = blockIdx.x;            // b*LQ*NH + q*NH + h
    const int h   = bid % NHEAD;
    const int bq  = bid / NHEAD;           // b*LQ + q
    const int b   = bq / LQ;
    const int dt  = threadIdx.x;           // 0..63

    // softmax over 12 (level, point) slots (redundant per-thread; broadcast loads)
    const float* lg = logits + (size_t)bq * (NHEAD * NLVL * NPTS) + h * (NLVL * NPTS);
    float w[12];
    float mx = -1e30f;
#pragma unroll
    for (int i = 0; i < 12; i++) { w[i] = lg[i]; mx = fmaxf(mx, w[i]); }
    float ssum = 0.f;
#pragma unroll
    for (int i = 0; i < 12; i++) { w[i] = __expf(w[i] - mx); ssum += w[i]; }
    const float inv = 1.f / ssum;

    const float* op = off + (size_t)bq * (NHEAD * NLVL * NPTS * 2) + h * (NLVL * NPTS * 2);
    const float rx = refp[(size_t)bq * 2];
    const float ry = refp[(size_t)bq * 2 + 1];

    const int lvlStart[NLVL] = {0, 2304, 2880};
    const int lvlH[NLVL] = {48, 24, 12};
    const int lvlW[NLVL] = {48, 24, 12};

    float acc = 0.f;
#pragma unroll
    for (int lv = 0; lv < NLVL; lv++) {
        const int Hl = lvlH[lv], Wl = lvlW[lv], st = lvlStart[lv];
#pragma unroll
        for (int p = 0; p < NPTS; p++) {
            float cx = op[lv * (NPTS * 2) + p * 2 + 0] + rx;
            float cy = op[lv * (NPTS * 2) + p * 2 + 1] + ry;
            float px = cx * (float)Wl - 0.5f;
            float py = cy * (float)Hl - 0.5f;
            float x0f = floorf(px), y0f = floorf(py);
            float lx = px - x0f, ly = py - y0f;
            int x0 = (int)x0f, y0 = (int)y0f;
            int x1 = x0 + 1,   y1 = y0 + 1;

            const float aw = w[lv * NPTS + p] * inv;

            float v00 = 0.f, v10 = 0.f, v01 = 0.f, v11 = 0.f;
            bool vx0 = (x0 >= 0) & (x0 < Wl);
            bool vx1 = (x1 >= 0) & (x1 < Wl);
            bool vy0 = (y0 >= 0) & (y0 < Hl);
            bool vy1 = (y1 >= 0) & (y1 < Hl);
            // val index: ((b*LV + st + y*Wl + x) * NHEAD + h) * DHEAD + dt
            size_t base = ((size_t)b * LV + st) * CDIM + (size_t)h * DHEAD + dt;
            if (vy0 & vx0) v00 = val[base + (size_t)(y0 * Wl + x0) * CDIM];
            if (vy0 & vx1) v10 = val[base + (size_t)(y0 * Wl + x1) * CDIM];
            if (vy1 & vx0) v01 = val[base + (size_t)(y1 * Wl + x0) * CDIM];
            if (vy1 & vx1) v11 = val[base + (size_t)(y1 * Wl + x1) * CDIM];

            float s = (1.f - lx) * (1.f - ly) * v00 + lx * (1.f - ly) * v10
                    + (1.f - lx) * ly * v01 + lx * ly * v11;
            acc += aw * s;
        }
    }

    mid[(size_t)bq * CDIM + h * DHEAD + dt] = acc;
}

// ---------------------------------------------------------------------------
extern "C" void kernel_launch(void* const* d_in, const int* in_sizes, int n_in,
                              void* d_out, int out_size)
{
    const float* query   = (const float*)d_in[0];
    const float* value   = (const float*)d_in[1];
    const float* rp      = (const float*)d_in[2];
    const float* W_value = (const float*)d_in[3];
    const float* b_value = (const float*)d_in[4];
    const float* W_off   = (const float*)d_in[5];
    const float* b_off   = (const float*)d_in[6];
    const float* W_attn  = (const float*)d_in[7];
    const float* b_attn  = (const float*)d_in[8];
    const float* W_out   = (const float*)d_in[9];
    const float* b_out   = (const float*)d_in[10];
    float* out = (float*)d_out;

    float *val, *off, *attn, *ref, *mid;
    cudaGetSymbolAddress((void**)&val,  g_val);
    cudaGetSymbolAddress((void**)&off,  g_off);
    cudaGetSymbolAddress((void**)&attn, g_attn);
    cudaGetSymbolAddress((void**)&ref,  g_ref);
    cudaGetSymbolAddress((void**)&mid,  g_mid);

    const int Mval = BATCH * LV;   // 96768
    const int Mq   = BATCH * LQ;   // 18432

    // value projection: (96768,384) @ (384,384) + b
    {
        dim3 g(CDIM / 64, Mval / 64);
        sgemm64<<<g, 256>>>(value, W_value, b_value, val, Mval, CDIM, CDIM);
    }
    // offsets: (18432,384) @ (384,144) + b
    {
        dim3 g((144 + 63) / 64, Mq / 64);
        sgemm64<<<g, 256>>>(query, W_off, b_off, off, Mq, 144, CDIM);
    }
    // attn logits: (18432,384) @ (384,72) + b
    {
        dim3 g((72 + 63) / 64, Mq / 64);
        sgemm64<<<g, 256>>>(query, W_attn, b_attn, attn, Mq, 72, CDIM);
    }
    // reference points
    ref_kernel<<<BATCH, 256>>>(rp, ref);

    // deformable sampling
    sample_kernel<<<BATCH * LQ * NHEAD, DHEAD>>>(off, attn, ref, val, mid);

    // output projection: (18432,384) @ (384,384) + b
    {
        dim3 g(CDIM / 64, Mq / 64);
        sgemm64<<<g, 256>>>(mid, W_out, b_out, out, Mq, CDIM, CDIM);
    }
}

// round 2
// speedup vs baseline: 1.6385x; 1.6385x over previous
#include <cuda_runtime.h>
#include <math.h>
#include <stdint.h>

// Problem constants
#define BATCH 32
#define LQ    576
#define LV    3024
#define CDIM  384
#define NHEAD 6
#define DHEAD 64
#define NLVL  3
#define NPTS  4

// Scratch (device globals; no dynamic allocation allowed)
__device__ float g_val [BATCH * LV * CDIM];
__device__ float g_off [BATCH * LQ * (NHEAD*NLVL*NPTS*2)];
__device__ float g_attn[BATCH * LQ * (NHEAD*NLVL*NPTS)];
__device__ float g_ref [BATCH * LQ * 2];
__device__ float g_mid [BATCH * LQ * CDIM];

__device__ __forceinline__ uint32_t f2tf32(float x) {
    uint32_t r;
    asm("cvt.rna.tf32.f32 %0, %1;" : "=r"(r) : "f"(x));
    return r;
}

#define MMA_TF32(C, Af, Bf) \
  asm volatile("mma.sync.aligned.m16n8k8.row.col.f32.tf32.tf32.f32 " \
    "{%0,%1,%2,%3}, {%4,%5,%6,%7}, {%8,%9}, {%0,%1,%2,%3};" \
    : "+f"(C[0]), "+f"(C[1]), "+f"(C[2]), "+f"(C[3]) \
    : "r"(Af[0]), "r"(Af[1]), "r"(Af[2]), "r"(Af[3]), "r"(Bf[0]), "r"(Bf[1]))

// ---------------------------------------------------------------------------
// TF32 tensor-core GEMM: C[M,N] = A[M,K] @ B[K,N] + bias[N]
// Block tile 128x64, 256 threads (8 warps: 4m x 2n), warp tile 32x32.
// M % 128 == 0, K % 32 == 0, N % 4 == 0.
// PRECISE: 3-pass error-compensated TF32 (hi*hi + hi*lo + lo*hi) ~ fp32 accuracy.
// ---------------------------------------------------------------------------
template<bool PRECISE>
__global__ __launch_bounds__(256, 2)
void gemm_tf32(const float* __restrict__ A, const float* __restrict__ Bm,
               const float* __restrict__ bias, float* __restrict__ Cm,
               int M, int N, int K)
{
    // A: [k8][row(128)][8] floats, col index = perm(c) ^ (k8<<1); perm(c)=2*(c&3)+(c>>2)
    __shared__ uint32_t AsH[4 * 128 * 8];
    // B: [k8][perm(k)(8)][n(64)]
    __shared__ uint32_t BsH[4 * 8 * 64];
    __shared__ uint32_t AsL[PRECISE ? 4 * 128 * 8 : 1];
    __shared__ uint32_t BsL[PRECISE ? 4 * 8 * 64 : 1];

    const int tid  = threadIdx.x;
    const int m0   = blockIdx.y * 128;
    const int n0   = blockIdx.x * 64;
    const int warp = tid >> 5, lane = tid & 31;
    const int g = lane >> 2, t = lane & 3;
    const int mwb = (warp >> 1) * 32;   // warp m base within block
    const int nwb = (warp & 1) * 32;    // warp n base within block

    // A ldg mapping: 4 passes, each thread one float4. row = arow + it*32
    const int arow = tid >> 3;          // 0..31
    const int acol = (tid & 7) * 4;     // 0..28
    const int ak8  = acol >> 3;
    const int ahb  = (acol >> 2) & 1;
    // B ldg mapping: 2 passes. k = bk + it*16
    const int bk = tid >> 4;            // 0..15
    const int bn = (tid & 15) * 4;      // 0..60

    float4 pa[4];
    float4 pb[2];
    float  cacc[2][4][4];
#pragma unroll
    for (int i = 0; i < 2; i++)
#pragma unroll
        for (int j = 0; j < 4; j++)
#pragma unroll
            for (int k = 0; k < 4; k++) cacc[i][j][k] = 0.f;

    const int nt = K / 32;

    // ---- prologue load ----
    {
        const float* p = A + (size_t)(m0 + arow) * K + acol;
#pragma unroll
        for (int it = 0; it < 4; it++) pa[it] = *(const float4*)(p + (size_t)it * 32 * K);
#pragma unroll
        for (int it = 0; it < 2; it++) {
            int col = n0 + bn;
            if (col < N) pb[it] = *(const float4*)&Bm[(size_t)(bk + it * 16) * N + col];
            else         pb[it] = make_float4(0.f, 0.f, 0.f, 0.f);
        }
    }

    for (int kt = 0; kt < nt; kt++) {
        // ---- STS current tile ----
#pragma unroll
        for (int it = 0; it < 4; it++) {
            int row = arow + it * 32;
            float v[4] = {pa[it].x, pa[it].y, pa[it].z, pa[it].w};
#pragma unroll
            for (int j = 0; j < 4; j++) {
                int idx = (2 * j + ahb) ^ (ak8 << 1);
                uint32_t h = f2tf32(v[j]);
                AsH[ak8 * 1024 + row * 8 + idx] = h;
                if (PRECISE)
                    AsL[ak8 * 1024 + row * 8 + idx] = f2tf32(v[j] - __uint_as_float(h));
            }
        }
#pragma unroll
        for (int it = 0; it < 2; it++) {
            int k   = bk + it * 16;
            int k8  = k >> 3, kk = k & 7;
            int perm = 2 * (kk & 3) + (kk >> 2);
            float v[4] = {pb[it].x, pb[it].y, pb[it].z, pb[it].w};
            uint32_t h0 = f2tf32(v[0]), h1 = f2tf32(v[1]), h2 = f2tf32(v[2]), h3 = f2tf32(v[3]);
            *(uint4*)&BsH[k8 * 512 + perm * 64 + bn] = make_uint4(h0, h1, h2, h3);
            if (PRECISE) {
                uint32_t l0 = f2tf32(v[0] - __uint_as_float(h0));
                uint32_t l1 = f2tf32(v[1] - __uint_as_float(h1));
                uint32_t l2 = f2tf32(v[2] - __uint_as_float(h2));
                uint32_t l3 = f2tf32(v[3] - __uint_as_float(h3));
                *(uint4*)&BsL[k8 * 512 + perm * 64 + bn] = make_uint4(l0, l1, l2, l3);
            }
        }
        __syncthreads();

        // ---- prefetch next tile into regs ----
        if (kt + 1 < nt) {
            const float* p = A + (size_t)(m0 + arow) * K + (kt + 1) * 32 + acol;
#pragma unroll
            for (int it = 0; it < 4; it++) pa[it] = *(const float4*)(p + (size_t)it * 32 * K);
#pragma unroll
            for (int it = 0; it < 2; it++) {
                int col = n0 + bn;
                if (col < N) pb[it] = *(const float4*)&Bm[(size_t)((kt + 1) * 32 + bk + it * 16) * N + col];
                else         pb[it] = make_float4(0.f, 0.f, 0.f, 0.f);
            }
        }

        // ---- compute on current smem tile ----
#pragma unroll
        for (int k8 = 0; k8 < 4; k8++) {
            uint32_t aH[2][4], bH[4][2];
            uint32_t aL[2][4], bL[4][2];
            const int cidx = (2 * t) ^ (k8 << 1);
#pragma unroll
            for (int i = 0; i < 2; i++) {
                int r = mwb + i * 16 + g;
                uint2 u0 = *(const uint2*)&AsH[k8 * 1024 + r * 8 + cidx];
                uint2 u1 = *(const uint2*)&AsH[k8 * 1024 + (r + 8) * 8 + cidx];
                aH[i][0] = u0.x; aH[i][2] = u0.y;
                aH[i][1] = u1.x; aH[i][3] = u1.y;
                if (PRECISE) {
                    uint2 v0 = *(const uint2*)&AsL[k8 * 1024 + r * 8 + cidx];
                    uint2 v1 = *(const uint2*)&AsL[k8 * 1024 + (r + 8) * 8 + cidx];
                    aL[i][0] = v0.x; aL[i][2] = v0.y;
                    aL[i][1] = v1.x; aL[i][3] = v1.y;
                }
            }
#pragma unroll
            for (int j = 0; j < 4; j++) {
                int n = nwb + j * 8 + g;
                bH[j][0] = BsH[k8 * 512 + (2 * t) * 64 + n];
                bH[j][1] = BsH[k8 * 512 + (2 * t + 1) * 64 + n];
                if (PRECISE) {
                    bL[j][0] = BsL[k8 * 512 + (2 * t) * 64 + n];
                    bL[j][1] = BsL[k8 * 512 + (2 * t + 1) * 64 + n];
                }
            }
#pragma unroll
            for (int i = 0; i < 2; i++)
#pragma unroll
                for (int j = 0; j < 4; j++) {
                    MMA_TF32(cacc[i][j], aH[i], bH[j]);
                    if (PRECISE) {
                        MMA_TF32(cacc[i][j], aH[i], bL[j]);
                        MMA_TF32(cacc[i][j], aL[i], bH[j]);
                    }
                }
        }
        __syncthreads();
    }

    // ---- epilogue: bias + store (cols even, N even -> float2 safe) ----
#pragma unroll
    for (int i = 0; i < 2; i++) {
#pragma unroll
        for (int j = 0; j < 4; j++) {
            int row = m0 + mwb + i * 16 + g;
            int col = n0 + nwb + j * 8 + 2 * t;
            if (col < N) {
                float b0 = bias[col], b1 = bias[col + 1];
                *(float2*)&Cm[(size_t)row * N + col] =
                    make_float2(cacc[i][j][0] + b0, cacc[i][j][1] + b1);
                *(float2*)&Cm[(size_t)(row + 8) * N + col] =
                    make_float2(cacc[i][j][2] + b0, cacc[i][j][3] + b1);
            }
        }
    }
}

// ---------------------------------------------------------------------------
// Reference-point processing (unchanged)
// ---------------------------------------------------------------------------
__global__ void ref_kernel(const float* __restrict__ rp, float* __restrict__ ref)
{
    const int b = blockIdx.x;
    const float* r = rp + (size_t)b * LV * 2;

    __shared__ float redx[256], redy[256];
    float ax = 0.f, ay = 0.f;
    for (int i = threadIdx.x; i < 2304; i += 256) {
        ax += r[2 * i];
        ay += r[2 * i + 1];
    }
    redx[threadIdx.x] = ax; redy[threadIdx.x] = ay;
    __syncthreads();
    for (int s = 128; s > 0; s >>= 1) {
        if (threadIdx.x < s) {
            redx[threadIdx.x] += redx[threadIdx.x + s];
            redy[threadIdx.x] += redy[threadIdx.x + s];
        }
        __syncthreads();
    }
    const float p1x = redx[0] * (1.f / 2304.f);
    const float p1y = redy[0] * (1.f / 2304.f);

    for (int q = threadIdx.x; q < LQ; q += 256) {
        float p2x = r[2 * (2304 + q)];
        float p2y = r[2 * (2304 + q) + 1];

        int rr = q / 24, cc = q % 24;
        float yy = 0.5f * rr - 0.25f;
        float xx = 0.5f * cc - 0.25f;
        int y0 = (int)floorf(yy), x0 = (int)floorf(xx);
        float wy = yy - (float)y0, wx = xx - (float)x0;
        int y0c = max(y0, 0), y1c = min(y0 + 1, 11);
        int x0c = max(x0, 0), x1c = min(x0 + 1, 11);

        const float* p3 = r + 2 * 2880;
        float v00x = p3[2 * (y0c * 12 + x0c)],     v00y = p3[2 * (y0c * 12 + x0c) + 1];
        float v01x = p3[2 * (y0c * 12 + x1c)],     v01y = p3[2 * (y0c * 12 + x1c) + 1];
        float v10x = p3[2 * (y1c * 12 + x0c)],     v10y = p3[2 * (y1c * 12 + x0c) + 1];
        float v11x = p3[2 * (y1c * 12 + x1c)],     v11y = p3[2 * (y1c * 12 + x1c) + 1];
        float p3x = (1.f - wy) * ((1.f - wx) * v00x + wx * v01x) + wy * ((1.f - wx) * v10x + wx * v11x);
        float p3y = (1.f - wy) * ((1.f - wx) * v00y + wx * v01y) + wy * ((1.f - wx) * v10y + wx * v11y);

        ref[((size_t)b * LQ + q) * 2 + 0] = (p1x + p2x + p3x) * (1.f / 3.f);
        ref[((size_t)b * LQ + q) * 2 + 1] = (p1y + p2y + p3y) * (1.f / 3.f);
    }
}

// ---------------------------------------------------------------------------
// Deformable sampling + softmax + weighted accumulation (unchanged)
// ---------------------------------------------------------------------------
__global__ void sample_kernel(const float* __restrict__ off,
                              const float* __restrict__ logits,
                              const float* __restrict__ refp,
                              const float* __restrict__ val,
                              float* __restrict__ mid)
{
    const int bid = blockIdx.x;            // b*LQ*NH + q*NH + h
    const int h   = bid % NHEAD;
    const int bq  = bid / NHEAD;
    const int b   = bq / LQ;
    const int dt  = threadIdx.x;

    const float* lg = logits + (size_t)bq * (NHEAD * NLVL * NPTS) + h * (NLVL * NPTS);
    float w[12];
    float mx = -1e30f;
#pragma unroll
    for (int i = 0; i < 12; i++) { w[i] = lg[i]; mx = fmaxf(mx, w[i]); }
    float ssum = 0.f;
#pragma unroll
    for (int i = 0; i < 12; i++) { w[i] = __expf(w[i] - mx); ssum += w[i]; }
    const float inv = 1.f / ssum;

    const float* op = off + (size_t)bq * (NHEAD * NLVL * NPTS * 2) + h * (NLVL * NPTS * 2);
    const float rx = refp[(size_t)bq * 2];
    const float ry = refp[(size_t)bq * 2 + 1];

    const int lvlStart[NLVL] = {0, 2304, 2880};
    const int lvlH[NLVL] = {48, 24, 12};
    const int lvlW[NLVL] = {48, 24, 12};

    float acc = 0.f;
#pragma unroll
    for (int lv = 0; lv < NLVL; lv++) {
        const int Hl = lvlH[lv], Wl = lvlW[lv], st = lvlStart[lv];
#pragma unroll
        for (int p = 0; p < NPTS; p++) {
            float cx = op[lv * (NPTS * 2) + p * 2 + 0] + rx;
            float cy = op[lv * (NPTS * 2) + p * 2 + 1] + ry;
            float px = cx * (float)Wl - 0.5f;
            float py = cy * (float)Hl - 0.5f;
            float x0f = floorf(px), y0f = floorf(py);
            float lx = px - x0f, ly = py - y0f;
            int x0 = (int)x0f, y0 = (int)y0f;
            int x1 = x0 + 1,   y1 = y0 + 1;

            const float aw = w[lv * NPTS + p] * inv;

            float v00 = 0.f, v10 = 0.f, v01 = 0.f, v11 = 0.f;
            bool vx0 = (x0 >= 0) & (x0 < Wl);
            bool vx1 = (x1 >= 0) & (x1 < Wl);
            bool vy0 = (y0 >= 0) & (y0 < Hl);
            bool vy1 = (y1 >= 0) & (y1 < Hl);
            size_t base = ((size_t)b * LV + st) * CDIM + (size_t)h * DHEAD + dt;
            if (vy0 & vx0) v00 = val[base + (size_t)(y0 * Wl + x0) * CDIM];
            if (vy0 & vx1) v10 = val[base + (size_t)(y0 * Wl + x1) * CDIM];
            if (vy1 & vx0) v01 = val[base + (size_t)(y1 * Wl + x0) * CDIM];
            if (vy1 & vx1) v11 = val[base + (size_t)(y1 * Wl + x1) * CDIM];

            float s = (1.f - lx) * (1.f - ly) * v00 + lx * (1.f - ly) * v10
                    + (1.f - lx) * ly * v01 + lx * ly * v11;
            acc += aw * s;
        }
    }

    mid[(size_t)bq * CDIM + h * DHEAD + dt] = acc;
}

// ---------------------------------------------------------------------------
extern "C" void kernel_launch(void* const* d_in, const int* in_sizes, int n_in,
                              void* d_out, int out_size)
{
    const float* query   = (const float*)d_in[0];
    const float* value   = (const float*)d_in[1];
    const float* rp      = (const float*)d_in[2];
    const float* W_value = (const float*)d_in[3];
    const float* b_value = (const float*)d_in[4];
    const float* W_off   = (const float*)d_in[5];
    const float* b_off   = (const float*)d_in[6];
    const float* W_attn  = (const float*)d_in[7];
    const float* b_attn  = (const float*)d_in[8];
    const float* W_out   = (const float*)d_in[9];
    const float* b_out   = (const float*)d_in[10];
    float* out = (float*)d_out;

    float *val, *off, *attn, *ref, *mid;
    cudaGetSymbolAddress((void**)&val,  g_val);
    cudaGetSymbolAddress((void**)&off,  g_off);
    cudaGetSymbolAddress((void**)&attn, g_attn);
    cudaGetSymbolAddress((void**)&ref,  g_ref);
    cudaGetSymbolAddress((void**)&mid,  g_mid);

    const int Mval = BATCH * LV;   // 96768
    const int Mq   = BATCH * LQ;   // 18432

    // value projection: (96768,384) @ (384,384)
    gemm_tf32<false><<<dim3(CDIM / 64, Mval / 128), 256>>>(value, W_value, b_value, val, Mval, CDIM, CDIM);
    // offsets (precision-critical): (18432,384) @ (384,144)
    gemm_tf32<true><<<dim3(3, Mq / 128), 256>>>(query, W_off, b_off, off, Mq, 144, CDIM);
    // attn logits: (18432,384) @ (384,72)
    gemm_tf32<false><<<dim3(2, Mq / 128), 256>>>(query, W_attn, b_attn, attn, Mq, 72, CDIM);
    // reference points
    ref_kernel<<<BATCH, 256>>>(rp, ref);
    // deformable sampling
    sample_kernel<<<BATCH * LQ * NHEAD, DHEAD>>>(off, attn, ref, val, mid);
    // output projection: (18432,384) @ (384,384)
    gemm_tf32<false><<<dim3(CDIM / 64, Mq / 128), 256>>>(mid, W_out, b_out, out, Mq, CDIM, CDIM);
}

// round 5
// speedup vs baseline: 1.9593x; 1.1958x over previous
#include <cuda_runtime.h>
#include <cuda_fp16.h>
#include <math.h>
#include <stdint.h>

// Problem constants
#define BATCH 32
#define LQ    576
#define LV    3024
#define CDIM  384
#define NHEAD 6
#define DHEAD 64
#define NLVL  3
#define NPTS  4

// Scratch (device globals; no dynamic allocation allowed)
__device__ __half g_val [BATCH * LV * CDIM];                 // value projection (fp16)
__device__ float  g_off [BATCH * LQ * (NHEAD*NLVL*NPTS*2)];
__device__ float  g_attn[BATCH * LQ * (NHEAD*NLVL*NPTS)];
__device__ float  g_ref [BATCH * LQ * 2];
__device__ float  g_mid [BATCH * LQ * CDIM];

// ===========================================================================
// fp16 tensor-core GEMM via mma.sync.m16n8k16: C[M,N] = A[M,K] @ B[K,N] + bias
// Block tile 128x64, 256 threads (8 warps: 4m x 2n), warp tile 32x32, KT=32.
// M % 128 == 0, K % 32 == 0. N arbitrary multiple of 4.
// PRECISE: 3-pass compensated fp16 (hi*hi + hi*lo + lo*hi) ~ 21-bit accuracy.
// Smem stride 40 halves (80B): 8 consecutive rows' 16B windows cover all 32
// banks (i*80 mod 128 = {0,80,32,112,64,16,96,48}) -> conflict-free frag LDS.
// ===========================================================================
#define MMA_F16(Cc, Af, Bf) \
  asm volatile("mma.sync.aligned.m16n8k16.row.col.f32.f16.f16.f32 " \
    "{%0,%1,%2,%3}, {%4,%5,%6,%7}, {%8,%9}, {%0,%1,%2,%3};" \
    : "+f"(Cc[0]), "+f"(Cc[1]), "+f"(Cc[2]), "+f"(Cc[3]) \
    : "r"(Af[0]), "r"(Af[1]), "r"(Af[2]), "r"(Af[3]), "r"(Bf[0]), "r"(Bf[1]))

__device__ __forceinline__ uint32_t pack_h2(float a, float b) {
    __half2 t = __floats2half2_rn(a, b);
    return *(uint32_t*)&t;
}

template<bool PRECISE, typename OutT>
__global__ __launch_bounds__(256, 2)
void gemm_f16(const float* __restrict__ A, const float* __restrict__ Bm,
              const float* __restrict__ bias, OutT* __restrict__ Cm,
              int M, int N, int K)
{
    __shared__ __half AsH[128 * 40];
    __shared__ __half BsH[64 * 40];
    __shared__ __half AsL[PRECISE ? 128 * 40 : 2];
    __shared__ __half BsL[PRECISE ? 64 * 40 : 2];

    const int tid  = threadIdx.x;
    const int m0   = blockIdx.y * 128;
    const int n0   = blockIdx.x * 64;
    const int warp = tid >> 5, lane = tid & 31;
    const int g = lane >> 2, t = lane & 3;
    const int mwb = (warp >> 1) * 32;   // warp m base
    const int nwb = (warp & 1) * 32;    // warp n base

    // A ldg: 256 threads, 128 rows x 32 k. 2 threads/row, 16 k each (4 float4).
    const int arow = tid >> 1;
    const int ak   = (tid & 1) * 16;
    // B ldg: 2 passes of k16. thread: k=bk(+16), n=bn4..bn4+3.
    const int bk  = tid >> 4;           // 0..15
    const int bn4 = (tid & 15) * 4;     // 0..60

    float4 pa[4];
    float4 pb[2];
    float  cacc[2][4][4];
#pragma unroll
    for (int i = 0; i < 2; i++)
#pragma unroll
        for (int j = 0; j < 4; j++)
#pragma unroll
            for (int k = 0; k < 4; k++) cacc[i][j][k] = 0.f;

    const int nt = K / 32;

    // ---- prologue loads ----
    {
        const float* p = A + (size_t)(m0 + arow) * K + ak;
#pragma unroll
        for (int j = 0; j < 4; j++) pa[j] = *(const float4*)(p + j * 4);
        int col = n0 + bn4;
#pragma unroll
        for (int it = 0; it < 2; it++) {
            if (col < N) pb[it] = *(const float4*)&Bm[(size_t)(bk + it * 16) * N + col];
            else         pb[it] = make_float4(0.f, 0.f, 0.f, 0.f);
        }
    }

    for (int kt = 0; kt < nt; kt++) {
        // ---- STS A ----
#pragma unroll
        for (int j = 0; j < 4; j++) {
            float4 v = pa[j];
            __half h0 = __float2half_rn(v.x), h1 = __float2half_rn(v.y);
            __half h2 = __float2half_rn(v.z), h3 = __float2half_rn(v.w);
            __half2 p0 = __halves2half2(h0, h1), p1 = __halves2half2(h2, h3);
            *(uint2*)&AsH[arow * 40 + ak + j * 4] =
                make_uint2(*(uint32_t*)&p0, *(uint32_t*)&p1);
            if (PRECISE) {
                *(uint2*)&AsL[arow * 40 + ak + j * 4] = make_uint2(
                    pack_h2(v.x - __half2float(h0), v.y - __half2float(h1)),
                    pack_h2(v.z - __half2float(h2), v.w - __half2float(h3)));
            }
        }
        // ---- STS B (transposed: Bs[n][k]) ----
#pragma unroll
        for (int it = 0; it < 2; it++) {
            int k = bk + it * 16;
            float v[4] = {pb[it].x, pb[it].y, pb[it].z, pb[it].w};
#pragma unroll
            for (int j = 0; j < 4; j++) {
                __half h = __float2half_rn(v[j]);
                BsH[(bn4 + j) * 40 + k] = h;
                if (PRECISE)
                    BsL[(bn4 + j) * 40 + k] = __float2half_rn(v[j] - __half2float(h));
            }
        }
        __syncthreads();

        // ---- prefetch next tile ----
        if (kt + 1 < nt) {
            const float* p = A + (size_t)(m0 + arow) * K + (kt + 1) * 32 + ak;
#pragma unroll
            for (int j = 0; j < 4; j++) pa[j] = *(const float4*)(p + j * 4);
            int col = n0 + bn4;
#pragma unroll
            for (int it = 0; it < 2; it++) {
                if (col < N) pb[it] = *(const float4*)&Bm[(size_t)((kt + 1) * 32 + bk + it * 16) * N + col];
                else         pb[it] = make_float4(0.f, 0.f, 0.f, 0.f);
            }
        }

        // ---- compute: 2 k16 steps ----
#pragma unroll
        for (int ks = 0; ks < 2; ks++) {
            const int kb = ks * 16;
            uint32_t aH[2][4], bH[4][2];
            uint32_t aL[2][4], bL[4][2];
#pragma unroll
            for (int mi = 0; mi < 2; mi++) {
                int r = mwb + mi * 16 + g;
                aH[mi][0] = *(const uint32_t*)&AsH[r * 40 + kb + 2 * t];
                aH[mi][1] = *(const uint32_t*)&AsH[(r + 8) * 40 + kb + 2 * t];
                aH[mi][2] = *(const uint32_t*)&AsH[r * 40 + kb + 8 + 2 * t];
                aH[mi][3] = *(const uint32_t*)&AsH[(r + 8) * 40 + kb + 8 + 2 * t];
                if (PRECISE) {
                    aL[mi][0] = *(const uint32_t*)&AsL[r * 40 + kb + 2 * t];
                    aL[mi][1] = *(const uint32_t*)&AsL[(r + 8) * 40 + kb + 2 * t];
                    aL[mi][2] = *(const uint32_t*)&AsL[r * 40 + kb + 8 + 2 * t];
                    aL[mi][3] = *(const uint32_t*)&AsL[(r + 8) * 40 + kb + 8 + 2 * t];
                }
            }
#pragma unroll
            for (int nj = 0; nj < 4; nj++) {
                int n = nwb + nj * 8 + g;
                bH[nj][0] = *(const uint32_t*)&BsH[n * 40 + kb + 2 * t];
                bH[nj][1] = *(const uint32_t*)&BsH[n * 40 + kb + 8 + 2 * t];
                if (PRECISE) {
                    bL[nj][0] = *(const uint32_t*)&BsL[n * 40 + kb + 2 * t];
                    bL[nj][1] = *(const uint32_t*)&BsL[n * 40 + kb + 8 + 2 * t];
                }
            }
#pragma unroll
            for (int mi = 0; mi < 2; mi++)
#pragma unroll
                for (int nj = 0; nj < 4; nj++) {
                    MMA_F16(cacc[mi][nj], aH[mi], bH[nj]);
                    if (PRECISE) {
                        MMA_F16(cacc[mi][nj], aH[mi], bL[nj]);
                        MMA_F16(cacc[mi][nj], aL[mi], bH[nj]);
                    }
                }
        }
        __syncthreads();
    }

    // ---- epilogue: bias + store. c0,c1 @ (row, col..col+1); c2,c3 @ row+8 ----
#pragma unroll
    for (int mi = 0; mi < 2; mi++) {
#pragma unroll
        for (int nj = 0; nj < 4; nj++) {
            int row = m0 + mwb + mi * 16 + g;
            int col = n0 + nwb + nj * 8 + 2 * t;
            if (col < N) {
                float b0 = bias[col], b1 = bias[col + 1];
                float v00 = cacc[mi][nj][0] + b0, v01 = cacc[mi][nj][1] + b1;
                float v10 = cacc[mi][nj][2] + b0, v11 = cacc[mi][nj][3] + b1;
                if (sizeof(OutT) == 4) {
                    *(float2*)((float*)Cm + (size_t)row * N + col) = make_float2(v00, v01);
                    *(float2*)((float*)Cm + (size_t)(row + 8) * N + col) = make_float2(v10, v11);
                } else {
                    __half2 h0 = __floats2half2_rn(v00, v01);
                    __half2 h1 = __floats2half2_rn(v10, v11);
                    *(__half2*)((__half*)Cm + (size_t)row * N + col) = h0;
                    *(__half2*)((__half*)Cm + (size_t)(row + 8) * N + col) = h1;
                }
            }
        }
    }
}

// ===========================================================================
// Reference-point processing
// ===========================================================================
__global__ void ref_kernel(const float* __restrict__ rp, float* __restrict__ ref)
{
    const int b = blockIdx.x;
    const float* r = rp + (size_t)b * LV * 2;

    __shared__ float redx[256], redy[256];
    float ax = 0.f, ay = 0.f;
    for (int i = threadIdx.x; i < 2304; i += 256) {
        ax += r[2 * i];
        ay += r[2 * i + 1];
    }
    redx[threadIdx.x] = ax; redy[threadIdx.x] = ay;
    __syncthreads();
    for (int s = 128; s > 0; s >>= 1) {
        if (threadIdx.x < s) {
            redx[threadIdx.x] += redx[threadIdx.x + s];
            redy[threadIdx.x] += redy[threadIdx.x + s];
        }
        __syncthreads();
    }
    const float p1x = redx[0] * (1.f / 2304.f);
    const float p1y = redy[0] * (1.f / 2304.f);

    for (int q = threadIdx.x; q < LQ; q += 256) {
        float p2x = r[2 * (2304 + q)];
        float p2y = r[2 * (2304 + q) + 1];

        int rr = q / 24, cc = q % 24;
        float yy = 0.5f * rr - 0.25f;
        float xx = 0.5f * cc - 0.25f;
        int y0 = (int)floorf(yy), x0 = (int)floorf(xx);
        float wy = yy - (float)y0, wx = xx - (float)x0;
        int y0c = max(y0, 0), y1c = min(y0 + 1, 11);
        int x0c = max(x0, 0), x1c = min(x0 + 1, 11);

        const float* p3 = r + 2 * 2880;
        float v00x = p3[2 * (y0c * 12 + x0c)],     v00y = p3[2 * (y0c * 12 + x0c) + 1];
        float v01x = p3[2 * (y0c * 12 + x1c)],     v01y = p3[2 * (y0c * 12 + x1c) + 1];
        float v10x = p3[2 * (y1c * 12 + x0c)],     v10y = p3[2 * (y1c * 12 + x0c) + 1];
        float v11x = p3[2 * (y1c * 12 + x1c)],     v11y = p3[2 * (y1c * 12 + x1c) + 1];
        float p3x = (1.f - wy) * ((1.f - wx) * v00x + wx * v01x) + wy * ((1.f - wx) * v10x + wx * v11x);
        float p3y = (1.f - wy) * ((1.f - wx) * v00y + wx * v01y) + wy * ((1.f - wx) * v10y + wx * v11y);

        ref[((size_t)b * LQ + q) * 2 + 0] = (p1x + p2x + p3x) * (1.f / 3.f);
        ref[((size_t)b * LQ + q) * 2 + 1] = (p1y + p2y + p3y) * (1.f / 3.f);
    }
}

// ===========================================================================
// Deformable sampling: 1 block per (b,q), 192 threads = 6 heads x 32 lanes.
// Each lane handles 2 channels via __half2 gathers.
// ===========================================================================
__global__ __launch_bounds__(192)
void sample_kernel(const float* __restrict__ off,
                   const float* __restrict__ logits,
                   const float* __restrict__ refp,
                   const __half* __restrict__ val,
                   float* __restrict__ mid)
{
    const int bq   = blockIdx.x;            // b*LQ + q
    const int b    = bq / LQ;
    const int h    = threadIdx.x >> 5;      // 0..5
    const int lane = threadIdx.x & 31;

    // softmax over 12 slots (per-thread; warp-uniform broadcast loads)
    const float* lg = logits + (size_t)bq * (NHEAD * NLVL * NPTS) + h * (NLVL * NPTS);
    float w[12];
    float mx = -1e30f;
#pragma unroll
    for (int i = 0; i < 12; i++) { w[i] = lg[i]; mx = fmaxf(mx, w[i]); }
    float ssum = 0.f;
#pragma unroll
    for (int i = 0; i < 12; i++) { w[i] = __expf(w[i] - mx); ssum += w[i]; }
    const float inv = 1.f / ssum;

    const float* op = off + (size_t)bq * (NHEAD * NLVL * NPTS * 2) + h * (NLVL * NPTS * 2);
    const float rx = refp[(size_t)bq * 2];
    const float ry = refp[(size_t)bq * 2 + 1];

    const int lvlStart[NLVL] = {0, 2304, 2880};
    const int lvlH[NLVL] = {48, 24, 12};
    const int lvlW[NLVL] = {48, 24, 12};

    float accx = 0.f, accy = 0.f;
#pragma unroll
    for (int lv = 0; lv < NLVL; lv++) {
        const int Hl = lvlH[lv], Wl = lvlW[lv], st = lvlStart[lv];
        const size_t base = ((size_t)b * LV + st) * CDIM + (size_t)h * DHEAD + 2 * lane;
#pragma unroll
        for (int p = 0; p < NPTS; p++) {
            float cx = op[lv * (NPTS * 2) + p * 2 + 0] + rx;
            float cy = op[lv * (NPTS * 2) + p * 2 + 1] + ry;
            float px = cx * (float)Wl - 0.5f;
            float py = cy * (float)Hl - 0.5f;
            float x0f = floorf(px), y0f = floorf(py);
            float lx = px - x0f, ly = py - y0f;
            int x0 = (int)x0f, y0 = (int)y0f;
            int x1 = x0 + 1,   y1 = y0 + 1;

            const float aw = w[lv * NPTS + p] * inv;

            bool vx0 = (x0 >= 0) & (x0 < Wl);
            bool vx1 = (x1 >= 0) & (x1 < Wl);
            bool vy0 = (y0 >= 0) & (y0 < Hl);
            bool vy1 = (y1 >= 0) & (y1 < Hl);

            float2 v00 = {0.f, 0.f}, v10 = {0.f, 0.f}, v01 = {0.f, 0.f}, v11 = {0.f, 0.f};
            if (vy0 & vx0) v00 = __half22float2(*(const __half2*)&val[base + (size_t)(y0 * Wl + x0) * CDIM]);
            if (vy0 & vx1) v10 = __half22float2(*(const __half2*)&val[base + (size_t)(y0 * Wl + x1) * CDIM]);
            if (vy1 & vx0) v01 = __half22float2(*(const __half2*)&val[base + (size_t)(y1 * Wl + x0) * CDIM]);
            if (vy1 & vx1) v11 = __half22float2(*(const __half2*)&val[base + (size_t)(y1 * Wl + x1) * CDIM]);

            float w00 = (1.f - lx) * (1.f - ly), w10 = lx * (1.f - ly);
            float w01 = (1.f - lx) * ly,         w11 = lx * ly;
            accx += aw * (w00 * v00.x + w10 * v10.x + w01 * v01.x + w11 * v11.x);
            accy += aw * (w00 * v00.y + w10 * v10.y + w01 * v01.y + w11 * v11.y);
        }
    }

    *(float2*)&mid[(size_t)bq * CDIM + h * DHEAD + 2 * lane] = make_float2(accx, accy);
}

// ===========================================================================
extern "C" void kernel_launch(void* const* d_in, const int* in_sizes, int n_in,
                              void* d_out, int out_size)
{
    const float* query   = (const float*)d_in[0];
    const float* value   = (const float*)d_in[1];
    const float* rp      = (const float*)d_in[2];
    const float* W_value = (const float*)d_in[3];
    const float* b_value = (const float*)d_in[4];
    const float* W_off   = (const float*)d_in[5];
    const float* b_off   = (const float*)d_in[6];
    const float* W_attn  = (const float*)d_in[7];
    const float* b_attn  = (const float*)d_in[8];
    const float* W_out   = (const float*)d_in[9];
    const float* b_out   = (const float*)d_in[10];
    float* out = (float*)d_out;

    __half* val;  float *off, *attn, *ref, *mid;
    cudaGetSymbolAddress((void**)&val,  g_val);
    cudaGetSymbolAddress((void**)&off,  g_off);
    cudaGetSymbolAddress((void**)&attn, g_attn);
    cudaGetSymbolAddress((void**)&ref,  g_ref);
    cudaGetSymbolAddress((void**)&mid,  g_mid);

    const int Mval = BATCH * LV;   // 96768
    const int Mq   = BATCH * LQ;   // 18432

    // value projection: (96768,384)@(384,384) -> fp16
    gemm_f16<false, __half><<<dim3(6, Mval / 128), 256>>>(value, W_value, b_value, val, Mval, CDIM, CDIM);
    // offsets (precision-critical, 3-pass): (18432,384)@(384,144)
    gemm_f16<true, float><<<dim3(3, Mq / 128), 256>>>(query, W_off, b_off, off, Mq, 144, CDIM);
    // attn logits: (18432,384)@(384,72)
    gemm_f16<false, float><<<dim3(2, Mq / 128), 256>>>(query, W_attn, b_attn, attn, Mq, 72, CDIM);
    // reference points
    ref_kernel<<<BATCH, 256>>>(rp, ref);
    // deformable sampling
    sample_kernel<<<BATCH * LQ, 192>>>(off, attn, ref, val, mid);
    // output projection: (18432,384)@(384,384) -> fp32
    gemm_f16<false, float><<<dim3(6, Mq / 128), 256>>>(mid, W_out, b_out, out, Mq, CDIM, CDIM);
}

// round 7
// speedup vs baseline: 3.2024x; 1.6344x over previous
#include <cuda_runtime.h>
#include <cuda_fp16.h>
#include <math.h>
#include <stdint.h>

// Problem constants
#define BATCH 32
#define LQ    576
#define LV    3024
#define CDIM  384
#define NHEAD 6
#define DHEAD 64
#define NLVL  3
#define NPTS  4

// Scratch (device globals; no dynamic allocation allowed)
__device__ __half g_val    [BATCH * LV * CDIM];    // value projection (fp16)
__device__ __half g_value_h[BATCH * LV * CDIM];    // fp16 copy of input value
__device__ __half g_query_h[BATCH * LQ * CDIM];    // fp16 copy of query
__device__ __half g_mid_h  [BATCH * LQ * CDIM];    // sampled output (fp16)
__device__ __half g_Wv_h[CDIM * CDIM];             // fp16 weights
__device__ __half g_Wo_h[CDIM * CDIM];
__device__ __half g_Wa_h[CDIM * 128];              // W_attn padded 72 -> 128
__device__ float  g_off [BATCH * LQ * (NHEAD*NLVL*NPTS*2)];
__device__ float  g_attn[BATCH * LQ * (NHEAD*NLVL*NPTS)];
__device__ float  g_ref [BATCH * LQ * 2];

// ===========================================================================
// helpers
// ===========================================================================
__device__ __forceinline__ uint32_t smem_u32(const void* p) {
    uint32_t a;
    asm("{ .reg .u64 t; cvta.to.shared.u64 t, %1; cvt.u32.u64 %0, t; }" : "=r"(a) : "l"(p));
    return a;
}
__device__ __forceinline__ void cp_async16(uint32_t dst, const void* src) {
    asm volatile("cp.async.cg.shared.global [%0], [%1], 16;" :: "r"(dst), "l"(src));
}
__device__ __forceinline__ void cp_commit() {
    asm volatile("cp.async.commit_group;");
}
__device__ __forceinline__ void ldsm4(uint32_t* r, uint32_t a) {
    asm volatile("ldmatrix.sync.aligned.m8n8.x4.shared.b16 {%0,%1,%2,%3}, [%4];"
        : "=r"(r[0]), "=r"(r[1]), "=r"(r[2]), "=r"(r[3]) : "r"(a));
}
__device__ __forceinline__ void ldsm4t(uint32_t* r, uint32_t a) {
    asm volatile("ldmatrix.sync.aligned.m8n8.x4.trans.shared.b16 {%0,%1,%2,%3}, [%4];"
        : "=r"(r[0]), "=r"(r[1]), "=r"(r[2]), "=r"(r[3]) : "r"(a));
}
#define MMA_F16(Cc, Af, Bf) \
  asm volatile("mma.sync.aligned.m16n8k16.row.col.f32.f16.f16.f32 " \
    "{%0,%1,%2,%3}, {%4,%5,%6,%7}, {%8,%9}, {%0,%1,%2,%3};" \
    : "+f"(Cc[0]), "+f"(Cc[1]), "+f"(Cc[2]), "+f"(Cc[3]) \
    : "r"(Af[0]), "r"(Af[1]), "r"(Af[2]), "r"(Af[3]), "r"(Bf[0]), "r"(Bf[1]))

__device__ __forceinline__ uint32_t pack_h2(float a, float b) {
    __half2 t = __floats2half2_rn(a, b);
    return *(uint32_t*)&t;
}

// ===========================================================================
// Conversion prep kernels
// ===========================================================================
__global__ void conv_f16(const float* __restrict__ in, __half* __restrict__ outp, int n4)
{
    int i = blockIdx.x * 256 + threadIdx.x;
    if (i < n4) {
        float4 v = ((const float4*)in)[i];
        ((uint2*)outp)[i] = make_uint2(pack_h2(v.x, v.y), pack_h2(v.z, v.w));
    }
}

__global__ void conv_w(const float* __restrict__ Wv, const float* __restrict__ Wo,
                       const float* __restrict__ Wa,
                       __half* __restrict__ wv, __half* __restrict__ wo, __half* __restrict__ wa)
{
    int i = blockIdx.x * 256 + threadIdx.x;   // 0 .. 344063
    if (i < CDIM * CDIM) {
        wv[i] = __float2half_rn(Wv[i]);
    } else if (i < 2 * CDIM * CDIM) {
        int j = i - CDIM * CDIM;
        wo[j] = __float2half_rn(Wo[j]);
    } else {
        int j = i - 2 * CDIM * CDIM;          // 0 .. 49151
        int r = j >> 7, c = j & 127;
        wa[j] = (c < 72) ? __float2half_rn(Wa[r * 72 + c]) : __half(0.f);
    }
}

// ===========================================================================
// Fast fp16 GEMM: C[M,N] = Ah[M,K] @ Bh[K,Bw](cols n0..n0+127) + bias
// 128x128 block tile, 256 threads (8 warps: 4m x 2n, warp tile 32x64), KT=32.
// cp.async double-buffered; ldmatrix fragment loads.
// A smem: [row][40 halves] (80B stride, conflict-free LDSM).
// B smem: [k][136 halves]  (272B stride, conflict-free LDSM.trans).
// ===========================================================================
#define ASTB 10240   // bytes per A stage
#define BSTB 8704    // bytes per B stage

template<typename OutT>
__global__ __launch_bounds__(256, 2)
void gemm_f16_fast(const __half* __restrict__ A, const __half* __restrict__ B,
                   const float* __restrict__ bias, OutT* __restrict__ C,
                   int M, int N, int K, int Bw)
{
    __shared__ __align__(16) __half As[2][128 * 40];
    __shared__ __align__(16) __half Bs[2][32 * 136];

    const int tid  = threadIdx.x;
    const int m0   = blockIdx.y * 128;
    const int n0   = blockIdx.x * 128;
    const int warp = tid >> 5, lane = tid & 31;
    const int g = lane >> 2, t = lane & 3;
    const int mwb = (warp >> 1) * 32;
    const int nwb = (warp & 1) * 64;

    const uint32_t sA = smem_u32(As);
    const uint32_t sB = smem_u32(Bs);

    // cp.async mappings
    const int arow = tid >> 2;            // 0..63 (and +64)
    const int ac   = tid & 3;             // chunk within row (16B)
    const int brow = tid >> 4;            // 0..15 (and +16)
    const int bc   = tid & 15;            // chunk (16B = 8 n)
    const __half* agp = A + (size_t)(m0 + arow) * K + ac * 8;
    const __half* bgp = B + (size_t)brow * Bw + n0 + bc * 8;
    const uint32_t adp = sA + arow * 80 + ac * 16;
    const uint32_t bdp = sB + brow * 272 + bc * 16;

    // ldmatrix per-lane offsets
    const uint32_t aOff = ((lane & 15) * 40 + (lane >> 4) * 8) * 2 + mwb * 80;
    const uint32_t bOff = ((lane & 15) * 136 + (lane >> 4) * 8) * 2 + nwb * 2;

    float cacc[2][8][4];
#pragma unroll
    for (int i = 0; i < 2; i++)
#pragma unroll
        for (int j = 0; j < 8; j++)
#pragma unroll
            for (int k = 0; k < 4; k++) cacc[i][j][k] = 0.f;

    const int nt = K / 32;

    // stage loader
    auto load_stage = [&](int kt, int s) {
        const __half* ag = agp + kt * 32;
        uint32_t ad = adp + s * ASTB;
        cp_async16(ad, ag);
        cp_async16(ad + 64 * 80, ag + (size_t)64 * K);
        const __half* bg = bgp + (size_t)(kt * 32) * Bw;
        uint32_t bd = bdp + s * BSTB;
        cp_async16(bd, bg);
        cp_async16(bd + 16 * 272, bg + (size_t)16 * Bw);
    };

    load_stage(0, 0);
    cp_commit();

    for (int kt = 0; kt < nt; kt++) {
        if (kt + 1 < nt) {
            load_stage(kt + 1, (kt + 1) & 1);
            cp_commit();
            asm volatile("cp.async.wait_group 1;");
        } else {
            asm volatile("cp.async.wait_group 0;");
        }
        __syncthreads();

        const int s = kt & 1;
        const uint32_t aBase = sA + s * ASTB + aOff;
        const uint32_t bBase = sB + s * BSTB + bOff;
#pragma unroll
        for (int ks = 0; ks < 2; ks++) {
            uint32_t aH[2][4], bF[4][4];
            ldsm4(aH[0], aBase + ks * 32);
            ldsm4(aH[1], aBase + 16 * 80 + ks * 32);
#pragma unroll
            for (int p = 0; p < 4; p++)
                ldsm4t(bF[p], bBase + ks * 16 * 272 + p * 32);
#pragma unroll
            for (int mi = 0; mi < 2; mi++)
#pragma unroll
                for (int nj = 0; nj < 8; nj++) {
                    uint32_t bfr[2] = { bF[nj >> 1][(nj & 1) * 2], bF[nj >> 1][(nj & 1) * 2 + 1] };
                    MMA_F16(cacc[mi][nj], aH[mi], bfr);
                }
        }
        __syncthreads();
    }

    // epilogue
#pragma unroll
    for (int mi = 0; mi < 2; mi++) {
#pragma unroll
        for (int nj = 0; nj < 8; nj++) {
            int row = m0 + mwb + mi * 16 + g;
            int col = n0 + nwb + nj * 8 + 2 * t;
            if (col < N) {
                float b0 = bias[col], b1 = bias[col + 1];
                float v00 = cacc[mi][nj][0] + b0, v01 = cacc[mi][nj][1] + b1;
                float v10 = cacc[mi][nj][2] + b0, v11 = cacc[mi][nj][3] + b1;
                if (sizeof(OutT) == 4) {
                    *(float2*)((float*)C + (size_t)row * N + col) = make_float2(v00, v01);
                    *(float2*)((float*)C + (size_t)(row + 8) * N + col) = make_float2(v10, v11);
                } else {
                    *(__half2*)((__half*)C + (size_t)row * N + col) = __floats2half2_rn(v00, v01);
                    *(__half2*)((__half*)C + (size_t)(row + 8) * N + col) = __floats2half2_rn(v10, v11);
                }
            }
        }
    }
}

// ===========================================================================
// 3-pass compensated fp16 GEMM (precision-critical offsets) — proven R5 path
// ===========================================================================
template<bool PRECISE>
__global__ __launch_bounds__(256, 2)
void gemm_f16(const float* __restrict__ A, const float* __restrict__ Bm,
              const float* __restrict__ bias, float* __restrict__ Cm,
              int M, int N, int K)
{
    __shared__ __half AsH[128 * 40];
    __shared__ __half BsH[64 * 40];
    __shared__ __half AsL[PRECISE ? 128 * 40 : 2];
    __shared__ __half BsL[PRECISE ? 64 * 40 : 2];

    const int tid  = threadIdx.x;
    const int m0   = blockIdx.y * 128;
    const int n0   = blockIdx.x * 64;
    const int warp = tid >> 5, lane = tid & 31;
    const int g = lane >> 2, t = lane & 3;
    const int mwb = (warp >> 1) * 32;
    const int nwb = (warp & 1) * 32;

    const int arow = tid >> 1;
    const int ak   = (tid & 1) * 16;
    const int bk  = tid >> 4;
    const int bn4 = (tid & 15) * 4;

    float4 pa[4];
    float4 pb[2];
    float  cacc[2][4][4];
#pragma unroll
    for (int i = 0; i < 2; i++)
#pragma unroll
        for (int j = 0; j < 4; j++)
#pragma unroll
            for (int k = 0; k < 4; k++) cacc[i][j][k] = 0.f;

    const int nt = K / 32;
    {
        const float* p = A + (size_t)(m0 + arow) * K + ak;
#pragma unroll
        for (int j = 0; j < 4; j++) pa[j] = *(const float4*)(p + j * 4);
        int col = n0 + bn4;
#pragma unroll
        for (int it = 0; it < 2; it++) {
            if (col < N) pb[it] = *(const float4*)&Bm[(size_t)(bk + it * 16) * N + col];
            else         pb[it] = make_float4(0.f, 0.f, 0.f, 0.f);
        }
    }

    for (int kt = 0; kt < nt; kt++) {
#pragma unroll
        for (int j = 0; j < 4; j++) {
            float4 v = pa[j];
            __half h0 = __float2half_rn(v.x), h1 = __float2half_rn(v.y);
            __half h2 = __float2half_rn(v.z), h3 = __float2half_rn(v.w);
            __half2 p0 = __halves2half2(h0, h1), p1 = __halves2half2(h2, h3);
            *(uint2*)&AsH[arow * 40 + ak + j * 4] =
                make_uint2(*(uint32_t*)&p0, *(uint32_t*)&p1);
            if (PRECISE) {
                *(uint2*)&AsL[arow * 40 + ak + j * 4] = make_uint2(
                    pack_h2(v.x - __half2float(h0), v.y - __half2float(h1)),
                    pack_h2(v.z - __half2float(h2), v.w - __half2float(h3)));
            }
        }
#pragma unroll
        for (int it = 0; it < 2; it++) {
            int k = bk + it * 16;
            float v[4] = {pb[it].x, pb[it].y, pb[it].z, pb[it].w};
#pragma unroll
            for (int j = 0; j < 4; j++) {
                __half h = __float2half_rn(v[j]);
                BsH[(bn4 + j) * 40 + k] = h;
                if (PRECISE)
                    BsL[(bn4 + j) * 40 + k] = __float2half_rn(v[j] - __half2float(h));
            }
        }
        __syncthreads();

        if (kt + 1 < nt) {
            const float* p = A + (size_t)(m0 + arow) * K + (kt + 1) * 32 + ak;
#pragma unroll
            for (int j = 0; j < 4; j++) pa[j] = *(const float4*)(p + j * 4);
            int col = n0 + bn4;
#pragma unroll
            for (int it = 0; it < 2; it++) {
                if (col < N) pb[it] = *(const float4*)&Bm[(size_t)((kt + 1) * 32 + bk + it * 16) * N + col];
                else         pb[it] = make_float4(0.f, 0.f, 0.f, 0.f);
            }
        }

#pragma unroll
        for (int ks = 0; ks < 2; ks++) {
            const int kb = ks * 16;
            uint32_t aH[2][4], bH[4][2];
            uint32_t aL[2][4], bL[4][2];
#pragma unroll
            for (int mi = 0; mi < 2; mi++) {
                int r = mwb + mi * 16 + g;
                aH[mi][0] = *(const uint32_t*)&AsH[r * 40 + kb + 2 * t];
                aH[mi][1] = *(const uint32_t*)&AsH[(r + 8) * 40 + kb + 2 * t];
                aH[mi][2] = *(const uint32_t*)&AsH[r * 40 + kb + 8 + 2 * t];
                aH[mi][3] = *(const uint32_t*)&AsH[(r + 8) * 40 + kb + 8 + 2 * t];
                if (PRECISE) {
                    aL[mi][0] = *(const uint32_t*)&AsL[r * 40 + kb + 2 * t];
                    aL[mi][1] = *(const uint32_t*)&AsL[(r + 8) * 40 + kb + 2 * t];
                    aL[mi][2] = *(const uint32_t*)&AsL[r * 40 + kb + 8 + 2 * t];
                    aL[mi][3] = *(const uint32_t*)&AsL[(r + 8) * 40 + kb + 8 + 2 * t];
                }
            }
#pragma unroll
            for (int nj = 0; nj < 4; nj++) {
                int n = nwb + nj * 8 + g;
                bH[nj][0] = *(const uint32_t*)&BsH[n * 40 + kb + 2 * t];
                bH[nj][1] = *(const uint32_t*)&BsH[n * 40 + kb + 8 + 2 * t];
                if (PRECISE) {
                    bL[nj][0] = *(const uint32_t*)&BsL[n * 40 + kb + 2 * t];
                    bL[nj][1] = *(const uint32_t*)&BsL[n * 40 + kb + 8 + 2 * t];
                }
            }
#pragma unroll
            for (int mi = 0; mi < 2; mi++)
#pragma unroll
                for (int nj = 0; nj < 4; nj++) {
                    MMA_F16(cacc[mi][nj], aH[mi], bH[nj]);
                    if (PRECISE) {
                        MMA_F16(cacc[mi][nj], aH[mi], bL[nj]);
                        MMA_F16(cacc[mi][nj], aL[mi], bH[nj]);
                    }
                }
        }
        __syncthreads();
    }

#pragma unroll
    for (int mi = 0; mi < 2; mi++) {
#pragma unroll
        for (int nj = 0; nj < 4; nj++) {
            int row = m0 + mwb + mi * 16 + g;
            int col = n0 + nwb + nj * 8 + 2 * t;
            if (col < N) {
                float b0 = bias[col], b1 = bias[col + 1];
                *(float2*)&Cm[(size_t)row * N + col] =
                    make_float2(cacc[mi][nj][0] + b0, cacc[mi][nj][1] + b1);
                *(float2*)&Cm[(size_t)(row + 8) * N + col] =
                    make_float2(cacc[mi][nj][2] + b0, cacc[mi][nj][3] + b1);
            }
        }
    }
}

// ===========================================================================
// Reference-point processing
// ===========================================================================
__global__ void ref_kernel(const float* __restrict__ rp, float* __restrict__ ref)
{
    const int b = blockIdx.x;
    const float* r = rp + (size_t)b * LV * 2;

    __shared__ float redx[256], redy[256];
    float ax = 0.f, ay = 0.f;
    for (int i = threadIdx.x; i < 2304; i += 256) {
        ax += r[2 * i];
        ay += r[2 * i + 1];
    }
    redx[threadIdx.x] = ax; redy[threadIdx.x] = ay;
    __syncthreads();
    for (int s = 128; s > 0; s >>= 1) {
        if (threadIdx.x < s) {
            redx[threadIdx.x] += redx[threadIdx.x + s];
            redy[threadIdx.x] += redy[threadIdx.x + s];
        }
        __syncthreads();
    }
    const float p1x = redx[0] * (1.f / 2304.f);
    const float p1y = redy[0] * (1.f / 2304.f);

    for (int q = threadIdx.x; q < LQ; q += 256) {
        float p2x = r[2 * (2304 + q)];
        float p2y = r[2 * (2304 + q) + 1];

        int rr = q / 24, cc = q % 24;
        float yy = 0.5f * rr - 0.25f;
        float xx = 0.5f * cc - 0.25f;
        int y0 = (int)floorf(yy), x0 = (int)floorf(xx);
        float wy = yy - (float)y0, wx = xx - (float)x0;
        int y0c = max(y0, 0), y1c = min(y0 + 1, 11);
        int x0c = max(x0, 0), x1c = min(x0 + 1, 11);

        const float* p3 = r + 2 * 2880;
        float v00x = p3[2 * (y0c * 12 + x0c)],     v00y = p3[2 * (y0c * 12 + x0c) + 1];
        float v01x = p3[2 * (y0c * 12 + x1c)],     v01y = p3[2 * (y0c * 12 + x1c) + 1];
        float v10x = p3[2 * (y1c * 12 + x0c)],     v10y = p3[2 * (y1c * 12 + x0c) + 1];
        float v11x = p3[2 * (y1c * 12 + x1c)],     v11y = p3[2 * (y1c * 12 + x1c) + 1];
        float p3x = (1.f - wy) * ((1.f - wx) * v00x + wx * v01x) + wy * ((1.f - wx) * v10x + wx * v11x);
        float p3y = (1.f - wy) * ((1.f - wx) * v00y + wx * v01y) + wy * ((1.f - wx) * v10y + wx * v11y);

        ref[((size_t)b * LQ + q) * 2 + 0] = (p1x + p2x + p3x) * (1.f / 3.f);
        ref[((size_t)b * LQ + q) * 2 + 1] = (p1y + p2y + p3y) * (1.f / 3.f);
    }
}

// ===========================================================================
// Deformable sampling: 1 block per (b,q), 192 threads = 6 heads x 32 lanes.
// Outputs fp16 mid directly.
// ===========================================================================
__global__ __launch_bounds__(192)
void sample_kernel(const float* __restrict__ off,
                   const float* __restrict__ logits,
                   const float* __restrict__ refp,
                   const __half* __restrict__ val,
                   __half* __restrict__ mid)
{
    const int bq   = blockIdx.x;
    const int b    = bq / LQ;
    const int h    = threadIdx.x >> 5;
    const int lane = threadIdx.x & 31;

    const float* lg = logits + (size_t)bq * (NHEAD * NLVL * NPTS) + h * (NLVL * NPTS);
    float w[12];
    float mx = -1e30f;
#pragma unroll
    for (int i = 0; i < 12; i++) { w[i] = lg[i]; mx = fmaxf(mx, w[i]); }
    float ssum = 0.f;
#pragma unroll
    for (int i = 0; i < 12; i++) { w[i] = __expf(w[i] - mx); ssum += w[i]; }
    const float inv = 1.f / ssum;

    const float* op = off + (size_t)bq * (NHEAD * NLVL * NPTS * 2) + h * (NLVL * NPTS * 2);
    const float rx = refp[(size_t)bq * 2];
    const float ry = refp[(size_t)bq * 2 + 1];

    const int lvlStart[NLVL] = {0, 2304, 2880};
    const int lvlH[NLVL] = {48, 24, 12};
    const int lvlW[NLVL] = {48, 24, 12};

    float accx = 0.f, accy = 0.f;
#pragma unroll
    for (int lv = 0; lv < NLVL; lv++) {
        const int Hl = lvlH[lv], Wl = lvlW[lv], st = lvlStart[lv];
        const size_t base = ((size_t)b * LV + st) * CDIM + (size_t)h * DHEAD + 2 * lane;
#pragma unroll
        for (int p = 0; p < NPTS; p++) {
            float cx = op[lv * (NPTS * 2) + p * 2 + 0] + rx;
            float cy = op[lv * (NPTS * 2) + p * 2 + 1] + ry;
            float px = cx * (float)Wl - 0.5f;
            float py = cy * (float)Hl - 0.5f;
            float x0f = floorf(px), y0f = floorf(py);
            float lx = px - x0f, ly = py - y0f;
            int x0 = (int)x0f, y0 = (int)y0f;
            int x1 = x0 + 1,   y1 = y0 + 1;

            const float aw = w[lv * NPTS + p] * inv;

            bool vx0 = (x0 >= 0) & (x0 < Wl);
            bool vx1 = (x1 >= 0) & (x1 < Wl);
            bool vy0 = (y0 >= 0) & (y0 < Hl);
            bool vy1 = (y1 >= 0) & (y1 < Hl);

            float2 v00 = {0.f, 0.f}, v10 = {0.f, 0.f}, v01 = {0.f, 0.f}, v11 = {0.f, 0.f};
            if (vy0 & vx0) v00 = __half22float2(*(const __half2*)&val[base + (size_t)(y0 * Wl + x0) * CDIM]);
            if (vy0 & vx1) v10 = __half22float2(*(const __half2*)&val[base + (size_t)(y0 * Wl + x1) * CDIM]);
            if (vy1 & vx0) v01 = __half22float2(*(const __half2*)&val[base + (size_t)(y1 * Wl + x0) * CDIM]);
            if (vy1 & vx1) v11 = __half22float2(*(const __half2*)&val[base + (size_t)(y1 * Wl + x1) * CDIM]);

            float w00 = (1.f - lx) * (1.f - ly), w10 = lx * (1.f - ly);
            float w01 = (1.f - lx) * ly,         w11 = lx * ly;
            accx += aw * (w00 * v00.x + w10 * v10.x + w01 * v01.x + w11 * v11.x);
            accy += aw * (w00 * v00.y + w10 * v10.y + w01 * v01.y + w11 * v11.y);
        }
    }

    *(__half2*)&mid[(size_t)bq * CDIM + h * DHEAD + 2 * lane] = __floats2half2_rn(accx, accy);
}

// ===========================================================================
extern "C" void kernel_launch(void* const* d_in, const int* in_sizes, int n_in,
                              void* d_out, int out_size)
{
    const float* query   = (const float*)d_in[0];
    const float* value   = (const float*)d_in[1];
    const float* rp      = (const float*)d_in[2];
    const float* W_value = (const float*)d_in[3];
    const float* b_value = (const float*)d_in[4];
    const float* W_off   = (const float*)d_in[5];
    const float* b_off   = (const float*)d_in[6];
    const float* W_attn  = (const float*)d_in[7];
    const float* b_attn  = (const float*)d_in[8];
    const float* W_out   = (const float*)d_in[9];
    const float* b_out   = (const float*)d_in[10];
    float* out = (float*)d_out;

    __half *val, *valh, *qh, *midh, *wv, *wo, *wa;
    float *off, *attn, *ref;
    cudaGetSymbolAddress((void**)&val,  g_val);
    cudaGetSymbolAddress((void**)&valh, g_value_h);
    cudaGetSymbolAddress((void**)&qh,   g_query_h);
    cudaGetSymbolAddress((void**)&midh, g_mid_h);
    cudaGetSymbolAddress((void**)&wv,   g_Wv_h);
    cudaGetSymbolAddress((void**)&wo,   g_Wo_h);
    cudaGetSymbolAddress((void**)&wa,   g_Wa_h);
    cudaGetSymbolAddress((void**)&off,  g_off);
    cudaGetSymbolAddress((void**)&attn, g_attn);
    cudaGetSymbolAddress((void**)&ref,  g_ref);

    const int Mval = BATCH * LV;   // 96768
    const int Mq   = BATCH * LQ;   // 18432

    // ---- conversions ----
    conv_f16<<<(Mval * CDIM / 4 + 255) / 256, 256>>>(value, valh, Mval * CDIM / 4);
    conv_f16<<<(Mq * CDIM / 4 + 255) / 256, 256>>>(query, qh, Mq * CDIM / 4);
    conv_w<<<(2 * CDIM * CDIM + CDIM * 128) / 256, 256>>>(W_value, W_out, W_attn, wv, wo, wa);

    // ---- value projection: (96768,384)@(384,384) -> fp16 ----
    gemm_f16_fast<__half><<<dim3(3, Mval / 128), 256>>>(valh, wv, b_value, val, Mval, CDIM, CDIM, CDIM);

    // ---- offsets (precision-critical, 3-pass) ----
    gemm_f16<true><<<dim3(3, Mq / 128), 256>>>(query, W_off, b_off, off, Mq, 144, CDIM);

    // ---- attn logits: (18432,384)@(384,72) via padded-128 weights ----
    gemm_f16_fast<float><<<dim3(1, Mq / 128), 256>>>(qh, wa, b_attn, attn, Mq, 72, CDIM, 128);

    // ---- reference points ----
    ref_kernel<<<BATCH, 256>>>(rp, ref);

    // ---- deformable sampling -> fp16 mid ----
    sample_kernel<<<BATCH * LQ, 192>>>(off, attn, ref, val, midh);

    // ---- output projection: (18432,384)@(384,384) -> fp32 ----
    gemm_f16_fast<float><<<dim3(3, Mq / 128), 256>>>(midh, wo, b_out, out, Mq, CDIM, CDIM, CDIM);
}

// round 9
// speedup vs baseline: 3.2478x; 1.0142x over previous
#include <cuda_runtime.h>
#include <cuda_fp16.h>
#include <math.h>
#include <stdint.h>

// Problem constants
#define BATCH 32
#define LQ    576
#define LV    3024
#define CDIM  384
#define NHEAD 6
#define DHEAD 64
#define NLVL  3
#define NPTS  4

// Scratch (device globals; no dynamic allocation allowed)
__device__ __half g_val    [BATCH * LV * CDIM];    // value projection (fp16)
__device__ __half g_value_h[BATCH * LV * CDIM];    // fp16 copy of input value
__device__ __half g_q3     [BATCH * LQ * 1152];    // [qh | qh | ql] stacked K image
__device__ __half g_mid_h  [BATCH * LQ * CDIM];    // sampled output (fp16)
__device__ __half g_Wv_h[CDIM * CDIM];             // fp16 weights
__device__ __half g_Wo_h[CDIM * CDIM];
__device__ __half g_Wa_h[CDIM * 128];              // W_attn padded 72 -> 128
__device__ __half g_W3  [1152 * 256];              // [Wh; Wl; Wh] for offsets, N pad 144->256
__device__ float  g_off [BATCH * LQ * (NHEAD*NLVL*NPTS*2)];
__device__ float  g_attn[BATCH * LQ * (NHEAD*NLVL*NPTS)];
__device__ float  g_ref [BATCH * LQ * 2];

// ===========================================================================
// helpers
// ===========================================================================
__device__ __forceinline__ uint32_t smem_u32(const void* p) {
    uint32_t a;
    asm("{ .reg .u64 t; cvta.to.shared.u64 t, %1; cvt.u32.u64 %0, t; }" : "=r"(a) : "l"(p));
    return a;
}
__device__ __forceinline__ void cp_async16(uint32_t dst, const void* src) {
    asm volatile("cp.async.cg.shared.global [%0], [%1], 16;" :: "r"(dst), "l"(src));
}
__device__ __forceinline__ void cp_commit() {
    asm volatile("cp.async.commit_group;");
}
__device__ __forceinline__ void ldsm4(uint32_t* r, uint32_t a) {
    asm volatile("ldmatrix.sync.aligned.m8n8.x4.shared.b16 {%0,%1,%2,%3}, [%4];"
        : "=r"(r[0]), "=r"(r[1]), "=r"(r[2]), "=r"(r[3]) : "r"(a));
}
__device__ __forceinline__ void ldsm4t(uint32_t* r, uint32_t a) {
    asm volatile("ldmatrix.sync.aligned.m8n8.x4.trans.shared.b16 {%0,%1,%2,%3}, [%4];"
        : "=r"(r[0]), "=r"(r[1]), "=r"(r[2]), "=r"(r[3]) : "r"(a));
}
#define MMA_F16(Cc, Af, Bf) \
  asm volatile("mma.sync.aligned.m16n8k16.row.col.f32.f16.f16.f32 " \
    "{%0,%1,%2,%3}, {%4,%5,%6,%7}, {%8,%9}, {%0,%1,%2,%3};" \
    : "+f"(Cc[0]), "+f"(Cc[1]), "+f"(Cc[2]), "+f"(Cc[3]) \
    : "r"(Af[0]), "r"(Af[1]), "r"(Af[2]), "r"(Af[3]), "r"(Bf[0]), "r"(Bf[1]))

__device__ __forceinline__ uint32_t pack_h2(float a, float b) {
    __half2 t = __floats2half2_rn(a, b);
    return *(uint32_t*)&t;
}

// ===========================================================================
// Conversion prep kernels
// ===========================================================================
__global__ void conv_f16(const float* __restrict__ in, __half* __restrict__ outp, int n4)
{
    int i = blockIdx.x * 256 + threadIdx.x;
    if (i < n4) {
        float4 v = ((const float4*)in)[i];
        ((uint2*)outp)[i] = make_uint2(pack_h2(v.x, v.y), pack_h2(v.z, v.w));
    }
}

// query -> [qh | qh | ql] per row (K stacked 1152)
__global__ void conv_q3(const float* __restrict__ q, __half* __restrict__ q3, int n)
{
    int i = blockIdx.x * 256 + threadIdx.x;
    if (i < n) {
        int row = i / CDIM, c = i % CDIM;
        float v = q[i];
        __half h = __float2half_rn(v);
        __half l = __float2half_rn(v - __half2float(h));
        __half* r = q3 + (size_t)row * 1152;
        r[c] = h; r[384 + c] = h; r[768 + c] = l;
    }
}

__global__ void conv_w(const float* __restrict__ Wv, const float* __restrict__ Wo,
                       const float* __restrict__ Wa,
                       __half* __restrict__ wv, __half* __restrict__ wo, __half* __restrict__ wa)
{
    int i = blockIdx.x * 256 + threadIdx.x;   // 0 .. 344063
    if (i < CDIM * CDIM) {
        wv[i] = __float2half_rn(Wv[i]);
    } else if (i < 2 * CDIM * CDIM) {
        int j = i - CDIM * CDIM;
        wo[j] = __float2half_rn(Wo[j]);
    } else {
        int j = i - 2 * CDIM * CDIM;          // 0 .. 49151
        int r = j >> 7, c = j & 127;
        wa[j] = (c < 72) ? __float2half_rn(Wa[r * 72 + c]) : __half(0.f);
    }
}

// W_off[384x144] -> W3[1152x256] = [Wh; Wl; Wh], cols padded with 0
__global__ void conv_woff(const float* __restrict__ Wf, __half* __restrict__ w3)
{
    int i = blockIdx.x * 256 + threadIdx.x;   // 0 .. 384*256-1
    if (i < 384 * 256) {
        int k = i >> 8, c = i & 255;
        float v = (c < 144) ? Wf[k * 144 + c] : 0.f;
        __half h = __float2half_rn(v);
        __half l = __float2half_rn(v - __half2float(h));
        w3[(size_t)k * 256 + c] = h;
        w3[(size_t)(384 + k) * 256 + c] = l;
        w3[(size_t)(768 + k) * 256 + c] = h;
    }
}

// ===========================================================================
// Fast fp16 GEMM: C[M,N] = A[M,K](row stride lda) @ B[K,Bw](cols n0..n0+127) + bias
// 128x128 block tile, 256 threads (8 warps: 4m x 2n, warp tile 32x64), KT=32.
// 3-stage cp.async pipeline; ldmatrix fragment loads. Dynamic smem 56832B.
// A smem: [row][40 halves] (80B stride, conflict-free LDSM).
// B smem: [k][136 halves]  (272B stride, conflict-free LDSM.trans).
// ===========================================================================
#define ASTB 10240   // bytes per A stage
#define BSTB 8704    // bytes per B stage
#define SMEM_TOTAL (3 * (ASTB + BSTB))   // 56832

template<typename OutT>
__global__ __launch_bounds__(256, 2)
void gemm_f16_fast(const __half* __restrict__ A, const __half* __restrict__ B,
                   const float* __restrict__ bias, OutT* __restrict__ C,
                   int M, int N, int K, int lda, int Bw)
{
    extern __shared__ __align__(16) char dsm[];
    const uint32_t sA = smem_u32(dsm);
    const uint32_t sB = sA + 3 * ASTB;

    const int tid  = threadIdx.x;
    const int m0   = blockIdx.y * 128;
    const int n0   = blockIdx.x * 128;
    const int warp = tid >> 5, lane = tid & 31;
    const int g = lane >> 2, t = lane & 3;
    const int mwb = (warp >> 1) * 32;
    const int nwb = (warp & 1) * 64;

    // cp.async mappings
    const int arow = tid >> 2;            // 0..63 (and +64)
    const int ac   = tid & 3;             // 16B chunk within row
    const int brow = tid >> 4;            // 0..15 (and +16)
    const int bc   = tid & 15;            // 16B chunk = 8 n
    const __half* agp = A + (size_t)(m0 + arow) * lda + ac * 8;
    const __half* bgp = B + (size_t)brow * Bw + n0 + bc * 8;
    const uint32_t adp = sA + arow * 80 + ac * 16;
    const uint32_t bdp = sB + brow * 272 + bc * 16;

    // ldmatrix per-lane offsets
    const uint32_t aOff = ((lane & 15) * 40 + (lane >> 4) * 8) * 2 + mwb * 80;
    const uint32_t bOff = ((lane & 15) * 136 + (lane >> 4) * 8) * 2 + nwb * 2;

    float cacc[2][8][4];
#pragma unroll
    for (int i = 0; i < 2; i++)
#pragma unroll
        for (int j = 0; j < 8; j++)
#pragma unroll
            for (int k = 0; k < 4; k++) cacc[i][j][k] = 0.f;

    const int nt = K / 32;

    auto load_stage = [&](int kt, int s) {
        const __half* ag = agp + kt * 32;
        uint32_t ad = adp + s * ASTB;
        cp_async16(ad, ag);
        cp_async16(ad + 64 * 80, ag + (size_t)64 * lda);
        const __half* bg = bgp + (size_t)(kt * 32) * Bw;
        uint32_t bd = bdp + s * BSTB;
        cp_async16(bd, bg);
        cp_async16(bd + 16 * 272, bg + (size_t)16 * Bw);
    };

    load_stage(0, 0); cp_commit();
    load_stage(1, 1); cp_commit();

    for (int kt = 0; kt < nt; kt++) {
        if (kt < nt - 1) { asm volatile("cp.async.wait_group 1;"); }
        else             { asm volatile("cp.async.wait_group 0;"); }
        __syncthreads();

        // prefetch stage kt+2 (buffer (kt+2)%3 was consumed in iter kt-1)
        if (kt + 2 < nt) {
            int s2 = (kt + 2) % 3;
            load_stage(kt + 2, s2);
            cp_commit();
        }

        const int s = kt % 3;
        const uint32_t aBase = sA + s * ASTB + aOff;
        const uint32_t bBase = sB + s * BSTB + bOff;
#pragma unroll
        for (int ks = 0; ks < 2; ks++) {
            uint32_t aH[2][4], bF[4][4];
            ldsm4(aH[0], aBase + ks * 32);
            ldsm4(aH[1], aBase + 16 * 80 + ks * 32);
#pragma unroll
            for (int p = 0; p < 4; p++)
                ldsm4t(bF[p], bBase + ks * 16 * 272 + p * 32);
#pragma unroll
            for (int mi = 0; mi < 2; mi++)
#pragma unroll
                for (int nj = 0; nj < 8; nj++) {
                    uint32_t bfr[2] = { bF[nj >> 1][(nj & 1) * 2], bF[nj >> 1][(nj & 1) * 2 + 1] };
                    MMA_F16(cacc[mi][nj], aH[mi], bfr);
                }
        }
    }
    __syncthreads();

    // epilogue
#pragma unroll
    for (int mi = 0; mi < 2; mi++) {
#pragma unroll
        for (int nj = 0; nj < 8; nj++) {
            int row = m0 + mwb + mi * 16 + g;
            int col = n0 + nwb + nj * 8 + 2 * t;
            if (col < N) {
                float b0 = bias[col], b1 = bias[col + 1];
                float v00 = cacc[mi][nj][0] + b0, v01 = cacc[mi][nj][1] + b1;
                float v10 = cacc[mi][nj][2] + b0, v11 = cacc[mi][nj][3] + b1;
                if (sizeof(OutT) == 4) {
                    *(float2*)((float*)C + (size_t)row * N + col) = make_float2(v00, v01);
                    *(float2*)((float*)C + (size_t)(row + 8) * N + col) = make_float2(v10, v11);
                } else {
                    *(__half2*)((__half*)C + (size_t)row * N + col) = __floats2half2_rn(v00, v01);
                    *(__half2*)((__half*)C + (size_t)(row + 8) * N + col) = __floats2half2_rn(v10, v11);
                }
            }
        }
    }
}

// ===========================================================================
// Reference-point processing
// ===========================================================================
__global__ void ref_kernel(const float* __restrict__ rp, float* __restrict__ ref)
{
    const int b = blockIdx.x;
    const float* r = rp + (size_t)b * LV * 2;

    __shared__ float redx[256], redy[256];
    float ax = 0.f, ay = 0.f;
    for (int i = threadIdx.x; i < 2304; i += 256) {
        ax += r[2 * i];
        ay += r[2 * i + 1];
    }
    redx[threadIdx.x] = ax; redy[threadIdx.x] = ay;
    __syncthreads();
    for (int s = 128; s > 0; s >>= 1) {
        if (threadIdx.x < s) {
            redx[threadIdx.x] += redx[threadIdx.x + s];
            redy[threadIdx.x] += redy[threadIdx.x + s];
        }
        __syncthreads();
    }
    const float p1x = redx[0] * (1.f / 2304.f);
    const float p1y = redy[0] * (1.f / 2304.f);

    for (int q = threadIdx.x; q < LQ; q += 256) {
        float p2x = r[2 * (2304 + q)];
        float p2y = r[2 * (2304 + q) + 1];

        int rr = q / 24, cc = q % 24;
        float yy = 0.5f * rr - 0.25f;
        float xx = 0.5f * cc - 0.25f;
        int y0 = (int)floorf(yy), x0 = (int)floorf(xx);
        float wy = yy - (float)y0, wx = xx - (float)x0;
        int y0c = max(y0, 0), y1c = min(y0 + 1, 11);
        int x0c = max(x0, 0), x1c = min(x0 + 1, 11);

        const float* p3 = r + 2 * 2880;
        float v00x = p3[2 * (y0c * 12 + x0c)],     v00y = p3[2 * (y0c * 12 + x0c) + 1];
        float v01x = p3[2 * (y0c * 12 + x1c)],     v01y = p3[2 * (y0c * 12 + x1c) + 1];
        float v10x = p3[2 * (y1c * 12 + x0c)],     v10y = p3[2 * (y1c * 12 + x0c) + 1];
        float v11x = p3[2 * (y1c * 12 + x1c)],     v11y = p3[2 * (y1c * 12 + x1c) + 1];
        float p3x = (1.f - wy) * ((1.f - wx) * v00x + wx * v01x) + wy * ((1.f - wx) * v10x + wx * v11x);
        float p3y = (1.f - wy) * ((1.f - wx) * v00y + wx * v01y) + wy * ((1.f - wx) * v10y + wx * v11y);

        ref[((size_t)b * LQ + q) * 2 + 0] = (p1x + p2x + p3x) * (1.f / 3.f);
        ref[((size_t)b * LQ + q) * 2 + 1] = (p1y + p2y + p3y) * (1.f / 3.f);
    }
}

// ===========================================================================
// Deformable sampling: 1 block per (b,q), 192 threads = 6 heads x 32 lanes.
// ===========================================================================
__global__ __launch_bounds__(192)
void sample_kernel(const float* __restrict__ off,
                   const float* __restrict__ logits,
                   const float* __restrict__ refp,
                   const __half* __restrict__ val,
                   __half* __restrict__ mid)
{
    const int bq   = blockIdx.x;
    const int b    = bq / LQ;
    const int h    = threadIdx.x >> 5;
    const int lane = threadIdx.x & 31;

    const float* lg = logits + (size_t)bq * (NHEAD * NLVL * NPTS) + h * (NLVL * NPTS);
    float w[12];
    float mx = -1e30f;
#pragma unroll
    for (int i = 0; i < 12; i++) { w[i] = lg[i]; mx = fmaxf(mx, w[i]); }
    float ssum = 0.f;
#pragma unroll
    for (int i = 0; i < 12; i++) { w[i] = __expf(w[i] - mx); ssum += w[i]; }
    const float inv = 1.f / ssum;

    const float* op = off + (size_t)bq * (NHEAD * NLVL * NPTS * 2) + h * (NLVL * NPTS * 2);
    const float rx = refp[(size_t)bq * 2];
    const float ry = refp[(size_t)bq * 2 + 1];

    const int lvlStart[NLVL] = {0, 2304, 2880};
    const int lvlH[NLVL] = {48, 24, 12};
    const int lvlW[NLVL] = {48, 24, 12};

    float accx = 0.f, accy = 0.f;
#pragma unroll
    for (int lv = 0; lv < NLVL; lv++) {
        const int Hl = lvlH[lv], Wl = lvlW[lv], st = lvlStart[lv];
        const size_t base = ((size_t)b * LV + st) * CDIM + (size_t)h * DHEAD + 2 * lane;
#pragma unroll
        for (int p = 0; p < NPTS; p++) {
            float cx = op[lv * (NPTS * 2) + p * 2 + 0] + rx;
            float cy = op[lv * (NPTS * 2) + p * 2 + 1] + ry;
            float px = cx * (float)Wl - 0.5f;
            float py = cy * (float)Hl - 0.5f;
            float x0f = floorf(px), y0f = floorf(py);
            float lx = px - x0f, ly = py - y0f;
            int x0 = (int)x0f, y0 = (int)y0f;
            int x1 = x0 + 1,   y1 = y0 + 1;

            const float aw = w[lv * NPTS + p] * inv;

            bool vx0 = (x0 >= 0) & (x0 < Wl);
            bool vx1 = (x1 >= 0) & (x1 < Wl);
            bool vy0 = (y0 >= 0) & (y0 < Hl);
            bool vy1 = (y1 >= 0) & (y1 < Hl);

            float2 v00 = {0.f, 0.f}, v10 = {0.f, 0.f}, v01 = {0.f, 0.f}, v11 = {0.f, 0.f};
            if (vy0 & vx0) v00 = __half22float2(*(const __half2*)&val[base + (size_t)(y0 * Wl + x0) * CDIM]);
            if (vy0 & vx1) v10 = __half22float2(*(const __half2*)&val[base + (size_t)(y0 * Wl + x1) * CDIM]);
            if (vy1 & vx0) v01 = __half22float2(*(const __half2*)&val[base + (size_t)(y1 * Wl + x0) * CDIM]);
            if (vy1 & vx1) v11 = __half22float2(*(const __half2*)&val[base + (size_t)(y1 * Wl + x1) * CDIM]);

            float w00 = (1.f - lx) * (1.f - ly), w10 = lx * (1.f - ly);
            float w01 = (1.f - lx) * ly,         w11 = lx * ly;
            accx += aw * (w00 * v00.x + w10 * v10.x + w01 * v01.x + w11 * v11.x);
            accy += aw * (w00 * v00.y + w10 * v10.y + w01 * v01.y + w11 * v11.y);
        }
    }

    *(__half2*)&mid[(size_t)bq * CDIM + h * DHEAD + 2 * lane] = __floats2half2_rn(accx, accy);
}

// ===========================================================================
extern "C" void kernel_launch(void* const* d_in, const int* in_sizes, int n_in,
                              void* d_out, int out_size)
{
    const float* query   = (const float*)d_in[0];
    const float* value   = (const float*)d_in[1];
    const float* rp      = (const float*)d_in[2];
    const float* W_value = (const float*)d_in[3];
    const float* b_value = (const float*)d_in[4];
    const float* W_off   = (const float*)d_in[5];
    const float* b_off   = (const float*)d_in[6];
    const float* W_attn  = (const float*)d_in[7];
    const float* b_attn  = (const float*)d_in[8];
    const float* W_out   = (const float*)d_in[9];
    const float* b_out   = (const float*)d_in[10];
    float* out = (float*)d_out;

    __half *val, *valh, *q3, *midh, *wv, *wo, *wa, *w3;
    float *off, *attn, *ref;
    cudaGetSymbolAddress((void**)&val,  g_val);
    cudaGetSymbolAddress((void**)&valh, g_value_h);
    cudaGetSymbolAddress((void**)&q3,   g_q3);
    cudaGetSymbolAddress((void**)&midh, g_mid_h);
    cudaGetSymbolAddress((void**)&wv,   g_Wv_h);
    cudaGetSymbolAddress((void**)&wo,   g_Wo_h);
    cudaGetSymbolAddress((void**)&wa,   g_Wa_h);
    cudaGetSymbolAddress((void**)&w3,   g_W3);
    cudaGetSymbolAddress((void**)&off,  g_off);
    cudaGetSymbolAddress((void**)&attn, g_attn);
    cudaGetSymbolAddress((void**)&ref,  g_ref);

    const int Mval = BATCH * LV;   // 96768
    const int Mq   = BATCH * LQ;   // 18432

    cudaFuncSetAttribute(gemm_f16_fast<__half>, cudaFuncAttributeMaxDynamicSharedMemorySize, SMEM_TOTAL);
    cudaFuncSetAttribute(gemm_f16_fast<float>,  cudaFuncAttributeMaxDynamicSharedMemorySize, SMEM_TOTAL);

    // ---- conversions ----
    conv_f16<<<(Mval * CDIM / 4 + 255) / 256, 256>>>(value, valh, Mval * CDIM / 4);
    conv_q3<<<(Mq * CDIM + 255) / 256, 256>>>(query, q3, Mq * CDIM);
    conv_w<<<(2 * CDIM * CDIM + CDIM * 128) / 256, 256>>>(W_value, W_out, W_attn, wv, wo, wa);
    conv_woff<<<(384 * 256) / 256, 256>>>(W_off, w3);

    // ---- value projection: (96768,384)@(384,384) -> fp16 ----
    gemm_f16_fast<__half><<<dim3(3, Mval / 128), 256, SMEM_TOTAL>>>(
        valh, wv, b_value, val, Mval, CDIM, CDIM, CDIM, CDIM);

    // ---- offsets (compensated via K-stacking): (18432,1152)@(1152,256->144) ----
    gemm_f16_fast<float><<<dim3(2, Mq / 128), 256, SMEM_TOTAL>>>(
        q3, w3, b_off, off, Mq, 144, 1152, 1152, 256);

    // ---- attn logits: hi half of q3, (18432,384)@(384,72) ----
    gemm_f16_fast<float><<<dim3(1, Mq / 128), 256, SMEM_TOTAL>>>(
        q3, wa, b_attn, attn, Mq, 72, CDIM, 1152, 128);

    // ---- reference points ----
    ref_kernel<<<BATCH, 256>>>(rp, ref);

    // ---- deformable sampling -> fp16 mid ----
    sample_kernel<<<BATCH * LQ, 192>>>(off, attn, ref, val, midh);

    // ---- output projection: (18432,384)@(384,384) -> fp32 ----
    gemm_f16_fast<float><<<dim3(3, Mq / 128), 256, SMEM_TOTAL>>>(
        midh, wo, b_out, out, Mq, CDIM, CDIM, CDIM, CDIM);
}

// round 10
// speedup vs baseline: 3.3069x; 1.0182x over previous
#include <cuda_runtime.h>
#include <cuda_fp16.h>
#include <math.h>
#include <stdint.h>

// Problem constants
#define BATCH 32
#define LQ    576
#define LV    3024
#define CDIM  384
#define NHEAD 6
#define DHEAD 64
#define NLVL  3
#define NPTS  4

// Scratch (device globals; no dynamic allocation allowed)
__device__ __half g_val    [BATCH * LV * CDIM];    // value projection (fp16)
__device__ __half g_value_h[BATCH * LV * CDIM];    // fp16 copy of input value
__device__ __half g_q3     [BATCH * LQ * 1152];    // [qh | qh | ql] stacked K image
__device__ __half g_mid_h  [BATCH * LQ * CDIM];    // sampled output (fp16)
__device__ __half g_Wv_h[CDIM * CDIM];             // fp16 weights
__device__ __half g_Wo_h[CDIM * CDIM];
__device__ __half g_Wa_h[CDIM * 128];              // W_attn padded 72 -> 128
__device__ __half g_W3  [1152 * 256];              // [Wh; Wl; Wh] for offsets, N pad 144->256
__device__ float  g_off [BATCH * LQ * (NHEAD*NLVL*NPTS*2)];
__device__ float  g_attn[BATCH * LQ * (NHEAD*NLVL*NPTS)];
__device__ float  g_ref [BATCH * LQ * 2];

// ===========================================================================
// helpers
// ===========================================================================
__device__ __forceinline__ uint32_t smem_u32(const void* p) {
    uint32_t a;
    asm("{ .reg .u64 t; cvta.to.shared.u64 t, %1; cvt.u32.u64 %0, t; }" : "=r"(a) : "l"(p));
    return a;
}
__device__ __forceinline__ void cp_async16(uint32_t dst, const void* src) {
    asm volatile("cp.async.cg.shared.global [%0], [%1], 16;" :: "r"(dst), "l"(src));
}
__device__ __forceinline__ void cp_commit() {
    asm volatile("cp.async.commit_group;");
}
__device__ __forceinline__ void ldsm4(uint32_t* r, uint32_t a) {
    asm volatile("ldmatrix.sync.aligned.m8n8.x4.shared.b16 {%0,%1,%2,%3}, [%4];"
        : "=r"(r[0]), "=r"(r[1]), "=r"(r[2]), "=r"(r[3]) : "r"(a));
}
__device__ __forceinline__ void ldsm4t(uint32_t* r, uint32_t a) {
    asm volatile("ldmatrix.sync.aligned.m8n8.x4.trans.shared.b16 {%0,%1,%2,%3}, [%4];"
        : "=r"(r[0]), "=r"(r[1]), "=r"(r[2]), "=r"(r[3]) : "r"(a));
}
#define MMA_F16(Cc, Af, Bf) \
  asm volatile("mma.sync.aligned.m16n8k16.row.col.f32.f16.f16.f32 " \
    "{%0,%1,%2,%3}, {%4,%5,%6,%7}, {%8,%9}, {%0,%1,%2,%3};" \
    : "+f"(Cc[0]), "+f"(Cc[1]), "+f"(Cc[2]), "+f"(Cc[3]) \
    : "r"(Af[0]), "r"(Af[1]), "r"(Af[2]), "r"(Af[3]), "r"(Bf[0]), "r"(Bf[1]))

__device__ __forceinline__ uint32_t pack_h2(float a, float b) {
    __half2 t = __floats2half2_rn(a, b);
    return *(uint32_t*)&t;
}

// ===========================================================================
// Conversion prep kernels
// ===========================================================================
// value -> fp16, Wv -> fp16, Wo -> fp16 (main-stream dependencies)
__global__ void conv_main(const float* __restrict__ value, __half* __restrict__ valh,
                          const float* __restrict__ Wv, __half* __restrict__ wv,
                          const float* __restrict__ Wo, __half* __restrict__ wo,
                          int n4val)
{
    int i = blockIdx.x * 256 + threadIdx.x;
    if (i < n4val) {
        float4 v = ((const float4*)value)[i];
        ((uint2*)valh)[i] = make_uint2(pack_h2(v.x, v.y), pack_h2(v.z, v.w));
    } else {
        int j = i - n4val;                    // 0 .. 2*36864-1  (CDIM*CDIM/4 each)
        const int nw4 = CDIM * CDIM / 4;
        if (j < nw4) {
            float4 v = ((const float4*)Wv)[j];
            ((uint2*)wv)[j] = make_uint2(pack_h2(v.x, v.y), pack_h2(v.z, v.w));
        } else if (j < 2 * nw4) {
            j -= nw4;
            float4 v = ((const float4*)Wo)[j];
            ((uint2*)wo)[j] = make_uint2(pack_h2(v.x, v.y), pack_h2(v.z, v.w));
        }
    }
}

// query -> [qh | qh | ql] per row (K stacked 1152)
__global__ void conv_q3(const float* __restrict__ q, __half* __restrict__ q3, int n)
{
    int i = blockIdx.x * 256 + threadIdx.x;
    if (i < n) {
        int row = i / CDIM, c = i % CDIM;
        float v = q[i];
        __half h = __float2half_rn(v);
        __half l = __float2half_rn(v - __half2float(h));
        __half* r = q3 + (size_t)row * 1152;
        r[c] = h; r[384 + c] = h; r[768 + c] = l;
    }
}

// W_off -> W3 stacked image; W_attn -> padded fp16
__global__ void conv_wside(const float* __restrict__ Wf, __half* __restrict__ w3,
                           const float* __restrict__ Wa, __half* __restrict__ wa)
{
    int i = blockIdx.x * 256 + threadIdx.x;
    if (i < 384 * 256) {
        int k = i >> 8, c = i & 255;
        float v = (c < 144) ? Wf[k * 144 + c] : 0.f;
        __half h = __float2half_rn(v);
        __half l = __float2half_rn(v - __half2float(h));
        w3[(size_t)k * 256 + c] = h;
        w3[(size_t)(384 + k) * 256 + c] = l;
        w3[(size_t)(768 + k) * 256 + c] = h;
    } else {
        int j = i - 384 * 256;                // 0 .. 49151
        if (j < CDIM * 128) {
            int r = j >> 7, c = j & 127;
            wa[j] = (c < 72) ? __float2half_rn(Wa[r * 72 + c]) : __half(0.f);
        }
    }
}

// ===========================================================================
// Fast fp16 GEMM: C[M,N] = A[M,K](row stride lda) @ B[K,Bw](cols n0..n0+127) + bias
// 128x128 block tile, 256 threads (8 warps: 4m x 2n, warp tile 32x64), KT=32.
// 3-stage cp.async pipeline; ldmatrix fragment loads. Dynamic smem 56832B.
// ===========================================================================
#define ASTB 10240   // bytes per A stage
#define BSTB 8704    // bytes per B stage
#define SMEM_TOTAL (3 * (ASTB + BSTB))   // 56832

template<typename OutT>
__global__ __launch_bounds__(256, 2)
void gemm_f16_fast(const __half* __restrict__ A, const __half* __restrict__ B,
                   const float* __restrict__ bias, OutT* __restrict__ C,
                   int M, int N, int K, int lda, int Bw)
{
    extern __shared__ __align__(16) char dsm[];
    const uint32_t sA = smem_u32(dsm);
    const uint32_t sB = sA + 3 * ASTB;

    const int tid  = threadIdx.x;
    const int m0   = blockIdx.y * 128;
    const int n0   = blockIdx.x * 128;
    const int warp = tid >> 5, lane = tid & 31;
    const int g = lane >> 2, t = lane & 3;
    const int mwb = (warp >> 1) * 32;
    const int nwb = (warp & 1) * 64;

    const int arow = tid >> 2;
    const int ac   = tid & 3;
    const int brow = tid >> 4;
    const int bc   = tid & 15;
    const __half* agp = A + (size_t)(m0 + arow) * lda + ac * 8;
    const __half* bgp = B + (size_t)brow * Bw + n0 + bc * 8;
    const uint32_t adp = sA + arow * 80 + ac * 16;
    const uint32_t bdp = sB + brow * 272 + bc * 16;

    const uint32_t aOff = ((lane & 15) * 40 + (lane >> 4) * 8) * 2 + mwb * 80;
    const uint32_t bOff = ((lane & 15) * 136 + (lane >> 4) * 8) * 2 + nwb * 2;

    float cacc[2][8][4];
#pragma unroll
    for (int i = 0; i < 2; i++)
#pragma unroll
        for (int j = 0; j < 8; j++)
#pragma unroll
            for (int k = 0; k < 4; k++) cacc[i][j][k] = 0.f;

    const int nt = K / 32;

    auto load_stage = [&](int kt, int s) {
        const __half* ag = agp + kt * 32;
        uint32_t ad = adp + s * ASTB;
        cp_async16(ad, ag);
        cp_async16(ad + 64 * 80, ag + (size_t)64 * lda);
        const __half* bg = bgp + (size_t)(kt * 32) * Bw;
        uint32_t bd = bdp + s * BSTB;
        cp_async16(bd, bg);
        cp_async16(bd + 16 * 272, bg + (size_t)16 * Bw);
    };

    load_stage(0, 0); cp_commit();
    load_stage(1, 1); cp_commit();

    for (int kt = 0; kt < nt; kt++) {
        if (kt < nt - 1) { asm volatile("cp.async.wait_group 1;"); }
        else             { asm volatile("cp.async.wait_group 0;"); }
        __syncthreads();

        if (kt + 2 < nt) {
            load_stage(kt + 2, (kt + 2) % 3);
            cp_commit();
        }

        const int s = kt % 3;
        const uint32_t aBase = sA + s * ASTB + aOff;
        const uint32_t bBase = sB + s * BSTB + bOff;
#pragma unroll
        for (int ks = 0; ks < 2; ks++) {
            uint32_t aH[2][4], bF[4][4];
            ldsm4(aH[0], aBase + ks * 32);
            ldsm4(aH[1], aBase + 16 * 80 + ks * 32);
#pragma unroll
            for (int p = 0; p < 4; p++)
                ldsm4t(bF[p], bBase + ks * 16 * 272 + p * 32);
#pragma unroll
            for (int mi = 0; mi < 2; mi++)
#pragma unroll
                for (int nj = 0; nj < 8; nj++) {
                    uint32_t bfr[2] = { bF[nj >> 1][(nj & 1) * 2], bF[nj >> 1][(nj & 1) * 2 + 1] };
                    MMA_F16(cacc[mi][nj], aH[mi], bfr);
                }
        }
    }
    __syncthreads();

#pragma unroll
    for (int mi = 0; mi < 2; mi++) {
#pragma unroll
        for (int nj = 0; nj < 8; nj++) {
            int row = m0 + mwb + mi * 16 + g;
            int col = n0 + nwb + nj * 8 + 2 * t;
            if (col < N) {
                float b0 = bias[col], b1 = bias[col + 1];
                float v00 = cacc[mi][nj][0] + b0, v01 = cacc[mi][nj][1] + b1;
                float v10 = cacc[mi][nj][2] + b0, v11 = cacc[mi][nj][3] + b1;
                if (sizeof(OutT) == 4) {
                    *(float2*)((float*)C + (size_t)row * N + col) = make_float2(v00, v01);
                    *(float2*)((float*)C + (size_t)(row + 8) * N + col) = make_float2(v10, v11);
                } else {
                    *(__half2*)((__half*)C + (size_t)row * N + col) = __floats2half2_rn(v00, v01);
                    *(__half2*)((__half*)C + (size_t)(row + 8) * N + col) = __floats2half2_rn(v10, v11);
                }
            }
        }
    }
}

// ===========================================================================
// Reference-point processing
// ===========================================================================
__global__ void ref_kernel(const float* __restrict__ rp, float* __restrict__ ref)
{
    const int b = blockIdx.x;
    const float* r = rp + (size_t)b * LV * 2;

    __shared__ float redx[256], redy[256];
    float ax = 0.f, ay = 0.f;
    for (int i = threadIdx.x; i < 2304; i += 256) {
        ax += r[2 * i];
        ay += r[2 * i + 1];
    }
    redx[threadIdx.x] = ax; redy[threadIdx.x] = ay;
    __syncthreads();
    for (int s = 128; s > 0; s >>= 1) {
        if (threadIdx.x < s) {
            redx[threadIdx.x] += redx[threadIdx.x + s];
            redy[threadIdx.x] += redy[threadIdx.x + s];
        }
        __syncthreads();
    }
    const float p1x = redx[0] * (1.f / 2304.f);
    const float p1y = redy[0] * (1.f / 2304.f);

    for (int q = threadIdx.x; q < LQ; q += 256) {
        float p2x = r[2 * (2304 + q)];
        float p2y = r[2 * (2304 + q) + 1];

        int rr = q / 24, cc = q % 24;
        float yy = 0.5f * rr - 0.25f;
        float xx = 0.5f * cc - 0.25f;
        int y0 = (int)floorf(yy), x0 = (int)floorf(xx);
        float wy = yy - (float)y0, wx = xx - (float)x0;
        int y0c = max(y0, 0), y1c = min(y0 + 1, 11);
        int x0c = max(x0, 0), x1c = min(x0 + 1, 11);

        const float* p3 = r + 2 * 2880;
        float v00x = p3[2 * (y0c * 12 + x0c)],     v00y = p3[2 * (y0c * 12 + x0c) + 1];
        float v01x = p3[2 * (y0c * 12 + x1c)],     v01y = p3[2 * (y0c * 12 + x1c) + 1];
        float v10x = p3[2 * (y1c * 12 + x0c)],     v10y = p3[2 * (y1c * 12 + x0c) + 1];
        float v11x = p3[2 * (y1c * 12 + x1c)],     v11y = p3[2 * (y1c * 12 + x1c) + 1];
        float p3x = (1.f - wy) * ((1.f - wx) * v00x + wx * v01x) + wy * ((1.f - wx) * v10x + wx * v11x);
        float p3y = (1.f - wy) * ((1.f - wx) * v00y + wx * v01y) + wy * ((1.f - wx) * v10y + wx * v11y);

        ref[((size_t)b * LQ + q) * 2 + 0] = (p1x + p2x + p3x) * (1.f / 3.f);
        ref[((size_t)b * LQ + q) * 2 + 1] = (p1y + p2y + p3y) * (1.f / 3.f);
    }
}

// ===========================================================================
// Deformable sampling: 1 block per (b,q), 192 threads = 6 heads x 32 lanes.
// ===========================================================================
__global__ __launch_bounds__(192)
void sample_kernel(const float* __restrict__ off,
                   const float* __restrict__ logits,
                   const float* __restrict__ refp,
                   const __half* __restrict__ val,
                   __half* __restrict__ mid)
{
    const int bq   = blockIdx.x;
    const int b    = bq / LQ;
    const int h    = threadIdx.x >> 5;
    const int lane = threadIdx.x & 31;

    const float* lg = logits + (size_t)bq * (NHEAD * NLVL * NPTS) + h * (NLVL * NPTS);
    float w[12];
    float mx = -1e30f;
#pragma unroll
    for (int i = 0; i < 12; i++) { w[i] = lg[i]; mx = fmaxf(mx, w[i]); }
    float ssum = 0.f;
#pragma unroll
    for (int i = 0; i < 12; i++) { w[i] = __expf(w[i] - mx); ssum += w[i]; }
    const float inv = 1.f / ssum;

    const float* op = off + (size_t)bq * (NHEAD * NLVL * NPTS * 2) + h * (NLVL * NPTS * 2);
    const float rx = refp[(size_t)bq * 2];
    const float ry = refp[(size_t)bq * 2 + 1];

    const int lvlStart[NLVL] = {0, 2304, 2880};
    const int lvlH[NLVL] = {48, 24, 12};
    const int lvlW[NLVL] = {48, 24, 12};

    float accx = 0.f, accy = 0.f;
#pragma unroll
    for (int lv = 0; lv < NLVL; lv++) {
        const int Hl = lvlH[lv], Wl = lvlW[lv], st = lvlStart[lv];
        const size_t base = ((size_t)b * LV + st) * CDIM + (size_t)h * DHEAD + 2 * lane;
#pragma unroll
        for (int p = 0; p < NPTS; p++) {
            float cx = op[lv * (NPTS * 2) + p * 2 + 0] + rx;
            float cy = op[lv * (NPTS * 2) + p * 2 + 1] + ry;
            float px = cx * (float)Wl - 0.5f;
            float py = cy * (float)Hl - 0.5f;
            float x0f = floorf(px), y0f = floorf(py);
            float lx = px - x0f, ly = py - y0f;
            int x0 = (int)x0f, y0 = (int)y0f;
            int x1 = x0 + 1,   y1 = y0 + 1;

            const float aw = w[lv * NPTS + p] * inv;

            bool vx0 = (x0 >= 0) & (x0 < Wl);
            bool vx1 = (x1 >= 0) & (x1 < Wl);
            bool vy0 = (y0 >= 0) & (y0 < Hl);
            bool vy1 = (y1 >= 0) & (y1 < Hl);

            float2 v00 = {0.f, 0.f}, v10 = {0.f, 0.f}, v01 = {0.f, 0.f}, v11 = {0.f, 0.f};
            if (vy0 & vx0) v00 = __half22float2(*(const __half2*)&val[base + (size_t)(y0 * Wl + x0) * CDIM]);
            if (vy0 & vx1) v10 = __half22float2(*(const __half2*)&val[base + (size_t)(y0 * Wl + x1) * CDIM]);
            if (vy1 & vx0) v01 = __half22float2(*(const __half2*)&val[base + (size_t)(y1 * Wl + x0) * CDIM]);
            if (vy1 & vx1) v11 = __half22float2(*(const __half2*)&val[base + (size_t)(y1 * Wl + x1) * CDIM]);

            float w00 = (1.f - lx) * (1.f - ly), w10 = lx * (1.f - ly);
            float w01 = (1.f - lx) * ly,         w11 = lx * ly;
            accx += aw * (w00 * v00.x + w10 * v10.x + w01 * v01.x + w11 * v11.x);
            accy += aw * (w00 * v00.y + w10 * v10.y + w01 * v01.y + w11 * v11.y);
        }
    }

    *(__half2*)&mid[(size_t)bq * CDIM + h * DHEAD + 2 * lane] = __floats2half2_rn(accx, accy);
}

// ===========================================================================
extern "C" void kernel_launch(void* const* d_in, const int* in_sizes, int n_in,
                              void* d_out, int out_size)
{
    const float* query   = (const float*)d_in[0];
    const float* value   = (const float*)d_in[1];
    const float* rp      = (const float*)d_in[2];
    const float* W_value = (const float*)d_in[3];
    const float* b_value = (const float*)d_in[4];
    const float* W_off   = (const float*)d_in[5];
    const float* b_off   = (const float*)d_in[6];
    const float* W_attn  = (const float*)d_in[7];
    const float* b_attn  = (const float*)d_in[8];
    const float* W_out   = (const float*)d_in[9];
    const float* b_out   = (const float*)d_in[10];
    float* out = (float*)d_out;

    __half *val, *valh, *q3, *midh, *wv, *wo, *wa, *w3;
    float *off, *attn, *ref;
    cudaGetSymbolAddress((void**)&val,  g_val);
    cudaGetSymbolAddress((void**)&valh, g_value_h);
    cudaGetSymbolAddress((void**)&q3,   g_q3);
    cudaGetSymbolAddress((void**)&midh, g_mid_h);
    cudaGetSymbolAddress((void**)&wv,   g_Wv_h);
    cudaGetSymbolAddress((void**)&wo,   g_Wo_h);
    cudaGetSymbolAddress((void**)&wa,   g_Wa_h);
    cudaGetSymbolAddress((void**)&w3,   g_W3);
    cudaGetSymbolAddress((void**)&off,  g_off);
    cudaGetSymbolAddress((void**)&attn, g_attn);
    cudaGetSymbolAddress((void**)&ref,  g_ref);

    const int Mval = BATCH * LV;   // 96768
    const int Mq   = BATCH * LQ;   // 18432

    static cudaStream_t s2 = nullptr;
    static cudaEvent_t evFork = nullptr, evJoin = nullptr;
    static int configured = 0;
    if (!configured) {
        cudaFuncSetAttribute(gemm_f16_fast<__half>, cudaFuncAttributeMaxDynamicSharedMemorySize, SMEM_TOTAL);
        cudaFuncSetAttribute(gemm_f16_fast<float>,  cudaFuncAttributeMaxDynamicSharedMemorySize, SMEM_TOTAL);
        cudaStreamCreateWithFlags(&s2, cudaStreamNonBlocking);
        cudaEventCreateWithFlags(&evFork, cudaEventDisableTiming);
        cudaEventCreateWithFlags(&evJoin, cudaEventDisableTiming);
        configured = 1;
    }

    // ---- fork: side stream handles the query-side chain ----
    cudaEventRecord(evFork, 0);
    cudaStreamWaitEvent(s2, evFork, 0);

    // ---- side stream: q3 conv, weight convs, off GEMM, attn GEMM, ref ----
    conv_q3<<<(Mq * CDIM + 255) / 256, 256, 0, s2>>>(query, q3, Mq * CDIM);
    conv_wside<<<(384 * 256 + CDIM * 128 + 255) / 256, 256, 0, s2>>>(W_off, w3, W_attn, wa);
    gemm_f16_fast<float><<<dim3(2, Mq / 128), 256, SMEM_TOTAL, s2>>>(
        q3, w3, b_off, off, Mq, 144, 1152, 1152, 256);
    gemm_f16_fast<float><<<dim3(1, Mq / 128), 256, SMEM_TOTAL, s2>>>(
        q3, wa, b_attn, attn, Mq, 72, CDIM, 1152, 128);
    ref_kernel<<<BATCH, 256, 0, s2>>>(rp, ref);
    cudaEventRecord(evJoin, s2);

    // ---- main stream: value conv + val GEMM ----
    {
        int n4val = Mval * CDIM / 4;
        int total = n4val + 2 * (CDIM * CDIM / 4);
        conv_main<<<(total + 255) / 256, 256>>>(value, valh, W_value, wv, W_out, wo, n4val);
    }
    gemm_f16_fast<__half><<<dim3(3, Mval / 128), 256, SMEM_TOTAL>>>(
        valh, wv, b_value, val, Mval, CDIM, CDIM, CDIM, CDIM);

    // ---- join ----
    cudaStreamWaitEvent(0, evJoin, 0);

    // ---- deformable sampling -> fp16 mid ----
    sample_kernel<<<BATCH * LQ, 192>>>(off, attn, ref, val, midh);

    // ---- output projection: (18432,384)@(384,384) -> fp32 ----
    gemm_f16_fast<float><<<dim3(3, Mq / 128), 256, SMEM_TOTAL>>>(
        midh, wo, b_out, out, Mq, CDIM, CDIM, CDIM, CDIM);
}

// round 13
// speedup vs baseline: 3.7943x; 1.1474x over previous
#include <cuda_runtime.h>
#include <cuda_fp16.h>
#include <math.h>
#include <stdint.h>

// Problem constants
#define BATCH 32
#define LQ    576
#define LV    3024
#define CDIM  384
#define NHEAD 6
#define DHEAD 64
#define NLVL  3
#define NPTS  4

#define MQ    (BATCH * LQ)          // 18432
#define MVAL  (BATCH * LV)          // 96768
#define MH    (MVAL / 2)            // 48384 rows per half (16 batches)
#define QH    (MQ / 2)              // 9216  query rows per half
#define NMETA (MQ * NHEAD * 12)     // 1327104 sample points

// Scratch (device globals; no dynamic allocation allowed)
__device__ __half g_val    [MVAL * CDIM];      // value projection (fp16)
__device__ __half g_value_h[MVAL * CDIM];      // fp16 copy of input value
__device__ __half g_q3     [MQ * 1152];        // [qh | qh | ql] stacked K image
__device__ __half g_mid_h  [MQ * CDIM];        // sampled output (fp16)
__device__ __half g_Wv_h[CDIM * CDIM];
__device__ __half g_Wo_h[CDIM * CDIM];
__device__ __half g_Wa_h[CDIM * 128];          // W_attn padded 72 -> 128
__device__ __half g_W3  [1152 * 256];          // [Wh; Wl; Wh] offsets W, N pad 144->256
__device__ float  g_off [MQ * 144];
__device__ float  g_attn[MQ * 72];
__device__ float  g_ref [MQ * 2];
__device__ float4 g_mw  [NMETA];               // premultiplied corner weights
__device__ int    g_mi  [NMETA];               // clamped base element index (incl. h*64)

// ===========================================================================
// helpers
// ===========================================================================
__device__ __forceinline__ uint32_t smem_u32(const void* p) {
    uint32_t a;
    asm("{ .reg .u64 t; cvta.to.shared.u64 t, %1; cvt.u32.u64 %0, t; }" : "=r"(a) : "l"(p));
    return a;
}
__device__ __forceinline__ void cp_async16(uint32_t dst, const void* src) {
    asm volatile("cp.async.cg.shared.global [%0], [%1], 16;" :: "r"(dst), "l"(src));
}
__device__ __forceinline__ void cp_commit() {
    asm volatile("cp.async.commit_group;");
}
__device__ __forceinline__ void ldsm4(uint32_t* r, uint32_t a) {
    asm volatile("ldmatrix.sync.aligned.m8n8.x4.shared.b16 {%0,%1,%2,%3}, [%4];"
        : "=r"(r[0]), "=r"(r[1]), "=r"(r[2]), "=r"(r[3]) : "r"(a));
}
__device__ __forceinline__ void ldsm4t(uint32_t* r, uint32_t a) {
    asm volatile("ldmatrix.sync.aligned.m8n8.x4.trans.shared.b16 {%0,%1,%2,%3}, [%4];"
        : "=r"(r[0]), "=r"(r[1]), "=r"(r[2]), "=r"(r[3]) : "r"(a));
}
#define MMA_F16(Cc, Af, Bf) \
  asm volatile("mma.sync.aligned.m16n8k16.row.col.f32.f16.f16.f32 " \
    "{%0,%1,%2,%3}, {%4,%5,%6,%7}, {%8,%9}, {%0,%1,%2,%3};" \
    : "+f"(Cc[0]), "+f"(Cc[1]), "+f"(Cc[2]), "+f"(Cc[3]) \
    : "r"(Af[0]), "r"(Af[1]), "r"(Af[2]), "r"(Af[3]), "r"(Bf[0]), "r"(Bf[1]))

__device__ __forceinline__ uint32_t pack_h2(float a, float b) {
    __half2 t = __floats2half2_rn(a, b);
    return *(uint32_t*)&t;
}

// ===========================================================================
// Conversion prep kernels
// ===========================================================================
__global__ void conv_f16(const float* __restrict__ in, __half* __restrict__ outp, int n4)
{
    int i = blockIdx.x * 256 + threadIdx.x;
    if (i < n4) {
        float4 v = ((const float4*)in)[i];
        ((uint2*)outp)[i] = make_uint2(pack_h2(v.x, v.y), pack_h2(v.z, v.w));
    }
}

// Wv + Wo -> fp16 (small, runs first on main stream)
__global__ void conv_wvo(const float* __restrict__ Wv, __half* __restrict__ wv,
                         const float* __restrict__ Wo, __half* __restrict__ wo)
{
    int i = blockIdx.x * 256 + threadIdx.x;
    const int nw4 = CDIM * CDIM / 4;
    if (i < nw4) {
        float4 v = ((const float4*)Wv)[i];
        ((uint2*)wv)[i] = make_uint2(pack_h2(v.x, v.y), pack_h2(v.z, v.w));
    } else if (i < 2 * nw4) {
        int j = i - nw4;
        float4 v = ((const float4*)Wo)[j];
        ((uint2*)wo)[j] = make_uint2(pack_h2(v.x, v.y), pack_h2(v.z, v.w));
    }
}

// query -> [qh | qh | ql] per row (K stacked 1152)
__global__ void conv_q3(const float* __restrict__ q, __half* __restrict__ q3, int n)
{
    int i = blockIdx.x * 256 + threadIdx.x;
    if (i < n) {
        int row = i / CDIM, c = i % CDIM;
        float v = q[i];
        __half h = __float2half_rn(v);
        __half l = __float2half_rn(v - __half2float(h));
        __half* r = q3 + (size_t)row * 1152;
        r[c] = h; r[384 + c] = h; r[768 + c] = l;
    }
}

// W_off -> W3 stacked image; W_attn -> padded fp16
__global__ void conv_wside(const float* __restrict__ Wf, __half* __restrict__ w3,
                           const float* __restrict__ Wa, __half* __restrict__ wa)
{
    int i = blockIdx.x * 256 + threadIdx.x;
    if (i < 384 * 256) {
        int k = i >> 8, c = i & 255;
        float v = (c < 144) ? Wf[k * 144 + c] : 0.f;
        __half h = __float2half_rn(v);
        __half l = __float2half_rn(v - __half2float(h));
        w3[(size_t)k * 256 + c] = h;
        w3[(size_t)(384 + k) * 256 + c] = l;
        w3[(size_t)(768 + k) * 256 + c] = h;
    } else {
        int j = i - 384 * 256;
        if (j < CDIM * 128) {
            int r = j >> 7, c = j & 127;
            wa[j] = (c < 72) ? __float2half_rn(Wa[r * 72 + c]) : __half(0.f);
        }
    }
}

// ===========================================================================
// Fast fp16 GEMM (proven R10 kernel, unchanged)
// ===========================================================================
#define ASTB 10240
#define BSTB 8704
#define SMEM_TOTAL (3 * (ASTB + BSTB))   // 56832

template<typename OutT>
__global__ __launch_bounds__(256, 2)
void gemm_f16_fast(const __half* __restrict__ A, const __half* __restrict__ B,
                   const float* __restrict__ bias, OutT* __restrict__ C,
                   int M, int N, int K, int lda, int Bw)
{
    extern __shared__ __align__(16) char dsm[];
    const uint32_t sA = smem_u32(dsm);
    const uint32_t sB = sA + 3 * ASTB;

    const int tid  = threadIdx.x;
    const int m0   = blockIdx.y * 128;
    const int n0   = blockIdx.x * 128;
    const int warp = tid >> 5, lane = tid & 31;
    const int g = lane >> 2, t = lane & 3;
    const int mwb = (warp >> 1) * 32;
    const int nwb = (warp & 1) * 64;

    const int arow = tid >> 2;
    const int ac   = tid & 3;
    const int brow = tid >> 4;
    const int bc   = tid & 15;
    const __half* agp = A + (size_t)(m0 + arow) * lda + ac * 8;
    const __half* bgp = B + (size_t)brow * Bw + n0 + bc * 8;
    const uint32_t adp = sA + arow * 80 + ac * 16;
    const uint32_t bdp = sB + brow * 272 + bc * 16;

    const uint32_t aOff = ((lane & 15) * 40 + (lane >> 4) * 8) * 2 + mwb * 80;
    const uint32_t bOff = ((lane & 15) * 136 + (lane >> 4) * 8) * 2 + nwb * 2;

    float cacc[2][8][4];
#pragma unroll
    for (int i = 0; i < 2; i++)
#pragma unroll
        for (int j = 0; j < 8; j++)
#pragma unroll
            for (int k = 0; k < 4; k++) cacc[i][j][k] = 0.f;

    const int nt = K / 32;

    auto load_stage = [&](int kt, int s) {
        const __half* ag = agp + kt * 32;
        uint32_t ad = adp + s * ASTB;
        cp_async16(ad, ag);
        cp_async16(ad + 64 * 80, ag + (size_t)64 * lda);
        const __half* bg = bgp + (size_t)(kt * 32) * Bw;
        uint32_t bd = bdp + s * BSTB;
        cp_async16(bd, bg);
        cp_async16(bd + 16 * 272, bg + (size_t)16 * Bw);
    };

    load_stage(0, 0); cp_commit();
    load_stage(1, 1); cp_commit();

    for (int kt = 0; kt < nt; kt++) {
        if (kt < nt - 1) { asm volatile("cp.async.wait_group 1;"); }
        else             { asm volatile("cp.async.wait_group 0;"); }
        __syncthreads();

        if (kt + 2 < nt) {
            load_stage(kt + 2, (kt + 2) % 3);
            cp_commit();
        }

        const int s = kt % 3;
        const uint32_t aBase = sA + s * ASTB + aOff;
        const uint32_t bBase = sB + s * BSTB + bOff;
#pragma unroll
        for (int ks = 0; ks < 2; ks++) {
            uint32_t aH[2][4], bF[4][4];
            ldsm4(aH[0], aBase + ks * 32);
            ldsm4(aH[1], aBase + 16 * 80 + ks * 32);
#pragma unroll
            for (int p = 0; p < 4; p++)
                ldsm4t(bF[p], bBase + ks * 16 * 272 + p * 32);
#pragma unroll
            for (int mi = 0; mi < 2; mi++)
#pragma unroll
                for (int nj = 0; nj < 8; nj++) {
                    uint32_t bfr[2] = { bF[nj >> 1][(nj & 1) * 2], bF[nj >> 1][(nj & 1) * 2 + 1] };
                    MMA_F16(cacc[mi][nj], aH[mi], bfr);
                }
        }
    }
    __syncthreads();

#pragma unroll
    for (int mi = 0; mi < 2; mi++) {
#pragma unroll
        for (int nj = 0; nj < 8; nj++) {
            int row = m0 + mwb + mi * 16 + g;
            int col = n0 + nwb + nj * 8 + 2 * t;
            if (col < N) {
                float b0 = bias[col], b1 = bias[col + 1];
                float v00 = cacc[mi][nj][0] + b0, v01 = cacc[mi][nj][1] + b1;
                float v10 = cacc[mi][nj][2] + b0, v11 = cacc[mi][nj][3] + b1;
                if (sizeof(OutT) == 4) {
                    *(float2*)((float*)C + (size_t)row * N + col) = make_float2(v00, v01);
                    *(float2*)((float*)C + (size_t)(row + 8) * N + col) = make_float2(v10, v11);
                } else {
                    *(__half2*)((__half*)C + (size_t)row * N + col) = __floats2half2_rn(v00, v01);
                    *(__half2*)((__half*)C + (size_t)(row + 8) * N + col) = __floats2half2_rn(v10, v11);
                }
            }
        }
    }
}

// ===========================================================================
// Reference-point processing
// ===========================================================================
__global__ void ref_kernel(const float* __restrict__ rp, float* __restrict__ ref)
{
    const int b = blockIdx.x;
    const float* r = rp + (size_t)b * LV * 2;

    __shared__ float redx[256], redy[256];
    float ax = 0.f, ay = 0.f;
    for (int i = threadIdx.x; i < 2304; i += 256) {
        ax += r[2 * i];
        ay += r[2 * i + 1];
    }
    redx[threadIdx.x] = ax; redy[threadIdx.x] = ay;
    __syncthreads();
    for (int s = 128; s > 0; s >>= 1) {
        if (threadIdx.x < s) {
            redx[threadIdx.x] += redx[threadIdx.x + s];
            redy[threadIdx.x] += redy[threadIdx.x + s];
        }
        __syncthreads();
    }
    const float p1x = redx[0] * (1.f / 2304.f);
    const float p1y = redy[0] * (1.f / 2304.f);

    for (int q = threadIdx.x; q < LQ; q += 256) {
        float p2x = r[2 * (2304 + q)];
        float p2y = r[2 * (2304 + q) + 1];

        int rr = q / 24, cc = q % 24;
        float yy = 0.5f * rr - 0.25f;
        float xx = 0.5f * cc - 0.25f;
        int y0 = (int)floorf(yy), x0 = (int)floorf(xx);
        float wy = yy - (float)y0, wx = xx - (float)x0;
        int y0c = max(y0, 0), y1c = min(y0 + 1, 11);
        int x0c = max(x0, 0), x1c = min(x0 + 1, 11);

        const float* p3 = r + 2 * 2880;
        float v00x = p3[2 * (y0c * 12 + x0c)],     v00y = p3[2 * (y0c * 12 + x0c) + 1];
        float v01x = p3[2 * (y0c * 12 + x1c)],     v01y = p3[2 * (y0c * 12 + x1c) + 1];
        float v10x = p3[2 * (y1c * 12 + x0c)],     v10y = p3[2 * (y1c * 12 + x0c) + 1];
        float v11x = p3[2 * (y1c * 12 + x1c)],     v11y = p3[2 * (y1c * 12 + x1c) + 1];
        float p3x = (1.f - wy) * ((1.f - wx) * v00x + wx * v01x) + wy * ((1.f - wx) * v10x + wx * v11x);
        float p3y = (1.f - wy) * ((1.f - wx) * v00y + wx * v01y) + wy * ((1.f - wx) * v10y + wx * v11y);

        ref[((size_t)b * LQ + q) * 2 + 0] = (p1x + p2x + p3x) * (1.f / 3.f);
        ref[((size_t)b * LQ + q) * 2 + 1] = (p1y + p2y + p3y) * (1.f / 3.f);
    }
}

// ===========================================================================
// Meta prep: one thread per (b,q,h,pt). Softmax + coords + clamped base +
// premultiplied (zeroed-if-invalid) corner weights.
// ===========================================================================
__global__ void meta_prep(const float* __restrict__ off,
                          const float* __restrict__ logits,
                          const float* __restrict__ refp,
                          float4* __restrict__ mw, int* __restrict__ mi)
{
    int j = blockIdx.x * 256 + threadIdx.x;
    if (j >= NMETA) return;
    int pt  = j % 12;
    int bqh = j / 12;
    int h   = bqh % NHEAD;
    int bq  = bqh / NHEAD;
    int b   = bq / LQ;

    // softmax weight for this slot
    const float* lg = logits + bq * 72 + h * 12;
    float e[12], mx = -1e30f;
#pragma unroll
    for (int i = 0; i < 12; i++) { e[i] = lg[i]; mx = fmaxf(mx, e[i]); }
    float ssum = 0.f;
#pragma unroll
    for (int i = 0; i < 12; i++) { e[i] = __expf(e[i] - mx); ssum += e[i]; }
    const float aw = e[pt] / ssum;

    const int lv = pt >> 2, p = pt & 3;
    const int Wl = (lv == 0) ? 48 : (lv == 1) ? 24 : 12;
    const int Hl = Wl;
    const int st = (lv == 0) ? 0  : (lv == 1) ? 2304 : 2880;

    float cx = off[bq * 144 + h * 24 + lv * 8 + p * 2 + 0] + refp[bq * 2 + 0];
    float cy = off[bq * 144 + h * 24 + lv * 8 + p * 2 + 1] + refp[bq * 2 + 1];
    float px = cx * (float)Wl - 0.5f;
    float py = cy * (float)Hl - 0.5f;
    float x0f = floorf(px), y0f = floorf(py);
    float lx = px - x0f, ly = py - y0f;
    int x0 = (int)x0f, y0 = (int)y0f;
    int x1 = x0 + 1,   y1 = y0 + 1;

    bool vx0 = (x0 >= 0) & (x0 < Wl);
    bool vx1 = (x1 >= 0) & (x1 < Wl);
    bool vy0 = (y0 >= 0) & (y0 < Hl);
    bool vy1 = (y1 >= 0) & (y1 < Hl);

    float w00 = (1.f - lx) * (1.f - ly) * aw, w10 = lx * (1.f - ly) * aw;
    float w01 = (1.f - lx) * ly * aw,         w11 = lx * ly * aw;

    int xb = min(max(x0, 0), Wl - 2);
    int yb = min(max(y0, 0), Hl - 2);

    float wb0 = 0.f, wb1 = 0.f, wb2 = 0.f, wb3 = 0.f;
    if (vx0 & vy0) { if (y0 == yb) { if (x0 == xb) wb0 += w00; else wb1 += w00; }
                     else          { if (x0 == xb) wb2 += w00; else wb3 += w00; } }
    if (vx1 & vy0) { if (y0 == yb) { if (x1 == xb) wb0 += w10; else wb1 += w10; }
                     else          { if (x1 == xb) wb2 += w10; else wb3 += w10; } }
    if (vx0 & vy1) { if (y1 == yb) { if (x0 == xb) wb0 += w01; else wb1 += w01; }
                     else          { if (x0 == xb) wb2 += w01; else wb3 += w01; } }
    if (vx1 & vy1) { if (y1 == yb) { if (x1 == xb) wb0 += w11; else wb1 += w11; }
                     else          { if (x1 == xb) wb2 += w11; else wb3 += w11; } }

    mw[j] = make_float4(wb0, wb1, wb2, wb3);
    mi[j] = (b * LV + st + yb * Wl + xb) * CDIM + h * DHEAD;
}

// ===========================================================================
// Slim sampling: warp per (b,q,h); per point 2 broadcast loads + 4 gathers.
// ===========================================================================
__global__ __launch_bounds__(192)
void sample2(const float4* __restrict__ mw, const int* __restrict__ mi,
             const __half* __restrict__ val, __half* __restrict__ mid, int bq0)
{
    const int bq   = bq0 + blockIdx.x;
    const int h    = threadIdx.x >> 5;
    const int lane = threadIdx.x & 31;

    const float4* wp = mw + (size_t)(bq * NHEAD + h) * 12;
    const int*    ip = mi + (size_t)(bq * NHEAD + h) * 12;

    float ax = 0.f, ay = 0.f;
#pragma unroll
    for (int pt = 0; pt < 12; pt++) {
        const int Wl = (pt < 4) ? 48 : (pt < 8) ? 24 : 12;
        float4 w = wp[pt];
        int base = ip[pt] + 2 * lane;
        float2 v00 = __half22float2(*(const __half2*)&val[base]);
        float2 v10 = __half22float2(*(const __half2*)&val[base + CDIM]);
        float2 v01 = __half22float2(*(const __half2*)&val[base + Wl * CDIM]);
        float2 v11 = __half22float2(*(const __half2*)&val[base + (Wl + 1) * CDIM]);
        ax += w.x * v00.x + w.y * v10.x + w.z * v01.x + w.w * v11.x;
        ay += w.x * v00.y + w.y * v10.y + w.z * v01.y + w.w * v11.y;
    }

    *(__half2*)&mid[(size_t)bq * CDIM + h * DHEAD + 2 * lane] = __floats2half2_rn(ax, ay);
}

// ===========================================================================
extern "C" void kernel_launch(void* const* d_in, const int* in_sizes, int n_in,
                              void* d_out, int out_size)
{
    const float* query   = (const float*)d_in[0];
    const float* value   = (const float*)d_in[1];
    const float* rp      = (const float*)d_in[2];
    const float* W_value = (const float*)d_in[3];
    const float* b_value = (const float*)d_in[4];
    const float* W_off   = (const float*)d_in[5];
    const float* b_off   = (const float*)d_in[6];
    const float* W_attn  = (const float*)d_in[7];
    const float* b_attn  = (const float*)d_in[8];
    const float* W_out   = (const float*)d_in[9];
    const float* b_out   = (const float*)d_in[10];
    float* out = (float*)d_out;

    __half *val, *valh, *q3, *midh, *wv, *wo, *wa, *w3;
    float *off, *attn, *ref;
    float4* mw; int* mi;
    cudaGetSymbolAddress((void**)&val,  g_val);
    cudaGetSymbolAddress((void**)&valh, g_value_h);
    cudaGetSymbolAddress((void**)&q3,   g_q3);
    cudaGetSymbolAddress((void**)&midh, g_mid_h);
    cudaGetSymbolAddress((void**)&wv,   g_Wv_h);
    cudaGetSymbolAddress((void**)&wo,   g_Wo_h);
    cudaGetSymbolAddress((void**)&wa,   g_Wa_h);
    cudaGetSymbolAddress((void**)&w3,   g_W3);
    cudaGetSymbolAddress((void**)&off,  g_off);
    cudaGetSymbolAddress((void**)&attn, g_attn);
    cudaGetSymbolAddress((void**)&ref,  g_ref);
    cudaGetSymbolAddress((void**)&mw,   g_mw);
    cudaGetSymbolAddress((void**)&mi,   g_mi);

    static cudaStream_t s2 = nullptr, s3 = nullptr;
    static cudaEvent_t evFork = nullptr, evC1 = nullptr, evV0 = nullptr,
                       evV1 = nullptr, evW = nullptr, evEnd = nullptr;
    static int configured = 0;
    if (!configured) {
        cudaFuncSetAttribute(gemm_f16_fast<__half>, cudaFuncAttributeMaxDynamicSharedMemorySize, SMEM_TOTAL);
        cudaFuncSetAttribute(gemm_f16_fast<float>,  cudaFuncAttributeMaxDynamicSharedMemorySize, SMEM_TOTAL);
        cudaStreamCreateWithFlags(&s2, cudaStreamNonBlocking);
        cudaStreamCreateWithFlags(&s3, cudaStreamNonBlocking);
        cudaEventCreateWithFlags(&evFork, cudaEventDisableTiming);
        cudaEventCreateWithFlags(&evC1,   cudaEventDisableTiming);
        cudaEventCreateWithFlags(&evV0,   cudaEventDisableTiming);
        cudaEventCreateWithFlags(&evV1,   cudaEventDisableTiming);
        cudaEventCreateWithFlags(&evW,    cudaEventDisableTiming);
        cudaEventCreateWithFlags(&evEnd,  cudaEventDisableTiming);
        configured = 1;
    }

    const int HOFF = MH * CDIM;     // element offset of half 1 in value/val

    // ---- fork ----
    cudaEventRecord(evFork, 0);
    cudaStreamWaitEvent(s2, evFork, 0);
    cudaStreamWaitEvent(s3, evFork, 0);

    // ---- s3: convert value half 1 ----
    conv_f16<<<(HOFF / 4 + 255) / 256, 256, 0, s3>>>(value + HOFF, valh + HOFF, HOFF / 4);
    cudaEventRecord(evC1, s3);

    // ---- s2: query-side chain + meta ----
    conv_q3<<<(MQ * CDIM + 255) / 256, 256, 0, s2>>>(query, q3, MQ * CDIM);
    conv_wside<<<(384 * 256 + CDIM * 128 + 255) / 256, 256, 0, s2>>>(W_off, w3, W_attn, wa);
    gemm_f16_fast<float><<<dim3(2, MQ / 128), 256, SMEM_TOTAL, s2>>>(
        q3, w3, b_off, off, MQ, 144, 1152, 1152, 256);
    gemm_f16_fast<float><<<dim3(1, MQ / 128), 256, SMEM_TOTAL, s2>>>(
        q3, wa, b_attn, attn, MQ, 72, CDIM, 1152, 128);
    ref_kernel<<<BATCH, 256, 0, s2>>>(rp, ref);
    meta_prep<<<(NMETA + 255) / 256, 256, 0, s2>>>(off, attn, ref, mw, mi);

    // ---- main: weights + value half 0 conversion, val GEMM halves ----
    conv_wvo<<<(2 * CDIM * CDIM / 4 + 255) / 256, 256>>>(W_value, wv, W_out, wo);
    cudaEventRecord(evW, 0);
    conv_f16<<<(HOFF / 4 + 255) / 256, 256>>>(value, valh, HOFF / 4);
    gemm_f16_fast<__half><<<dim3(3, MH / 128), 256, SMEM_TOTAL>>>(
        valh, wv, b_value, val, MH, CDIM, CDIM, CDIM, CDIM);
    cudaEventRecord(evV0, 0);
    cudaStreamWaitEvent(0, evC1, 0);
    gemm_f16_fast<__half><<<dim3(3, MH / 128), 256, SMEM_TOTAL>>>(
        valh + HOFF, wv, b_value, val + HOFF, MH, CDIM, CDIM, CDIM, CDIM);
    cudaEventRecord(evV1, 0);

    // ---- s2: sample + out-proj per half ----
    cudaStreamWaitEvent(s2, evW, 0);
    cudaStreamWaitEvent(s2, evV0, 0);
    sample2<<<QH, 192, 0, s2>>>(mw, mi, val, midh, 0);
    gemm_f16_fast<float><<<dim3(3, QH / 128), 256, SMEM_TOTAL, s2>>>(
        midh, wo, b_out, out, QH, CDIM, CDIM, CDIM, CDIM);
    cudaStreamWaitEvent(s2, evV1, 0);
    sample2<<<QH, 192, 0, s2>>>(mw, mi, val, midh, QH);
    gemm_f16_fast<float><<<dim3(3, QH / 128), 256, SMEM_TOTAL, s2>>>(
        midh + (size_t)QH * CDIM, wo, b_out, out + (size_t)QH * CDIM, QH, CDIM, CDIM, CDIM, CDIM);
    cudaEventRecord(evEnd, s2);

    // ---- join ----
    cudaStreamWaitEvent(0, evEnd, 0);
}

// round 15
// speedup vs baseline: 3.9652x; 1.0450x over previous
#include <cuda_runtime.h>
#include <cuda_fp16.h>
#include <math.h>
#include <stdint.h>

// Problem constants
#define BATCH 32
#define LQ    576
#define LV    3024
#define CDIM  384
#define NHEAD 6
#define DHEAD 64
#define NLVL  3
#define NPTS  4

#define MQ    (BATCH * LQ)          // 18432
#define MVAL  (BATCH * LV)          // 96768
#define MH    (MVAL / 2)            // 48384 rows per half
#define QH    (MQ / 2)              // 9216 query rows per half
#define NMETA (MQ * NHEAD * 12)

// Scratch (device globals; no dynamic allocation allowed)
__device__ __half g_val  [MVAL * CDIM];
__device__ __half g_q3   [MQ * 1152];
__device__ __half g_mid_h[MQ * CDIM];
__device__ __half g_Wv_h[CDIM * CDIM];
__device__ __half g_Wo_h[CDIM * CDIM];
__device__ __half g_Wa_h[CDIM * 128];
__device__ __half g_W3  [1152 * 256];
__device__ float  g_off [MQ * 144];
__device__ float  g_attn[MQ * 72];
__device__ float  g_ref [MQ * 2];
__device__ float4 g_mw  [NMETA];
__device__ int    g_mi  [NMETA];

// ===========================================================================
// helpers
// ===========================================================================
__device__ __forceinline__ uint32_t smem_u32(const void* p) {
    uint32_t a;
    asm("{ .reg .u64 t; cvta.to.shared.u64 t, %1; cvt.u32.u64 %0, t; }" : "=r"(a) : "l"(p));
    return a;
}
__device__ __forceinline__ void cp_async16(uint32_t dst, const void* src) {
    asm volatile("cp.async.cg.shared.global [%0], [%1], 16;" :: "r"(dst), "l"(src));
}
__device__ __forceinline__ void cp_commit() {
    asm volatile("cp.async.commit_group;");
}
__device__ __forceinline__ void ldsm4(uint32_t* r, uint32_t a) {
    asm volatile("ldmatrix.sync.aligned.m8n8.x4.shared.b16 {%0,%1,%2,%3}, [%4];"
        : "=r"(r[0]), "=r"(r[1]), "=r"(r[2]), "=r"(r[3]) : "r"(a));
}
__device__ __forceinline__ void ldsm4t(uint32_t* r, uint32_t a) {
    asm volatile("ldmatrix.sync.aligned.m8n8.x4.trans.shared.b16 {%0,%1,%2,%3}, [%4];"
        : "=r"(r[0]), "=r"(r[1]), "=r"(r[2]), "=r"(r[3]) : "r"(a));
}
#define MMA_F16(Cc, Af, Bf) \
  asm volatile("mma.sync.aligned.m16n8k16.row.col.f32.f16.f16.f32 " \
    "{%0,%1,%2,%3}, {%4,%5,%6,%7}, {%8,%9}, {%0,%1,%2,%3};" \
    : "+f"(Cc[0]), "+f"(Cc[1]), "+f"(Cc[2]), "+f"(Cc[3]) \
    : "r"(Af[0]), "r"(Af[1]), "r"(Af[2]), "r"(Af[3]), "r"(Bf[0]), "r"(Bf[1]))

__device__ __forceinline__ uint32_t pack_h2(float a, float b) {
    __half2 t = __floats2half2_rn(a, b);
    return *(uint32_t*)&t;
}

// ===========================================================================
// prep kernels
// ===========================================================================
__global__ void conv_wvo(const float* __restrict__ Wv, __half* __restrict__ wv,
                         const float* __restrict__ Wo, __half* __restrict__ wo)
{
    int i = blockIdx.x * 256 + threadIdx.x;
    const int nw4 = CDIM * CDIM / 4;
    if (i < nw4) {
        float4 v = ((const float4*)Wv)[i];
        ((uint2*)wv)[i] = make_uint2(pack_h2(v.x, v.y), pack_h2(v.z, v.w));
    } else if (i < 2 * nw4) {
        int j = i - nw4;
        float4 v = ((const float4*)Wo)[j];
        ((uint2*)wo)[j] = make_uint2(pack_h2(v.x, v.y), pack_h2(v.z, v.w));
    }
}

__global__ void conv_q3(const float* __restrict__ q, __half* __restrict__ q3, int n)
{
    int i = blockIdx.x * 256 + threadIdx.x;
    if (i < n) {
        int row = i / CDIM, c = i % CDIM;
        float v = q[i];
        __half h = __float2half_rn(v);
        __half l = __float2half_rn(v - __half2float(h));
        __half* r = q3 + (size_t)row * 1152;
        r[c] = h; r[384 + c] = h; r[768 + c] = l;
    }
}

__global__ void conv_wside(const float* __restrict__ Wf, __half* __restrict__ w3,
                           const float* __restrict__ Wa, __half* __restrict__ wa)
{
    int i = blockIdx.x * 256 + threadIdx.x;
    if (i < 384 * 256) {
        int k = i >> 8, c = i & 255;
        float v = (c < 144) ? Wf[k * 144 + c] : 0.f;
        __half h = __float2half_rn(v);
        __half l = __float2half_rn(v - __half2float(h));
        w3[(size_t)k * 256 + c] = h;
        w3[(size_t)(384 + k) * 256 + c] = l;
        w3[(size_t)(768 + k) * 256 + c] = h;
    } else {
        int j = i - 384 * 256;
        if (j < CDIM * 128) {
            int r = j >> 7, c = j & 127;
            wa[j] = (c < 72) ? __float2half_rn(Wa[r * 72 + c]) : __half(0.f);
        }
    }
}

// ===========================================================================
// Fast fp16 GEMM (proven kernel; A fp16)
// ===========================================================================
#define ASTB 10240
#define BSTB 8704
#define SMEM_TOTAL (3 * (ASTB + BSTB))   // 56832

template<typename OutT>
__global__ __launch_bounds__(256, 2)
void gemm_f16_fast(const __half* __restrict__ A, const __half* __restrict__ B,
                   const float* __restrict__ bias, OutT* __restrict__ C,
                   int M, int N, int K, int lda, int Bw)
{
    extern __shared__ __align__(16) char dsm[];
    const uint32_t sA = smem_u32(dsm);
    const uint32_t sB = sA + 3 * ASTB;

    const int tid  = threadIdx.x;
    const int m0   = blockIdx.y * 128;
    const int n0   = blockIdx.x * 128;
    const int warp = tid >> 5, lane = tid & 31;
    const int g = lane >> 2, t = lane & 3;
    const int mwb = (warp >> 1) * 32;
    const int nwb = (warp & 1) * 64;

    const int arow = tid >> 2;
    const int ac   = tid & 3;
    const int brow = tid >> 4;
    const int bc   = tid & 15;
    const __half* agp = A + (size_t)(m0 + arow) * lda + ac * 8;
    const __half* bgp = B + (size_t)brow * Bw + n0 + bc * 8;
    const uint32_t adp = sA + arow * 80 + ac * 16;
    const uint32_t bdp = sB + brow * 272 + bc * 16;

    const uint32_t aOff = ((lane & 15) * 40 + (lane >> 4) * 8) * 2 + mwb * 80;
    const uint32_t bOff = ((lane & 15) * 136 + (lane >> 4) * 8) * 2 + nwb * 2;

    float cacc[2][8][4];
#pragma unroll
    for (int i = 0; i < 2; i++)
#pragma unroll
        for (int j = 0; j < 8; j++)
#pragma unroll
            for (int k = 0; k < 4; k++) cacc[i][j][k] = 0.f;

    const int nt = K / 32;

    auto load_stage = [&](int kt, int s) {
        const __half* ag = agp + kt * 32;
        uint32_t ad = adp + s * ASTB;
        cp_async16(ad, ag);
        cp_async16(ad + 64 * 80, ag + (size_t)64 * lda);
        const __half* bg = bgp + (size_t)(kt * 32) * Bw;
        uint32_t bd = bdp + s * BSTB;
        cp_async16(bd, bg);
        cp_async16(bd + 16 * 272, bg + (size_t)16 * Bw);
    };

    load_stage(0, 0); cp_commit();
    load_stage(1, 1); cp_commit();

    for (int kt = 0; kt < nt; kt++) {
        if (kt < nt - 1) { asm volatile("cp.async.wait_group 1;"); }
        else             { asm volatile("cp.async.wait_group 0;"); }
        __syncthreads();

        if (kt + 2 < nt) {
            load_stage(kt + 2, (kt + 2) % 3);
            cp_commit();
        }

        const int s = kt % 3;
        const uint32_t aBase = sA + s * ASTB + aOff;
        const uint32_t bBase = sB + s * BSTB + bOff;
#pragma unroll
        for (int ks = 0; ks < 2; ks++) {
            uint32_t aH[2][4], bF[4][4];
            ldsm4(aH[0], aBase + ks * 32);
            ldsm4(aH[1], aBase + 16 * 80 + ks * 32);
#pragma unroll
            for (int p = 0; p < 4; p++)
                ldsm4t(bF[p], bBase + ks * 16 * 272 + p * 32);
#pragma unroll
            for (int mi = 0; mi < 2; mi++)
#pragma unroll
                for (int nj = 0; nj < 8; nj++) {
                    uint32_t bfr[2] = { bF[nj >> 1][(nj & 1) * 2], bF[nj >> 1][(nj & 1) * 2 + 1] };
                    MMA_F16(cacc[mi][nj], aH[mi], bfr);
                }
        }
        __syncthreads();
    }

#pragma unroll
    for (int mi = 0; mi < 2; mi++) {
#pragma unroll
        for (int nj = 0; nj < 8; nj++) {
            int row = m0 + mwb + mi * 16 + g;
            int col = n0 + nwb + nj * 8 + 2 * t;
            if (col < N) {
                float b0 = bias[col], b1 = bias[col + 1];
                float v00 = cacc[mi][nj][0] + b0, v01 = cacc[mi][nj][1] + b1;
                float v10 = cacc[mi][nj][2] + b0, v11 = cacc[mi][nj][3] + b1;
                if (sizeof(OutT) == 4) {
                    *(float2*)((float*)C + (size_t)row * N + col) = make_float2(v00, v01);
                    *(float2*)((float*)C + (size_t)(row + 8) * N + col) = make_float2(v10, v11);
                } else {
                    *(__half2*)((__half*)C + (size_t)row * N + col) = __floats2half2_rn(v00, v01);
                    *(__half2*)((__half*)C + (size_t)(row + 8) * N + col) = __floats2half2_rn(v10, v11);
                }
            }
        }
    }
}

// ===========================================================================
// Fused-conversion GEMM: A fp32 (registers, double-buffered cvt->STS),
// B fp16 via 3-stage cp.async. C fp16. N = 384, K = 384 fixed shapes OK.
// A smem: 2 stages x [128][40] fp16. One __syncthreads per K-iteration.
// ===========================================================================
__global__ __launch_bounds__(256, 2)
void gemm_conva(const float* __restrict__ A, const __half* __restrict__ B,
                const float* __restrict__ bias, __half* __restrict__ C,
                int M, int N, int K, int lda, int Bw)
{
    extern __shared__ __align__(16) char dsm[];
    const uint32_t sA = smem_u32(dsm);              // 2 * ASTB
    const uint32_t sB = sA + 2 * ASTB;              // 3 * BSTB

    const int tid  = threadIdx.x;
    const int m0   = blockIdx.y * 128;
    const int n0   = blockIdx.x * 128;
    const int warp = tid >> 5, lane = tid & 31;
    const int g = lane >> 2, t = lane & 3;
    const int mwb = (warp >> 1) * 32;
    const int nwb = (warp & 1) * 64;

    // A ldg: 2 threads/row, 16 fp32 each (4 float4)
    const int arow = tid >> 1;
    const int ak   = (tid & 1) * 16;
    const float* agp = A + (size_t)(m0 + arow) * lda + ak;
    // B cp.async mapping (same as fast kernel)
    const int brow = tid >> 4;
    const int bc   = tid & 15;
    const __half* bgp = B + (size_t)brow * Bw + n0 + bc * 8;
    const uint32_t bdp = sB + brow * 272 + bc * 16;

    const uint32_t aOff = ((lane & 15) * 40 + (lane >> 4) * 8) * 2 + mwb * 80;
    const uint32_t bOff = ((lane & 15) * 136 + (lane >> 4) * 8) * 2 + nwb * 2;

    float cacc[2][8][4];
#pragma unroll
    for (int i = 0; i < 2; i++)
#pragma unroll
        for (int j = 0; j < 8; j++)
#pragma unroll
            for (int k = 0; k < 4; k++) cacc[i][j][k] = 0.f;

    const int nt = K / 32;

    auto load_b = [&](int kt, int s) {
        const __half* bg = bgp + (size_t)(kt * 32) * Bw;
        uint32_t bd = bdp + s * BSTB;
        cp_async16(bd, bg);
        cp_async16(bd + 16 * 272, bg + (size_t)16 * Bw);
    };

    float4 pa[4];
#pragma unroll
    for (int j = 0; j < 4; j++) pa[j] = *(const float4*)(agp + j * 4);
    load_b(0, 0); cp_commit();
    load_b(1, 1); cp_commit();

    for (int kt = 0; kt < nt; kt++) {
        // STS A (cvt fp32->fp16) into buffer kt&1
        {
            uint32_t ad = sA + (kt & 1) * ASTB + arow * 80 + ak * 2;
#pragma unroll
            for (int j = 0; j < 4; j++) {
                float4 v = pa[j];
                *(uint2*)(dsm + (ad - sA) + j * 8) =
                    make_uint2(pack_h2(v.x, v.y), pack_h2(v.z, v.w));
            }
        }
        if (kt < nt - 1) { asm volatile("cp.async.wait_group 1;"); }
        else             { asm volatile("cp.async.wait_group 0;"); }
        __syncthreads();

        if (kt + 1 < nt) {
            const float* p = agp + (kt + 1) * 32;
#pragma unroll
            for (int j = 0; j < 4; j++) pa[j] = *(const float4*)(p + j * 4);
        }
        if (kt + 2 < nt) { load_b(kt + 2, (kt + 2) % 3); cp_commit(); }

        const uint32_t aBase = sA + (kt & 1) * ASTB + aOff;
        const uint32_t bBase = sB + (kt % 3) * BSTB + bOff;
#pragma unroll
        for (int ks = 0; ks < 2; ks++) {
            uint32_t aH[2][4], bF[4][4];
            ldsm4(aH[0], aBase + ks * 32);
            ldsm4(aH[1], aBase + 16 * 80 + ks * 32);
#pragma unroll
            for (int p = 0; p < 4; p++)
                ldsm4t(bF[p], bBase + ks * 16 * 272 + p * 32);
#pragma unroll
            for (int mi = 0; mi < 2; mi++)
#pragma unroll
                for (int nj = 0; nj < 8; nj++) {
                    uint32_t bfr[2] = { bF[nj >> 1][(nj & 1) * 2], bF[nj >> 1][(nj & 1) * 2 + 1] };
                    MMA_F16(cacc[mi][nj], aH[mi], bfr);
                }
        }
    }
    __syncthreads();

#pragma unroll
    for (int mi = 0; mi < 2; mi++) {
#pragma unroll
        for (int nj = 0; nj < 8; nj++) {
            int row = m0 + mwb + mi * 16 + g;
            int col = n0 + nwb + nj * 8 + 2 * t;
            float b0 = bias[col], b1 = bias[col + 1];
            *(__half2*)(C + (size_t)row * N + col) =
                __floats2half2_rn(cacc[mi][nj][0] + b0, cacc[mi][nj][1] + b1);
            *(__half2*)(C + (size_t)(row + 8) * N + col) =
                __floats2half2_rn(cacc[mi][nj][2] + b0, cacc[mi][nj][3] + b1);
        }
    }
}
#define SMEM_CONVA (2 * ASTB + 3 * BSTB)   // 46592

// ===========================================================================
// Reference-point processing
// ===========================================================================
__global__ void ref_kernel(const float* __restrict__ rp, float* __restrict__ ref)
{
    const int b = blockIdx.x;
    const float* r = rp + (size_t)b * LV * 2;

    __shared__ float redx[256], redy[256];
    float ax = 0.f, ay = 0.f;
    for (int i = threadIdx.x; i < 2304; i += 256) {
        ax += r[2 * i];
        ay += r[2 * i + 1];
    }
    redx[threadIdx.x] = ax; redy[threadIdx.x] = ay;
    __syncthreads();
    for (int s = 128; s > 0; s >>= 1) {
        if (threadIdx.x < s) {
            redx[threadIdx.x] += redx[threadIdx.x + s];
            redy[threadIdx.x] += redy[threadIdx.x + s];
        }
        __syncthreads();
    }
    const float p1x = redx[0] * (1.f / 2304.f);
    const float p1y = redy[0] * (1.f / 2304.f);

    for (int q = threadIdx.x; q < LQ; q += 256) {
        float p2x = r[2 * (2304 + q)];
        float p2y = r[2 * (2304 + q) + 1];

        int rr = q / 24, cc = q % 24;
        float yy = 0.5f * rr - 0.25f;
        float xx = 0.5f * cc - 0.25f;
        int y0 = (int)floorf(yy), x0 = (int)floorf(xx);
        float wy = yy - (float)y0, wx = xx - (float)x0;
        int y0c = max(y0, 0), y1c = min(y0 + 1, 11);
        int x0c = max(x0, 0), x1c = min(x0 + 1, 11);

        const float* p3 = r + 2 * 2880;
        float v00x = p3[2 * (y0c * 12 + x0c)],     v00y = p3[2 * (y0c * 12 + x0c) + 1];
        float v01x = p3[2 * (y0c * 12 + x1c)],     v01y = p3[2 * (y0c * 12 + x1c) + 1];
        float v10x = p3[2 * (y1c * 12 + x0c)],     v10y = p3[2 * (y1c * 12 + x0c) + 1];
        float v11x = p3[2 * (y1c * 12 + x1c)],     v11y = p3[2 * (y1c * 12 + x1c) + 1];
        float p3x = (1.f - wy) * ((1.f - wx) * v00x + wx * v01x) + wy * ((1.f - wx) * v10x + wx * v11x);
        float p3y = (1.f - wy) * ((1.f - wx) * v00y + wx * v01y) + wy * ((1.f - wx) * v10y + wx * v11y);

        ref[((size_t)b * LQ + q) * 2 + 0] = (p1x + p2x + p3x) * (1.f / 3.f);
        ref[((size_t)b * LQ + q) * 2 + 1] = (p1y + p2y + p3y) * (1.f / 3.f);
    }
}

// ===========================================================================
// Meta prep (unchanged)
// ===========================================================================
__global__ void meta_prep(const float* __restrict__ off,
                          const float* __restrict__ logits,
                          const float* __restrict__ refp,
                          float4* __restrict__ mw, int* __restrict__ mi)
{
    int j = blockIdx.x * 256 + threadIdx.x;
    if (j >= NMETA) return;
    int pt  = j % 12;
    int bqh = j / 12;
    int h   = bqh % NHEAD;
    int bq  = bqh / NHEAD;
    int b   = bq / LQ;

    const float* lg = logits + bq * 72 + h * 12;
    float e[12], mx = -1e30f;
#pragma unroll
    for (int i = 0; i < 12; i++) { e[i] = lg[i]; mx = fmaxf(mx, e[i]); }
    float ssum = 0.f;
#pragma unroll
    for (int i = 0; i < 12; i++) { e[i] = __expf(e[i] - mx); ssum += e[i]; }
    const float aw = e[pt] / ssum;

    const int lv = pt >> 2, p = pt & 3;
    const int Wl = (lv == 0) ? 48 : (lv == 1) ? 24 : 12;
    const int Hl = Wl;
    const int st = (lv == 0) ? 0  : (lv == 1) ? 2304 : 2880;

    float cx = off[bq * 144 + h * 24 + lv * 8 + p * 2 + 0] + refp[bq * 2 + 0];
    float cy = off[bq * 144 + h * 24 + lv * 8 + p * 2 + 1] + refp[bq * 2 + 1];
    float px = cx * (float)Wl - 0.5f;
    float py = cy * (float)Hl - 0.5f;
    float x0f = floorf(px), y0f = floorf(py);
    float lx = px - x0f, ly = py - y0f;
    int x0 = (int)x0f, y0 = (int)y0f;
    int x1 = x0 + 1,   y1 = y0 + 1;

    bool vx0 = (x0 >= 0) & (x0 < Wl);
    bool vx1 = (x1 >= 0) & (x1 < Wl);
    bool vy0 = (y0 >= 0) & (y0 < Hl);
    bool vy1 = (y1 >= 0) & (y1 < Hl);

    float w00 = (1.f - lx) * (1.f - ly) * aw, w10 = lx * (1.f - ly) * aw;
    float w01 = (1.f - lx) * ly * aw,         w11 = lx * ly * aw;

    int xb = min(max(x0, 0), Wl - 2);
    int yb = min(max(y0, 0), Hl - 2);

    float wb0 = 0.f, wb1 = 0.f, wb2 = 0.f, wb3 = 0.f;
    if (vx0 & vy0) { if (y0 == yb) { if (x0 == xb) wb0 += w00; else wb1 += w00; }
                     else          { if (x0 == xb) wb2 += w00; else wb3 += w00; } }
    if (vx1 & vy0) { if (y0 == yb) { if (x1 == xb) wb0 += w10; else wb1 += w10; }
                     else          { if (x1 == xb) wb2 += w10; else wb3 += w10; } }
    if (vx0 & vy1) { if (y1 == yb) { if (x0 == xb) wb0 += w01; else wb1 += w01; }
                     else          { if (x0 == xb) wb2 += w01; else wb3 += w01; } }
    if (vx1 & vy1) { if (y1 == yb) { if (x1 == xb) wb0 += w11; else wb1 += w11; }
                     else          { if (x1 == xb) wb2 += w11; else wb3 += w11; } }

    mw[j] = make_float4(wb0, wb1, wb2, wb3);
    mi[j] = (b * LV + st + yb * Wl + xb) * CDIM + h * DHEAD;
}

// ===========================================================================
// Slim sampling (unchanged)
// ===========================================================================
__global__ __launch_bounds__(192)
void sample2(const float4* __restrict__ mw, const int* __restrict__ mi,
             const __half* __restrict__ val, __half* __restrict__ mid, int bq0)
{
    const int bq   = bq0 + blockIdx.x;
    const int h    = threadIdx.x >> 5;
    const int lane = threadIdx.x & 31;

    const float4* wp = mw + (size_t)(bq * NHEAD + h) * 12;
    const int*    ip = mi + (size_t)(bq * NHEAD + h) * 12;

    float ax = 0.f, ay = 0.f;
#pragma unroll
    for (int pt = 0; pt < 12; pt++) {
        const int Wl = (pt < 4) ? 48 : (pt < 8) ? 24 : 12;
        float4 w = wp[pt];
        int base = ip[pt] + 2 * lane;
        float2 v00 = __half22float2(*(const __half2*)&val[base]);
        float2 v10 = __half22float2(*(const __half2*)&val[base + CDIM]);
        float2 v01 = __half22float2(*(const __half2*)&val[base + Wl * CDIM]);
        float2 v11 = __half22float2(*(const __half2*)&val[base + (Wl + 1) * CDIM]);
        ax += w.x * v00.x + w.y * v10.x + w.z * v01.x + w.w * v11.x;
        ay += w.x * v00.y + w.y * v10.y + w.z * v01.y + w.w * v11.y;
    }

    *(__half2*)&mid[(size_t)bq * CDIM + h * DHEAD + 2 * lane] = __floats2half2_rn(ax, ay);
}

// ===========================================================================
extern "C" void kernel_launch(void* const* d_in, const int* in_sizes, int n_in,
                              void* d_out, int out_size)
{
    const float* query   = (const float*)d_in[0];
    const float* value   = (const float*)d_in[1];
    const float* rp      = (const float*)d_in[2];
    const float* W_value = (const float*)d_in[3];
    const float* b_value = (const float*)d_in[4];
    const float* W_off   = (const float*)d_in[5];
    const float* b_off   = (const float*)d_in[6];
    const float* W_attn  = (const float*)d_in[7];
    const float* b_attn  = (const float*)d_in[8];
    const float* W_out   = (const float*)d_in[9];
    const float* b_out   = (const float*)d_in[10];
    float* out = (float*)d_out;

    __half *val, *q3, *midh, *wv, *wo, *wa, *w3;
    float *off, *attn, *ref;
    float4* mw; int* mi;
    cudaGetSymbolAddress((void**)&val,  g_val);
    cudaGetSymbolAddress((void**)&q3,   g_q3);
    cudaGetSymbolAddress((void**)&midh, g_mid_h);
    cudaGetSymbolAddress((void**)&wv,   g_Wv_h);
    cudaGetSymbolAddress((void**)&wo,   g_Wo_h);
    cudaGetSymbolAddress((void**)&wa,   g_Wa_h);
    cudaGetSymbolAddress((void**)&w3,   g_W3);
    cudaGetSymbolAddress((void**)&off,  g_off);
    cudaGetSymbolAddress((void**)&attn, g_attn);
    cudaGetSymbolAddress((void**)&ref,  g_ref);
    cudaGetSymbolAddress((void**)&mw,   g_mw);
    cudaGetSymbolAddress((void**)&mi,   g_mi);

    static cudaStream_t s2 = nullptr, s3 = nullptr;
    static cudaEvent_t evFork = nullptr, evQ3 = nullptr, evA = nullptr,
                       evV0 = nullptr, evV1 = nullptr, evW = nullptr, evEnd = nullptr;
    static int configured = 0;
    if (!configured) {
        cudaFuncSetAttribute(gemm_f16_fast<__half>, cudaFuncAttributeMaxDynamicSharedMemorySize, SMEM_TOTAL);
        cudaFuncSetAttribute(gemm_f16_fast<float>,  cudaFuncAttributeMaxDynamicSharedMemorySize, SMEM_TOTAL);
        cudaFuncSetAttribute(gemm_conva, cudaFuncAttributeMaxDynamicSharedMemorySize, SMEM_CONVA);
        cudaStreamCreateWithFlags(&s2, cudaStreamNonBlocking);
        cudaStreamCreateWithFlags(&s3, cudaStreamNonBlocking);
        cudaEventCreateWithFlags(&evFork, cudaEventDisableTiming);
        cudaEventCreateWithFlags(&evQ3,   cudaEventDisableTiming);
        cudaEventCreateWithFlags(&evA,    cudaEventDisableTiming);
        cudaEventCreateWithFlags(&evV0,   cudaEventDisableTiming);
        cudaEventCreateWithFlags(&evV1,   cudaEventDisableTiming);
        cudaEventCreateWithFlags(&evW,    cudaEventDisableTiming);
        cudaEventCreateWithFlags(&evEnd,  cudaEventDisableTiming);
        configured = 1;
    }

    const size_t HOFF = (size_t)MH * CDIM;

    // ---- fork ----
    cudaEventRecord(evFork, 0);
    cudaStreamWaitEvent(s2, evFork, 0);

    // ---- s2: side weights + q3, off GEMM ----
    conv_wside<<<(384 * 256 + CDIM * 128 + 255) / 256, 256, 0, s2>>>(W_off, w3, W_attn, wa);
    conv_q3<<<(MQ * CDIM + 255) / 256, 256, 0, s2>>>(query, q3, MQ * CDIM);
    cudaEventRecord(evQ3, s2);
    gemm_f16_fast<float><<<dim3(2, MQ / 128), 256, SMEM_TOTAL, s2>>>(
        q3, w3, b_off, off, MQ, 144, 1152, 1152, 256);

    // ---- s3: attn GEMM + ref (after q3/wa ready) ----
    cudaStreamWaitEvent(s3, evQ3, 0);
    gemm_f16_fast<float><<<dim3(1, MQ / 128), 256, SMEM_TOTAL, s3>>>(
        q3, wa, b_attn, attn, MQ, 72, CDIM, 1152, 128);
    ref_kernel<<<BATCH, 256, 0, s3>>>(rp, ref);
    cudaEventRecord(evA, s3);

    // ---- s2: meta after off + attn + ref ----
    cudaStreamWaitEvent(s2, evA, 0);
    meta_prep<<<(NMETA + 255) / 256, 256, 0, s2>>>(off, attn, ref, mw, mi);

    // ---- main: weight conv, fused-conversion val GEMM halves ----
    conv_wvo<<<(2 * CDIM * CDIM / 4 + 255) / 256, 256>>>(W_value, wv, W_out, wo);
    cudaEventRecord(evW, 0);
    gemm_conva<<<dim3(3, MH / 128), 256, SMEM_CONVA>>>(
        value, wv, b_value, val, MH, CDIM, CDIM, CDIM, CDIM);
    cudaEventRecord(evV0, 0);
    gemm_conva<<<dim3(3, MH / 128), 256, SMEM_CONVA>>>(
        value + HOFF, wv, b_value, val + HOFF, MH, CDIM, CDIM, CDIM, CDIM);
    cudaEventRecord(evV1, 0);

    // ---- s2: sample + out-proj per half ----
    cudaStreamWaitEvent(s2, evW, 0);
    cudaStreamWaitEvent(s2, evV0, 0);
    sample2<<<QH, 192, 0, s2>>>(mw, mi, val, midh, 0);
    gemm_f16_fast<float><<<dim3(3, QH / 128), 256, SMEM_TOTAL, s2>>>(
        midh, wo, b_out, out, QH, CDIM, CDIM, CDIM, CDIM);
    cudaStreamWaitEvent(s2, evV1, 0);
    sample2<<<QH, 192, 0, s2>>>(mw, mi, val, midh, QH);
    gemm_f16_fast<float><<<dim3(3, QH / 128), 256, SMEM_TOTAL, s2>>>(
        midh + (size_t)QH * CDIM, wo, b_out, out + (size_t)QH * CDIM, QH, CDIM, CDIM, CDIM, CDIM);
    cudaEventRecord(evEnd, s2);

    // ---- join ----
    cudaStreamWaitEvent(0, evEnd, 0);
}

// round 17
// speedup vs baseline: 4.0350x; 1.0176x over previous
#include <cuda_runtime.h>
#include <cuda_fp16.h>
#include <math.h>
#include <stdint.h>

// Problem constants
#define BATCH 32
#define LQ    576
#define LV    3024
#define CDIM  384
#define NHEAD 6
#define DHEAD 64
#define NLVL  3
#define NPTS  4

#define MQ    (BATCH * LQ)          // 18432
#define MVAL  (BATCH * LV)          // 96768
#define MH    (MVAL / 2)            // 48384 rows per half
#define QH    (MQ / 2)              // 9216 query rows per half
#define NMETA (MQ * NHEAD * 12)

// Scratch (device globals; no dynamic allocation allowed)
__device__ __half g_val  [MVAL * CDIM];
__device__ __half g_q3   [MQ * 1152];
__device__ __half g_mid_h[MQ * CDIM];
__device__ __half g_Wv_h[CDIM * CDIM];
__device__ __half g_Wo_h[CDIM * CDIM];
__device__ __half g_Wa_h[CDIM * 128];
__device__ __half g_W3  [1152 * 256];
__device__ float  g_off [MQ * 144];
__device__ float  g_attn[MQ * 72];
__device__ float  g_ref [MQ * 2];
__device__ float4 g_mw  [NMETA];
__device__ int    g_mi  [NMETA];

// ===========================================================================
// helpers
// ===========================================================================
__device__ __forceinline__ uint32_t smem_u32(const void* p) {
    uint32_t a;
    asm("{ .reg .u64 t; cvta.to.shared.u64 t, %1; cvt.u32.u64 %0, t; }" : "=r"(a) : "l"(p));
    return a;
}
__device__ __forceinline__ void cp_async16(uint32_t dst, const void* src) {
    asm volatile("cp.async.cg.shared.global [%0], [%1], 16;" :: "r"(dst), "l"(src));
}
__device__ __forceinline__ void cp_commit() {
    asm volatile("cp.async.commit_group;");
}
__device__ __forceinline__ void ldsm4(uint32_t* r, uint32_t a) {
    asm volatile("ldmatrix.sync.aligned.m8n8.x4.shared.b16 {%0,%1,%2,%3}, [%4];"
        : "=r"(r[0]), "=r"(r[1]), "=r"(r[2]), "=r"(r[3]) : "r"(a));
}
__device__ __forceinline__ void ldsm4t(uint32_t* r, uint32_t a) {
    asm volatile("ldmatrix.sync.aligned.m8n8.x4.trans.shared.b16 {%0,%1,%2,%3}, [%4];"
        : "=r"(r[0]), "=r"(r[1]), "=r"(r[2]), "=r"(r[3]) : "r"(a));
}
#define MMA_F16(Cc, Af, Bf) \
  asm volatile("mma.sync.aligned.m16n8k16.row.col.f32.f16.f16.f32 " \
    "{%0,%1,%2,%3}, {%4,%5,%6,%7}, {%8,%9}, {%0,%1,%2,%3};" \
    : "+f"(Cc[0]), "+f"(Cc[1]), "+f"(Cc[2]), "+f"(Cc[3]) \
    : "r"(Af[0]), "r"(Af[1]), "r"(Af[2]), "r"(Af[3]), "r"(Bf[0]), "r"(Bf[1]))

__device__ __forceinline__ uint32_t pack_h2(float a, float b) {
    __half2 t = __floats2half2_rn(a, b);
    return *(uint32_t*)&t;
}

// ===========================================================================
// prep kernels
// ===========================================================================
__global__ void conv_wvo(const float* __restrict__ Wv, __half* __restrict__ wv,
                         const float* __restrict__ Wo, __half* __restrict__ wo)
{
    int i = blockIdx.x * 256 + threadIdx.x;
    const int nw4 = CDIM * CDIM / 4;
    if (i < nw4) {
        float4 v = ((const float4*)Wv)[i];
        ((uint2*)wv)[i] = make_uint2(pack_h2(v.x, v.y), pack_h2(v.z, v.w));
    } else if (i < 2 * nw4) {
        int j = i - nw4;
        float4 v = ((const float4*)Wo)[j];
        ((uint2*)wo)[j] = make_uint2(pack_h2(v.x, v.y), pack_h2(v.z, v.w));
    }
}

// Combined side prep: q3 image + W3 image + Wa pad, one launch.
#define NSIDE (MQ * CDIM + 384 * 256 + CDIM * 128)
__global__ void conv_side(const float* __restrict__ q, __half* __restrict__ q3,
                          const float* __restrict__ Wf, __half* __restrict__ w3,
                          const float* __restrict__ Wa, __half* __restrict__ wa)
{
    int i = blockIdx.x * 256 + threadIdx.x;
    if (i < MQ * CDIM) {
        int row = i / CDIM, c = i % CDIM;
        float v = q[i];
        __half h = __float2half_rn(v);
        __half l = __float2half_rn(v - __half2float(h));
        __half* r = q3 + (size_t)row * 1152;
        r[c] = h; r[384 + c] = h; r[768 + c] = l;
    } else if (i < MQ * CDIM + 384 * 256) {
        int j = i - MQ * CDIM;
        int k = j >> 8, c = j & 255;
        float v = (c < 144) ? Wf[k * 144 + c] : 0.f;
        __half h = __float2half_rn(v);
        __half l = __float2half_rn(v - __half2float(h));
        w3[(size_t)k * 256 + c] = h;
        w3[(size_t)(384 + k) * 256 + c] = l;
        w3[(size_t)(768 + k) * 256 + c] = h;
    } else if (i < NSIDE) {
        int j = i - MQ * CDIM - 384 * 256;
        int r = j >> 7, c = j & 127;
        wa[j] = (c < 72) ? __float2half_rn(Wa[r * 72 + c]) : __half(0.f);
    }
}

// ===========================================================================
// Fast fp16 GEMM (proven kernel; A fp16)
// ===========================================================================
#define ASTB 10240
#define BSTB 8704
#define SMEM_TOTAL (3 * (ASTB + BSTB))   // 56832

template<typename OutT>
__global__ __launch_bounds__(256, 2)
void gemm_f16_fast(const __half* __restrict__ A, const __half* __restrict__ B,
                   const float* __restrict__ bias, OutT* __restrict__ C,
                   int M, int N, int K, int lda, int Bw)
{
    extern __shared__ __align__(16) char dsm[];
    const uint32_t sA = smem_u32(dsm);
    const uint32_t sB = sA + 3 * ASTB;

    const int tid  = threadIdx.x;
    const int m0   = blockIdx.y * 128;
    const int n0   = blockIdx.x * 128;
    const int warp = tid >> 5, lane = tid & 31;
    const int g = lane >> 2, t = lane & 3;
    const int mwb = (warp >> 1) * 32;
    const int nwb = (warp & 1) * 64;

    const int arow = tid >> 2;
    const int ac   = tid & 3;
    const int brow = tid >> 4;
    const int bc   = tid & 15;
    const __half* agp = A + (size_t)(m0 + arow) * lda + ac * 8;
    const __half* bgp = B + (size_t)brow * Bw + n0 + bc * 8;
    const uint32_t adp = sA + arow * 80 + ac * 16;
    const uint32_t bdp = sB + brow * 272 + bc * 16;

    const uint32_t aOff = ((lane & 15) * 40 + (lane >> 4) * 8) * 2 + mwb * 80;
    const uint32_t bOff = ((lane & 15) * 136 + (lane >> 4) * 8) * 2 + nwb * 2;

    float cacc[2][8][4];
#pragma unroll
    for (int i = 0; i < 2; i++)
#pragma unroll
        for (int j = 0; j < 8; j++)
#pragma unroll
            for (int k = 0; k < 4; k++) cacc[i][j][k] = 0.f;

    const int nt = K / 32;

    auto load_stage = [&](int kt, int s) {
        const __half* ag = agp + kt * 32;
        uint32_t ad = adp + s * ASTB;
        cp_async16(ad, ag);
        cp_async16(ad + 64 * 80, ag + (size_t)64 * lda);
        const __half* bg = bgp + (size_t)(kt * 32) * Bw;
        uint32_t bd = bdp + s * BSTB;
        cp_async16(bd, bg);
        cp_async16(bd + 16 * 272, bg + (size_t)16 * Bw);
    };

    load_stage(0, 0); cp_commit();
    load_stage(1, 1); cp_commit();

    for (int kt = 0; kt < nt; kt++) {
        if (kt < nt - 1) { asm volatile("cp.async.wait_group 1;"); }
        else             { asm volatile("cp.async.wait_group 0;"); }
        __syncthreads();

        if (kt + 2 < nt) {
            load_stage(kt + 2, (kt + 2) % 3);
            cp_commit();
        }

        const int s = kt % 3;
        const uint32_t aBase = sA + s * ASTB + aOff;
        const uint32_t bBase = sB + s * BSTB + bOff;
#pragma unroll
        for (int ks = 0; ks < 2; ks++) {
            uint32_t aH[2][4], bF[4][4];
            ldsm4(aH[0], aBase + ks * 32);
            ldsm4(aH[1], aBase + 16 * 80 + ks * 32);
#pragma unroll
            for (int p = 0; p < 4; p++)
                ldsm4t(bF[p], bBase + ks * 16 * 272 + p * 32);
#pragma unroll
            for (int mi = 0; mi < 2; mi++)
#pragma unroll
                for (int nj = 0; nj < 8; nj++) {
                    uint32_t bfr[2] = { bF[nj >> 1][(nj & 1) * 2], bF[nj >> 1][(nj & 1) * 2 + 1] };
                    MMA_F16(cacc[mi][nj], aH[mi], bfr);
                }
        }
        __syncthreads();
    }

#pragma unroll
    for (int mi = 0; mi < 2; mi++) {
#pragma unroll
        for (int nj = 0; nj < 8; nj++) {
            int row = m0 + mwb + mi * 16 + g;
            int col = n0 + nwb + nj * 8 + 2 * t;
            if (col < N) {
                float b0 = bias[col], b1 = bias[col + 1];
                float v00 = cacc[mi][nj][0] + b0, v01 = cacc[mi][nj][1] + b1;
                float v10 = cacc[mi][nj][2] + b0, v11 = cacc[mi][nj][3] + b1;
                if (sizeof(OutT) == 4) {
                    *(float2*)((float*)C + (size_t)row * N + col) = make_float2(v00, v01);
                    *(float2*)((float*)C + (size_t)(row + 8) * N + col) = make_float2(v10, v11);
                } else {
                    *(__half2*)((__half*)C + (size_t)row * N + col) = __floats2half2_rn(v00, v01);
                    *(__half2*)((__half*)C + (size_t)(row + 8) * N + col) = __floats2half2_rn(v10, v11);
                }
            }
        }
    }
}

// ===========================================================================
// Fused-conversion GEMM (val projection): A fp32 cvt->STS, B fp16 cp.async.
// ===========================================================================
__global__ __launch_bounds__(256, 2)
void gemm_conva(const float* __restrict__ A, const __half* __restrict__ B,
                const float* __restrict__ bias, __half* __restrict__ C,
                int M, int N, int K, int lda, int Bw)
{
    extern __shared__ __align__(16) char dsm[];
    const uint32_t sA = smem_u32(dsm);              // 2 * ASTB
    const uint32_t sB = sA + 2 * ASTB;              // 3 * BSTB

    const int tid  = threadIdx.x;
    const int m0   = blockIdx.y * 128;
    const int n0   = blockIdx.x * 128;
    const int warp = tid >> 5, lane = tid & 31;
    const int g = lane >> 2, t = lane & 3;
    const int mwb = (warp >> 1) * 32;
    const int nwb = (warp & 1) * 64;

    const int arow = tid >> 1;
    const int ak   = (tid & 1) * 16;
    const float* agp = A + (size_t)(m0 + arow) * lda + ak;
    const int brow = tid >> 4;
    const int bc   = tid & 15;
    const __half* bgp = B + (size_t)brow * Bw + n0 + bc * 8;
    const uint32_t bdp = sB + brow * 272 + bc * 16;

    const uint32_t aOff = ((lane & 15) * 40 + (lane >> 4) * 8) * 2 + mwb * 80;
    const uint32_t bOff = ((lane & 15) * 136 + (lane >> 4) * 8) * 2 + nwb * 2;

    float cacc[2][8][4];
#pragma unroll
    for (int i = 0; i < 2; i++)
#pragma unroll
        for (int j = 0; j < 8; j++)
#pragma unroll
            for (int k = 0; k < 4; k++) cacc[i][j][k] = 0.f;

    const int nt = K / 32;

    auto load_b = [&](int kt, int s) {
        const __half* bg = bgp + (size_t)(kt * 32) * Bw;
        uint32_t bd = bdp + s * BSTB;
        cp_async16(bd, bg);
        cp_async16(bd + 16 * 272, bg + (size_t)16 * Bw);
    };

    float4 pa[4];
#pragma unroll
    for (int j = 0; j < 4; j++) pa[j] = *(const float4*)(agp + j * 4);
    load_b(0, 0); cp_commit();
    load_b(1, 1); cp_commit();

    for (int kt = 0; kt < nt; kt++) {
        {
            uint32_t ad = sA + (kt & 1) * ASTB + arow * 80 + ak * 2;
#pragma unroll
            for (int j = 0; j < 4; j++) {
                float4 v = pa[j];
                *(uint2*)(dsm + (ad - sA) + j * 8) =
                    make_uint2(pack_h2(v.x, v.y), pack_h2(v.z, v.w));
            }
        }
        if (kt < nt - 1) { asm volatile("cp.async.wait_group 1;"); }
        else             { asm volatile("cp.async.wait_group 0;"); }
        __syncthreads();

        if (kt + 1 < nt) {
            const float* p = agp + (kt + 1) * 32;
#pragma unroll
            for (int j = 0; j < 4; j++) pa[j] = *(const float4*)(p + j * 4);
        }
        if (kt + 2 < nt) { load_b(kt + 2, (kt + 2) % 3); cp_commit(); }

        const uint32_t aBase = sA + (kt & 1) * ASTB + aOff;
        const uint32_t bBase = sB + (kt % 3) * BSTB + bOff;
#pragma unroll
        for (int ks = 0; ks < 2; ks++) {
            uint32_t aH[2][4], bF[4][4];
            ldsm4(aH[0], aBase + ks * 32);
            ldsm4(aH[1], aBase + 16 * 80 + ks * 32);
#pragma unroll
            for (int p = 0; p < 4; p++)
                ldsm4t(bF[p], bBase + ks * 16 * 272 + p * 32);
#pragma unroll
            for (int mi = 0; mi < 2; mi++)
#pragma unroll
                for (int nj = 0; nj < 8; nj++) {
                    uint32_t bfr[2] = { bF[nj >> 1][(nj & 1) * 2], bF[nj >> 1][(nj & 1) * 2 + 1] };
                    MMA_F16(cacc[mi][nj], aH[mi], bfr);
                }
        }
    }
    __syncthreads();

#pragma unroll
    for (int mi = 0; mi < 2; mi++) {
#pragma unroll
        for (int nj = 0; nj < 8; nj++) {
            int row = m0 + mwb + mi * 16 + g;
            int col = n0 + nwb + nj * 8 + 2 * t;
            float b0 = bias[col], b1 = bias[col + 1];
            *(__half2*)(C + (size_t)row * N + col) =
                __floats2half2_rn(cacc[mi][nj][0] + b0, cacc[mi][nj][1] + b1);
            *(__half2*)(C + (size_t)(row + 8) * N + col) =
                __floats2half2_rn(cacc[mi][nj][2] + b0, cacc[mi][nj][3] + b1);
        }
    }
}
#define SMEM_CONVA (2 * ASTB + 3 * BSTB)   // 46592

// ===========================================================================
// Reference-point processing
// ===========================================================================
__global__ void ref_kernel(const float* __restrict__ rp, float* __restrict__ ref)
{
    const int b = blockIdx.x;
    const float* r = rp + (size_t)b * LV * 2;

    __shared__ float redx[256], redy[256];
    float ax = 0.f, ay = 0.f;
    for (int i = threadIdx.x; i < 2304; i += 256) {
        ax += r[2 * i];
        ay += r[2 * i + 1];
    }
    redx[threadIdx.x] = ax; redy[threadIdx.x] = ay;
    __syncthreads();
    for (int s = 128; s > 0; s >>= 1) {
        if (threadIdx.x < s) {
            redx[threadIdx.x] += redx[threadIdx.x + s];
            redy[threadIdx.x] += redy[threadIdx.x + s];
        }
        __syncthreads();
    }
    const float p1x = redx[0] * (1.f / 2304.f);
    const float p1y = redy[0] * (1.f / 2304.f);

    for (int q = threadIdx.x; q < LQ; q += 256) {
        float p2x = r[2 * (2304 + q)];
        float p2y = r[2 * (2304 + q) + 1];

        int rr = q / 24, cc = q % 24;
        float yy = 0.5f * rr - 0.25f;
        float xx = 0.5f * cc - 0.25f;
        int y0 = (int)floorf(yy), x0 = (int)floorf(xx);
        float wy = yy - (float)y0, wx = xx - (float)x0;
        int y0c = max(y0, 0), y1c = min(y0 + 1, 11);
        int x0c = max(x0, 0), x1c = min(x0 + 1, 11);

        const float* p3 = r + 2 * 2880;
        float v00x = p3[2 * (y0c * 12 + x0c)],     v00y = p3[2 * (y0c * 12 + x0c) + 1];
        float v01x = p3[2 * (y0c * 12 + x1c)],     v01y = p3[2 * (y0c * 12 + x1c) + 1];
        float v10x = p3[2 * (y1c * 12 + x0c)],     v10y = p3[2 * (y1c * 12 + x0c) + 1];
        float v11x = p3[2 * (y1c * 12 + x1c)],     v11y = p3[2 * (y1c * 12 + x1c) + 1];
        float p3x = (1.f - wy) * ((1.f - wx) * v00x + wx * v01x) + wy * ((1.f - wx) * v10x + wx * v11x);
        float p3y = (1.f - wy) * ((1.f - wx) * v00y + wx * v01y) + wy * ((1.f - wx) * v10y + wx * v11y);

        ref[((size_t)b * LQ + q) * 2 + 0] = (p1x + p2x + p3x) * (1.f / 3.f);
        ref[((size_t)b * LQ + q) * 2 + 1] = (p1y + p2y + p3y) * (1.f / 3.f);
    }
}

// ===========================================================================
// Meta prep
// ===========================================================================
__global__ void meta_prep(const float* __restrict__ off,
                          const float* __restrict__ logits,
                          const float* __restrict__ refp,
                          float4* __restrict__ mw, int* __restrict__ mi)
{
    int j = blockIdx.x * 256 + threadIdx.x;
    if (j >= NMETA) return;
    int pt  = j % 12;
    int bqh = j / 12;
    int h   = bqh % NHEAD;
    int bq  = bqh / NHEAD;
    int b   = bq / LQ;

    const float* lg = logits + bq * 72 + h * 12;
    float e[12], mx = -1e30f;
#pragma unroll
    for (int i = 0; i < 12; i++) { e[i] = lg[i]; mx = fmaxf(mx, e[i]); }
    float ssum = 0.f;
#pragma unroll
    for (int i = 0; i < 12; i++) { e[i] = __expf(e[i] - mx); ssum += e[i]; }
    const float aw = e[pt] / ssum;

    const int lv = pt >> 2, p = pt & 3;
    const int Wl = (lv == 0) ? 48 : (lv == 1) ? 24 : 12;
    const int Hl = Wl;
    const int st = (lv == 0) ? 0  : (lv == 1) ? 2304 : 2880;

    float cx = off[bq * 144 + h * 24 + lv * 8 + p * 2 + 0] + refp[bq * 2 + 0];
    float cy = off[bq * 144 + h * 24 + lv * 8 + p * 2 + 1] + refp[bq * 2 + 1];
    float px = cx * (float)Wl - 0.5f;
    float py = cy * (float)Hl - 0.5f;
    float x0f = floorf(px), y0f = floorf(py);
    float lx = px - x0f, ly = py - y0f;
    int x0 = (int)x0f, y0 = (int)y0f;
    int x1 = x0 + 1,   y1 = y0 + 1;

    bool vx0 = (x0 >= 0) & (x0 < Wl);
    bool vx1 = (x1 >= 0) & (x1 < Wl);
    bool vy0 = (y0 >= 0) & (y0 < Hl);
    bool vy1 = (y1 >= 0) & (y1 < Hl);

    float w00 = (1.f - lx) * (1.f - ly) * aw, w10 = lx * (1.f - ly) * aw;
    float w01 = (1.f - lx) * ly * aw,         w11 = lx * ly * aw;

    int xb = min(max(x0, 0), Wl - 2);
    int yb = min(max(y0, 0), Hl - 2);

    float wb0 = 0.f, wb1 = 0.f, wb2 = 0.f, wb3 = 0.f;
    if (vx0 & vy0) { if (y0 == yb) { if (x0 == xb) wb0 += w00; else wb1 += w00; }
                     else          { if (x0 == xb) wb2 += w00; else wb3 += w00; } }
    if (vx1 & vy0) { if (y0 == yb) { if (x1 == xb) wb0 += w10; else wb1 += w10; }
                     else          { if (x1 == xb) wb2 += w10; else wb3 += w10; } }
    if (vx0 & vy1) { if (y1 == yb) { if (x0 == xb) wb0 += w01; else wb1 += w01; }
                     else          { if (x0 == xb) wb2 += w01; else wb3 += w01; } }
    if (vx1 & vy1) { if (y1 == yb) { if (x1 == xb) wb0 += w11; else wb1 += w11; }
                     else          { if (x1 == xb) wb2 += w11; else wb3 += w11; } }

    mw[j] = make_float4(wb0, wb1, wb2, wb3);
    mi[j] = (b * LV + st + yb * Wl + xb) * CDIM + h * DHEAD;
}

// ===========================================================================
// Slim sampling
// ===========================================================================
__global__ __launch_bounds__(192)
void sample2(const float4* __restrict__ mw, const int* __restrict__ mi,
             const __half* __restrict__ val, __half* __restrict__ mid, int bq0)
{
    const int bq   = bq0 + blockIdx.x;
    const int h    = threadIdx.x >> 5;
    const int lane = threadIdx.x & 31;

    const float4* wp = mw + (size_t)(bq * NHEAD + h) * 12;
    const int*    ip = mi + (size_t)(bq * NHEAD + h) * 12;

    float ax = 0.f, ay = 0.f;
#pragma unroll
    for (int pt = 0; pt < 12; pt++) {
        const int Wl = (pt < 4) ? 48 : (pt < 8) ? 24 : 12;
        float4 w = wp[pt];
        int base = ip[pt] + 2 * lane;
        float2 v00 = __half22float2(*(const __half2*)&val[base]);
        float2 v10 = __half22float2(*(const __half2*)&val[base + CDIM]);
        float2 v01 = __half22float2(*(const __half2*)&val[base + Wl * CDIM]);
        float2 v11 = __half22float2(*(const __half2*)&val[base + (Wl + 1) * CDIM]);
        ax += w.x * v00.x + w.y * v10.x + w.z * v01.x + w.w * v11.x;
        ay += w.x * v00.y + w.y * v10.y + w.z * v01.y + w.w * v11.y;
    }

    *(__half2*)&mid[(size_t)bq * CDIM + h * DHEAD + 2 * lane] = __floats2half2_rn(ax, ay);
}

// ===========================================================================
extern "C" void kernel_launch(void* const* d_in, const int* in_sizes, int n_in,
                              void* d_out, int out_size)
{
    const float* query   = (const float*)d_in[0];
    const float* value   = (const float*)d_in[1];
    const float* rp      = (const float*)d_in[2];
    const float* W_value = (const float*)d_in[3];
    const float* b_value = (const float*)d_in[4];
    const float* W_off   = (const float*)d_in[5];
    const float* b_off   = (const float*)d_in[6];
    const float* W_attn  = (const float*)d_in[7];
    const float* b_attn  = (const float*)d_in[8];
    const float* W_out   = (const float*)d_in[9];
    const float* b_out   = (const float*)d_in[10];
    float* out = (float*)d_out;

    __half *val, *q3, *midh, *wv, *wo, *wa, *w3;
    float *off, *attn, *ref;
    float4* mw; int* mi;
    cudaGetSymbolAddress((void**)&val,  g_val);
    cudaGetSymbolAddress((void**)&q3,   g_q3);
    cudaGetSymbolAddress((void**)&midh, g_mid_h);
    cudaGetSymbolAddress((void**)&wv,   g_Wv_h);
    cudaGetSymbolAddress((void**)&wo,   g_Wo_h);
    cudaGetSymbolAddress((void**)&wa,   g_Wa_h);
    cudaGetSymbolAddress((void**)&w3,   g_W3);
    cudaGetSymbolAddress((void**)&off,  g_off);
    cudaGetSymbolAddress((void**)&attn, g_attn);
    cudaGetSymbolAddress((void**)&ref,  g_ref);
    cudaGetSymbolAddress((void**)&mw,   g_mw);
    cudaGetSymbolAddress((void**)&mi,   g_mi);

    static cudaStream_t s2 = nullptr, s3 = nullptr;
    static cudaEvent_t evFork = nullptr, evQ3 = nullptr, evA = nullptr,
                       evV0 = nullptr, evV1 = nullptr, evW = nullptr,
                       evS0 = nullptr, evO0 = nullptr, evEnd = nullptr;
    static int configured = 0;
    if (!configured) {
        cudaFuncSetAttribute(gemm_f16_fast<__half>, cudaFuncAttributeMaxDynamicSharedMemorySize, SMEM_TOTAL);
        cudaFuncSetAttribute(gemm_f16_fast<float>,  cudaFuncAttributeMaxDynamicSharedMemorySize, SMEM_TOTAL);
        cudaFuncSetAttribute(gemm_conva, cudaFuncAttributeMaxDynamicSharedMemorySize, SMEM_CONVA);
        cudaStreamCreateWithFlags(&s2, cudaStreamNonBlocking);
        cudaStreamCreateWithFlags(&s3, cudaStreamNonBlocking);
        cudaEventCreateWithFlags(&evFork, cudaEventDisableTiming);
        cudaEventCreateWithFlags(&evQ3,   cudaEventDisableTiming);
        cudaEventCreateWithFlags(&evA,    cudaEventDisableTiming);
        cudaEventCreateWithFlags(&evV0,   cudaEventDisableTiming);
        cudaEventCreateWithFlags(&evV1,   cudaEventDisableTiming);
        cudaEventCreateWithFlags(&evW,    cudaEventDisableTiming);
        cudaEventCreateWithFlags(&evS0,   cudaEventDisableTiming);
        cudaEventCreateWithFlags(&evO0,   cudaEventDisableTiming);
        cudaEventCreateWithFlags(&evEnd,  cudaEventDisableTiming);
        configured = 1;
    }

    const size_t HOFF = (size_t)MH * CDIM;

    // ---- fork ----
    cudaEventRecord(evFork, 0);
    cudaStreamWaitEvent(s2, evFork, 0);

    // ---- s2: combined side prep, off GEMM ----
    conv_side<<<(NSIDE + 255) / 256, 256, 0, s2>>>(query, q3, W_off, w3, W_attn, wa);
    cudaEventRecord(evQ3, s2);
    gemm_f16_fast<float><<<dim3(2, MQ / 128), 256, SMEM_TOTAL, s2>>>(
        q3, w3, b_off, off, MQ, 144, 1152, 1152, 256);

    // ---- s3: attn GEMM + ref (after side prep) ----
    cudaStreamWaitEvent(s3, evQ3, 0);
    gemm_f16_fast<float><<<dim3(1, MQ / 128), 256, SMEM_TOTAL, s3>>>(
        q3, wa, b_attn, attn, MQ, 72, CDIM, 1152, 128);
    ref_kernel<<<BATCH, 256, 0, s3>>>(rp, ref);
    cudaEventRecord(evA, s3);

    // ---- s2: meta after off + attn + ref ----
    cudaStreamWaitEvent(s2, evA, 0);
    meta_prep<<<(NMETA + 255) / 256, 256, 0, s2>>>(off, attn, ref, mw, mi);

    // ---- main: weight conv, fused-conversion val GEMM halves ----
    conv_wvo<<<(2 * CDIM * CDIM / 4 + 255) / 256, 256>>>(W_value, wv, W_out, wo);
    cudaEventRecord(evW, 0);
    gemm_conva<<<dim3(3, MH / 128), 256, SMEM_CONVA>>>(
        value, wv, b_value, val, MH, CDIM, CDIM, CDIM, CDIM);
    cudaEventRecord(evV0, 0);
    gemm_conva<<<dim3(3, MH / 128), 256, SMEM_CONVA>>>(
        value + HOFF, wv, b_value, val + HOFF, MH, CDIM, CDIM, CDIM, CDIM);
    cudaEventRecord(evV1, 0);

    // ---- s2: sample0, then sample1 immediately after val1 (out0 on s3) ----
    cudaStreamWaitEvent(s2, evW, 0);
    cudaStreamWaitEvent(s2, evV0, 0);
    sample2<<<QH, 192, 0, s2>>>(mw, mi, val, midh, 0);
    cudaEventRecord(evS0, s2);

    // out0 on s3 (depends only on sample0 + wo)
    cudaStreamWaitEvent(s3, evS0, 0);
    cudaStreamWaitEvent(s3, evW, 0);
    gemm_f16_fast<float><<<dim3(3, QH / 128), 256, SMEM_TOTAL, s3>>>(
        midh, wo, b_out, out, QH, CDIM, CDIM, CDIM, CDIM);
    cudaEventRecord(evO0, s3);

    // sample1 + out1 on s2
    cudaStreamWaitEvent(s2, evV1, 0);
    sample2<<<QH, 192, 0, s2>>>(mw, mi, val, midh, QH);
    gemm_f16_fast<float><<<dim3(3, QH / 128), 256, SMEM_TOTAL, s2>>>(
        midh + (size_t)QH * CDIM, wo, b_out, out + (size_t)QH * CDIM, QH, CDIM, CDIM, CDIM, CDIM);
    cudaEventRecord(evEnd, s2);

    // ---- join ----
    cudaStreamWaitEvent(0, evO0, 0);
    cudaStreamWaitEvent(0, evEnd, 0);
}